// round 11
// baseline (speedup 1.0000x reference)
#include <cuda_runtime.h>
#include <cuda_bf16.h>
#include <cstdint>

using bf16 = __nv_bfloat16;

#define NQ 8
#define TSZ 67108864UL   // elements per T plane
#define ESZ 4194304UL    // elements per env plane

// Static device scratch. hi plane [0,P), lo plane [P,2P).
__device__ bf16 g_TA[2 * TSZ];
__device__ bf16 g_TB[2 * TSZ];
__device__ bf16 g_envA[2 * ESZ];
__device__ bf16 g_envB[2 * ESZ];
__device__ bf16 g_S[2 * 524288];   // state split  (native layout)
__device__ bf16 g_U[2 * 524288];   // layer split  (native layout)
__device__ bf16 g_Ud[2 * 524288];  // permuted U-dagger split
__device__ bf16 g_O[2 * 32768];    // operator split (native layout)

struct Scat { int radix[4]; int stride[4]; };

__device__ __forceinline__ int scat_off(int idx, const Scat s) {
    int off = 0;
#pragma unroll
    for (int d = 0; d < 4; d++) {
        off += (idx % s.radix[d]) * s.stride[d];
        idx /= s.radix[d];
    }
    return off;
}

// ---------------------------------------------------------------------------
// PTX helpers
// ---------------------------------------------------------------------------
__device__ __forceinline__ uint32_t s2u(const void* p) {
    return (uint32_t)__cvta_generic_to_shared(p);
}
__device__ __forceinline__ void cpa16(uint32_t saddr, const void* g) {
    asm volatile("cp.async.cg.shared.global [%0], [%1], 16;\n" :: "r"(saddr), "l"(g));
}
#define CP_COMMIT() asm volatile("cp.async.commit_group;\n")
#define CP_WAIT1()  asm volatile("cp.async.wait_group 1;\n")
#define CP_WAIT0()  asm volatile("cp.async.wait_group 0;\n")

__device__ __forceinline__ void ldsm4t(uint32_t* r, uint32_t addr) {
    asm volatile("ldmatrix.sync.aligned.m8n8.x4.trans.shared.b16 {%0,%1,%2,%3}, [%4];"
                 : "=r"(r[0]), "=r"(r[1]), "=r"(r[2]), "=r"(r[3]) : "r"(addr));
}
__device__ __forceinline__ void mma16816(float* d, const uint32_t* a, const uint32_t* b) {
    asm volatile(
        "mma.sync.aligned.m16n8k16.row.col.f32.bf16.bf16.f32 "
        "{%0,%1,%2,%3},{%4,%5,%6,%7},{%8,%9},{%0,%1,%2,%3};"
        : "+f"(d[0]), "+f"(d[1]), "+f"(d[2]), "+f"(d[3])
        : "r"(a[0]), "r"(a[1]), "r"(a[2]), "r"(a[3]), "r"(b[0]), "r"(b[1]));
}

__device__ __forceinline__ void store_pair(bf16* C, size_t Cplane, size_t off,
                                           float v0, float v1) {
    __nv_bfloat162 ph, pl;
    ph.x = __float2bfloat16(v0);
    ph.y = __float2bfloat16(v1);
    pl.x = __float2bfloat16(v0 - __bfloat162float(ph.x));
    pl.y = __float2bfloat16(v1 - __bfloat162float(ph.y));
    *(__nv_bfloat162*)(C + off) = ph;
    *(__nv_bfloat162*)(C + Cplane + off) = pl;
}

// ---------------------------------------------------------------------------
// gemm_big: BM=128, BN=128, 2 CTAs/SM, 3-stage (round-9/10 engine). Used: G1.
// ---------------------------------------------------------------------------
__global__ void __launch_bounds__(256, 2) gemm_big(
    const bf16* __restrict__ A, const bf16* __restrict__ B,
    bf16* __restrict__ C, int M, int N, int K,
    size_t Aplane, size_t Bplane, size_t Cplane, Scat rs, Scat cs)
{
    constexpr int BM = 128, BN = 128, BK = 32;
    constexpr int APITCH = BM + 8;
    constexpr int BPITCH = BN + 8;
    constexpr int AS_PLANE = BK * APITCH;
    constexpr int BS_PLANE = BK * BPITCH;
    constexpr int STAGE = 2 * AS_PLANE + 2 * BS_PLANE;
    constexpr int NSTG = 3;
    constexpr int NT = BN / 16;   // 8
    constexpr int MT = 2;

    extern __shared__ bf16 sm[];

    const int tid  = threadIdx.x;
    const int lane = tid & 31;
    const int warp = tid >> 5;
    const int wm = (warp & 3) * 32;
    const int wn = (warp >> 2) * (BN / 2);
    const int m0 = blockIdx.x * BM;
    const int n0 = blockIdx.y * BN;

    float acc[MT][NT][4];
#pragma unroll
    for (int mt = 0; mt < MT; mt++)
#pragma unroll
        for (int nt = 0; nt < NT; nt++)
#pragma unroll
            for (int i = 0; i < 4; i++) acc[mt][nt][i] = 0.f;

    const int lk   = tid >> 3;
    const int mseg = (tid & 7) * 16;

    auto load_stage = [&](int s, int k0) {
        bf16* base = sm + s * STAGE;
        const bf16* Ag = A + (size_t)(k0 + lk) * (size_t)M + (size_t)(m0 + mseg);
        uint32_t da = s2u(base + lk * APITCH + mseg);
        cpa16(da,      Ag);
        cpa16(da + 16, Ag + 8);
        uint32_t dal = s2u(base + AS_PLANE + lk * APITCH + mseg);
        cpa16(dal,      Ag + Aplane);
        cpa16(dal + 16, Ag + Aplane + 8);
        bf16* bb = base + 2 * AS_PLANE;
        const bf16* Bg = B + (size_t)(k0 + lk) * (size_t)N + (size_t)(n0 + mseg);
        uint32_t db = s2u(bb + lk * BPITCH + mseg);
        cpa16(db,      Bg);
        cpa16(db + 16, Bg + 8);
        uint32_t dbl = s2u(bb + BS_PLANE + lk * BPITCH + mseg);
        cpa16(dbl,      Bg + Bplane);
        cpa16(dbl + 16, Bg + Bplane + 8);
    };

    const int nchunks = K / BK;
    load_stage(0, 0);
    CP_COMMIT();
    if (nchunks > 1) load_stage(1, BK);
    CP_COMMIT();

    for (int c = 0; c < nchunks; c++) {
        CP_WAIT1();
        __syncthreads();

        if (c + 2 < nchunks) load_stage((c + 2) % NSTG, (c + 2) * BK);
        CP_COMMIT();

        const bf16* base = sm + (c % NSTG) * STAGE;
        const bf16* Ah = base;
        const bf16* Al = base + AS_PLANE;
        const bf16* Bh = base + 2 * AS_PLANE;
        const bf16* Bl = base + 2 * AS_PLANE + BS_PLANE;

#pragma unroll
        for (int kk = 0; kk < BK; kk += 16) {
            uint32_t a[MT][4];
            uint32_t bh[NT / 2][4], bl[NT / 2][4];
            const int akr = kk + (lane & 7) + ((lane >> 4) & 1) * 8;
            const int amc = wm + ((lane >> 3) & 1) * 8;
            const int bkr = kk + (lane & 7) + ((lane >> 3) & 1) * 8;
            const int bnc = wn + ((lane >> 4) & 1) * 8;
#pragma unroll
            for (int mt = 0; mt < MT; mt++)
                ldsm4t(a[mt], s2u(Ah + akr * APITCH + amc + mt * 16));
#pragma unroll
            for (int np = 0; np < NT / 2; np++) {
                ldsm4t(bh[np], s2u(Bh + bkr * BPITCH + bnc + np * 16));
                ldsm4t(bl[np], s2u(Bl + bkr * BPITCH + bnc + np * 16));
            }
#pragma unroll
            for (int mt = 0; mt < MT; mt++)
#pragma unroll
                for (int nt = 0; nt < NT; nt++)
                    mma16816(acc[mt][nt], a[mt], &bh[nt >> 1][(nt & 1) * 2]);
#pragma unroll
            for (int mt = 0; mt < MT; mt++)
#pragma unroll
                for (int nt = 0; nt < NT; nt++)
                    mma16816(acc[mt][nt], a[mt], &bl[nt >> 1][(nt & 1) * 2]);
#pragma unroll
            for (int mt = 0; mt < MT; mt++)
                ldsm4t(a[mt], s2u(Al + akr * APITCH + amc + mt * 16));
#pragma unroll
            for (int mt = 0; mt < MT; mt++)
#pragma unroll
                for (int nt = 0; nt < NT; nt++)
                    mma16816(acc[mt][nt], a[mt], &bh[nt >> 1][(nt & 1) * 2]);
        }
    }

    const int r  = lane >> 2;
    const int c2 = (lane & 3) * 2;
    int fo[MT][2], go[NT];
#pragma unroll
    for (int mt = 0; mt < MT; mt++) {
        fo[mt][0] = scat_off(m0 + wm + mt * 16 + r,     rs);
        fo[mt][1] = scat_off(m0 + wm + mt * 16 + r + 8, rs);
    }
#pragma unroll
    for (int nt = 0; nt < NT; nt++)
        go[nt] = scat_off(n0 + wn + nt * 8 + c2, cs);

#pragma unroll
    for (int mt = 0; mt < MT; mt++)
#pragma unroll
        for (int nt = 0; nt < NT; nt++)
#pragma unroll
            for (int h = 0; h < 2; h++)
                store_pair(C, Cplane, (size_t)(fo[mt][h] + go[nt]),
                           acc[mt][nt][h * 2], acc[mt][nt][h * 2 + 1]);
}

// ---------------------------------------------------------------------------
// gemm_mid: BM=64, BN=128, 3 CTAs/SM, 2-stage. Used: G2, G4 (62% of MMA work).
// 8 warps as 2(m) x 4(n); warp tile 32m x 32n; acc 32 regs/thread.
// ---------------------------------------------------------------------------
__global__ void __launch_bounds__(256, 3) gemm_mid(
    const bf16* __restrict__ A, const bf16* __restrict__ B,
    bf16* __restrict__ C, int M, int N, int K,
    size_t Aplane, size_t Bplane, size_t Cplane, Scat rs, Scat cs)
{
    constexpr int BM = 64, BN = 128, BK = 32;
    constexpr int APITCH = BM + 8;    // 72
    constexpr int BPITCH = BN + 8;    // 136
    constexpr int AS_PLANE = BK * APITCH;
    constexpr int BS_PLANE = BK * BPITCH;
    constexpr int STAGE = 2 * AS_PLANE + 2 * BS_PLANE;   // 13312 elems
    constexpr int NT = 4;             // n8 tiles per warp (32 cols)
    constexpr int MT = 2;             // m16 tiles per warp (32 rows)

    extern __shared__ bf16 sm[];

    const int tid  = threadIdx.x;
    const int lane = tid & 31;
    const int warp = tid >> 5;
    const int wm = (warp & 1) * 32;
    const int wn = (warp >> 1) * 32;
    const int m0 = blockIdx.x * BM;
    const int n0 = blockIdx.y * BN;

    float acc[MT][NT][4];
#pragma unroll
    for (int mt = 0; mt < MT; mt++)
#pragma unroll
        for (int nt = 0; nt < NT; nt++)
#pragma unroll
            for (int i = 0; i < 4; i++) acc[mt][nt][i] = 0.f;

    const int lk   = tid >> 3;          // 0..31
    const int aseg = (tid & 7) * 8;     // A: 8 elems (16B)
    const int nseg = (tid & 7) * 16;    // B: 16 elems (2x16B)

    auto load_stage = [&](int s, int k0) {
        bf16* base = sm + s * STAGE;
        const bf16* Ag = A + (size_t)(k0 + lk) * (size_t)M + (size_t)(m0 + aseg);
        cpa16(s2u(base + lk * APITCH + aseg), Ag);
        cpa16(s2u(base + AS_PLANE + lk * APITCH + aseg), Ag + Aplane);
        bf16* bb = base + 2 * AS_PLANE;
        const bf16* Bg = B + (size_t)(k0 + lk) * (size_t)N + (size_t)(n0 + nseg);
        uint32_t db = s2u(bb + lk * BPITCH + nseg);
        cpa16(db,      Bg);
        cpa16(db + 16, Bg + 8);
        uint32_t dbl = s2u(bb + BS_PLANE + lk * BPITCH + nseg);
        cpa16(dbl,      Bg + Bplane);
        cpa16(dbl + 16, Bg + Bplane + 8);
    };

    const int nchunks = K / BK;
    load_stage(0, 0);
    CP_COMMIT();

    for (int c = 0; c < nchunks; c++) {
        if (c + 1 < nchunks) {
            load_stage((c + 1) & 1, (c + 1) * BK);   // safe: trailing sync of c-1
            CP_COMMIT();
            CP_WAIT1();
        } else {
            CP_WAIT0();
        }
        __syncthreads();

        const bf16* base = sm + (c & 1) * STAGE;
        const bf16* Ah = base;
        const bf16* Al = base + AS_PLANE;
        const bf16* Bh = base + 2 * AS_PLANE;
        const bf16* Bl = base + 2 * AS_PLANE + BS_PLANE;

#pragma unroll
        for (int kk = 0; kk < BK; kk += 16) {
            uint32_t a[MT][4];
            uint32_t bh[NT / 2][4], bl[NT / 2][4];
            const int akr = kk + (lane & 7) + ((lane >> 4) & 1) * 8;
            const int amc = wm + ((lane >> 3) & 1) * 8;
            const int bkr = kk + (lane & 7) + ((lane >> 3) & 1) * 8;
            const int bnc = wn + ((lane >> 4) & 1) * 8;
#pragma unroll
            for (int mt = 0; mt < MT; mt++)
                ldsm4t(a[mt], s2u(Ah + akr * APITCH + amc + mt * 16));
#pragma unroll
            for (int np = 0; np < NT / 2; np++) {
                ldsm4t(bh[np], s2u(Bh + bkr * BPITCH + bnc + np * 16));
                ldsm4t(bl[np], s2u(Bl + bkr * BPITCH + bnc + np * 16));
            }
#pragma unroll
            for (int mt = 0; mt < MT; mt++)
#pragma unroll
                for (int nt = 0; nt < NT; nt++)
                    mma16816(acc[mt][nt], a[mt], &bh[nt >> 1][(nt & 1) * 2]);
#pragma unroll
            for (int mt = 0; mt < MT; mt++)
#pragma unroll
                for (int nt = 0; nt < NT; nt++)
                    mma16816(acc[mt][nt], a[mt], &bl[nt >> 1][(nt & 1) * 2]);
#pragma unroll
            for (int mt = 0; mt < MT; mt++)
                ldsm4t(a[mt], s2u(Al + akr * APITCH + amc + mt * 16));
#pragma unroll
            for (int mt = 0; mt < MT; mt++)
#pragma unroll
                for (int nt = 0; nt < NT; nt++)
                    mma16816(acc[mt][nt], a[mt], &bh[nt >> 1][(nt & 1) * 2]);
        }
        __syncthreads();   // protect 2-stage reuse (stage c+1 overwrote c-1)
    }

    const int r  = lane >> 2;
    const int c2 = (lane & 3) * 2;
    int fo[MT][2], go[NT];
#pragma unroll
    for (int mt = 0; mt < MT; mt++) {
        fo[mt][0] = scat_off(m0 + wm + mt * 16 + r,     rs);
        fo[mt][1] = scat_off(m0 + wm + mt * 16 + r + 8, rs);
    }
#pragma unroll
    for (int nt = 0; nt < NT; nt++)
        go[nt] = scat_off(n0 + wn + nt * 8 + c2, cs);

#pragma unroll
    for (int mt = 0; mt < MT; mt++)
#pragma unroll
        for (int nt = 0; nt < NT; nt++)
#pragma unroll
            for (int h = 0; h < 2; h++)
                store_pair(C, Cplane, (size_t)(fo[mt][h] + go[nt]),
                           acc[mt][nt][h * 2], acc[mt][nt][h * 2 + 1]);
}

// ---------------------------------------------------------------------------
// gemm_sm: BM=64, BN=64, 3 CTAs/SM, 3-stage (round-10). Used: G3, G5.
// ---------------------------------------------------------------------------
__global__ void __launch_bounds__(256, 3) gemm_sm(
    const bf16* __restrict__ A, const bf16* __restrict__ B,
    bf16* __restrict__ C, int M, int N, int K,
    size_t Aplane, size_t Bplane, size_t Cplane, Scat rs, Scat cs)
{
    constexpr int BM = 64, BN = 64, BK = 32;
    constexpr int APITCH = BM + 8;      // 72
    constexpr int BPITCH = BN + 8;      // 72
    constexpr int AS_PLANE = BK * APITCH;
    constexpr int BS_PLANE = BK * BPITCH;
    constexpr int STAGE = 2 * AS_PLANE + 2 * BS_PLANE;
    constexpr int NSTG = 3;
    constexpr int NT = 4;
    (void)N;

    extern __shared__ bf16 sm[];

    const int tid  = threadIdx.x;
    const int lane = tid & 31;
    const int warp = tid >> 5;
    const int wm = (warp & 3) * 16;
    const int wn = (warp >> 2) * 32;
    const int m0 = blockIdx.x * BM;
    const int n0 = 0;

    float acc[NT][4];
#pragma unroll
    for (int nt = 0; nt < NT; nt++)
#pragma unroll
        for (int i = 0; i < 4; i++) acc[nt][i] = 0.f;

    const int lk  = tid >> 3;
    const int seg = (tid & 7) * 8;

    auto load_stage = [&](int s, int k0) {
        bf16* base = sm + s * STAGE;
        const bf16* Ag = A + (size_t)(k0 + lk) * (size_t)M + (size_t)(m0 + seg);
        cpa16(s2u(base + lk * APITCH + seg), Ag);
        cpa16(s2u(base + AS_PLANE + lk * APITCH + seg), Ag + Aplane);
        bf16* bb = base + 2 * AS_PLANE;
        const bf16* Bg = B + (size_t)(k0 + lk) * 64 + seg;
        cpa16(s2u(bb + lk * BPITCH + seg), Bg);
        cpa16(s2u(bb + BS_PLANE + lk * BPITCH + seg), Bg + Bplane);
    };

    const int nchunks = K / BK;
    load_stage(0, 0);
    CP_COMMIT();
    if (nchunks > 1) load_stage(1, BK);
    CP_COMMIT();

    for (int c = 0; c < nchunks; c++) {
        CP_WAIT1();
        __syncthreads();

        if (c + 2 < nchunks) load_stage((c + 2) % NSTG, (c + 2) * BK);
        CP_COMMIT();

        const bf16* base = sm + (c % NSTG) * STAGE;
        const bf16* Ah = base;
        const bf16* Al = base + AS_PLANE;
        const bf16* Bh = base + 2 * AS_PLANE;
        const bf16* Bl = base + 2 * AS_PLANE + BS_PLANE;

#pragma unroll
        for (int kk = 0; kk < BK; kk += 16) {
            uint32_t a[4];
            uint32_t bh[NT / 2][4], bl[NT / 2][4];
            const int akr = kk + (lane & 7) + ((lane >> 4) & 1) * 8;
            const int amc = wm + ((lane >> 3) & 1) * 8;
            const int bkr = kk + (lane & 7) + ((lane >> 3) & 1) * 8;
            const int bnc = wn + ((lane >> 4) & 1) * 8;
            ldsm4t(a, s2u(Ah + akr * APITCH + amc));
#pragma unroll
            for (int np = 0; np < NT / 2; np++) {
                ldsm4t(bh[np], s2u(Bh + bkr * BPITCH + bnc + np * 16));
                ldsm4t(bl[np], s2u(Bl + bkr * BPITCH + bnc + np * 16));
            }
#pragma unroll
            for (int nt = 0; nt < NT; nt++)
                mma16816(acc[nt], a, &bh[nt >> 1][(nt & 1) * 2]);
#pragma unroll
            for (int nt = 0; nt < NT; nt++)
                mma16816(acc[nt], a, &bl[nt >> 1][(nt & 1) * 2]);
            ldsm4t(a, s2u(Al + akr * APITCH + amc));
#pragma unroll
            for (int nt = 0; nt < NT; nt++)
                mma16816(acc[nt], a, &bh[nt >> 1][(nt & 1) * 2]);
        }
    }

    const int r  = lane >> 2;
    const int c2 = (lane & 3) * 2;
    int fo[2], go[NT];
    fo[0] = scat_off(m0 + wm + r,     rs);
    fo[1] = scat_off(m0 + wm + r + 8, rs);
#pragma unroll
    for (int nt = 0; nt < NT; nt++)
        go[nt] = scat_off(n0 + wn + nt * 8 + c2, cs);

#pragma unroll
    for (int nt = 0; nt < NT; nt++)
#pragma unroll
        for (int h = 0; h < 2; h++)
            store_pair(C, Cplane, (size_t)(fo[h] + go[nt]),
                       acc[nt][h * 2], acc[nt][h * 2 + 1]);
}

// ---------------------------------------------------------------------------
// Fused prep kernel: split inputs into bf16 hi/lo pairs.
// ---------------------------------------------------------------------------
__device__ __forceinline__ void put_split_g(bf16* dst, size_t plane, size_t i, float x) {
    bf16 h = __float2bfloat16(x);
    dst[i] = h;
    dst[plane + i] = __float2bfloat16(x - __bfloat162float(h));
}

__global__ void prep_all(const float* __restrict__ state,
                         const float* __restrict__ layer,
                         const float* __restrict__ oper) {
    int idx = blockIdx.x * blockDim.x + threadIdx.x;   // 1,605,632 total
    if (idx < 524288) {
        put_split_g(g_S, 524288, idx, state[idx]);
    } else if (idx < 1048576) {
        int i = idx - 524288;
        put_split_g(g_U, 524288, i, layer[i]);
    } else if (idx < 1081344) {
        int i = idx - 1048576;
        put_split_g(g_O, 32768, i, oper[i]);
    } else {
        int i = idx - 1081344;
        int Lb = i & 15; int t = i >> 4;
        int j  = t & 15;   t >>= 4;
        int ii = t & 15;   t >>= 4;
        int l  = t & 15;   t >>= 4;
        int q  = t;
        float x = layer[((((size_t)q * 16 + l) * 16 + j) * 16 + ii) * 16 + Lb];
        put_split_g(g_Ud, 524288, i, x);
    }
}

// ---------------------------------------------------------------------------
// Fused site-0 boundary (exact fp32)
// ---------------------------------------------------------------------------
__global__ void s0_all(const float* __restrict__ st, const float* __restrict__ ly,
                       const float* __restrict__ op, bf16* __restrict__ env) {
    extern __shared__ float sf[];
    float* sY  = sf;           // [k*1024 + M*64 + B]
    float* sC2 = sf + 16384;   // [L*64 + k*4 + O]
    float* sC1 = sf + 17408;   // [j*16 + L]
    const int t = threadIdx.x;
    const int A = blockIdx.x;

    {
        int j = t >> 4, L = t & 15;
        float s = 0.f;
        for (int i = 0; i < 16; i++)
            s += st[i * 64 + A] * ly[j * 256 + i * 16 + L];
        sC1[t] = s;
    }
    for (int e = t; e < 16384; e += 256) {
        int k = e >> 10, M = (e >> 6) & 15, B = e & 63;
        float s = 0.f;
        for (int sx = 0; sx < 16; sx++)
            s += ly[k * 256 + sx * 16 + M] * st[sx * 64 + B];
        sY[e] = s;
    }
    __syncthreads();
    for (int e = t; e < 1024; e += 256) {
        int L = e >> 6, k = (e >> 2) & 15, O = e & 3;
        float s = 0.f;
        for (int j = 0; j < 16; j++)
            s += sC1[j * 16 + L] * op[j * 64 + k * 4 + O];
        sC2[e] = s;
    }
    __syncthreads();
    for (int e = t; e < 65536; e += 256) {
        int B = e & 63, M = (e >> 6) & 15, O = (e >> 10) & 3, L = e >> 12;
        float v = 0.f;
#pragma unroll
        for (int k = 0; k < 16; k++)
            v += sC2[L * 64 + k * 4 + O] * sY[k * 1024 + M * 64 + B];
        size_t off = (size_t)A * 65536 + e;
        bf16 h = __float2bfloat16(v);
        env[off] = h;
        env[ESZ + off] = __float2bfloat16(v - __bfloat162float(h));
    }
}

// ---------------------------------------------------------------------------
// Site-7 boundary
// ---------------------------------------------------------------------------
__global__ void s7_x1(const float* __restrict__ st, const float* __restrict__ ly,
                      float* __restrict__ X1) {
    int idx = blockIdx.x * blockDim.x + threadIdx.x;
    if (idx >= 16384) return;
    int j = idx & 15, l = (idx >> 4) & 15, a = idx >> 8;
    float s = 0.f;
    for (int i = 0; i < 16; i++)
        s += st[a * 1024 + i * 64] * ly[l * 4096 + j * 256 + i * 16];
    X1[idx] = s;
}
__global__ void s7_x2(const float* __restrict__ X1, const float* __restrict__ op,
                      float* __restrict__ X2) {
    int idx = blockIdx.x * blockDim.x + threadIdx.x;
    if (idx >= 65536) return;
    int k = idx & 15, o = (idx >> 4) & 3, l = (idx >> 6) & 15, a = idx >> 10;
    float s = 0.f;
    for (int j = 0; j < 16; j++)
        s += X1[(a * 16 + l) * 16 + j] * op[o * 1024 + j * 64 + k * 4];
    X2[idx] = s;
}
__global__ void s7_x3(const float* __restrict__ X2, const float* __restrict__ ly,
                      float* __restrict__ X3) {
    int idx = blockIdx.x * blockDim.x + threadIdx.x;
    if (idx >= 1048576) return;
    int s5 = idx & 15, m = (idx >> 4) & 15, o = (idx >> 8) & 3,
        l = (idx >> 10) & 15, a = idx >> 14;
    float s = 0.f;
    for (int k = 0; k < 16; k++)
        s += X2[((a * 16 + l) * 4 + o) * 16 + k] * ly[m * 4096 + k * 256 + s5 * 16];
    X3[idx] = s;
}
__global__ void s7_dot(const float* __restrict__ X3, const float* __restrict__ st,
                       const bf16* __restrict__ env, float* __restrict__ partial) {
    __shared__ float red[256];
    int t = blockIdx.x * 256 + threadIdx.x;
    float x3[16];
#pragma unroll
    for (int s = 0; s < 16; s++) x3[s] = X3[t * 16 + s];
    size_t base = (size_t)t * 64;
    float acc = 0.f;
    for (int b = 0; b < 64; b++) {
        float w = 0.f;
#pragma unroll
        for (int s = 0; s < 16; s++) w += x3[s] * st[b * 1024 + s * 64];
        float e = __bfloat162float(env[base + b]) + __bfloat162float(env[ESZ + base + b]);
        acc += e * w;
    }
    red[threadIdx.x] = acc;
    __syncthreads();
    for (int step = 128; step > 0; step >>= 1) {
        if (threadIdx.x < step) red[threadIdx.x] += red[threadIdx.x + step];
        __syncthreads();
    }
    if (threadIdx.x == 0) partial[blockIdx.x] = red[0];
}
__global__ void s7_reduce(const float* __restrict__ partial, float* __restrict__ out) {
    __shared__ float red[256];
    red[threadIdx.x] = partial[threadIdx.x];
    __syncthreads();
    for (int step = 128; step > 0; step >>= 1) {
        if (threadIdx.x < step) red[threadIdx.x] += red[threadIdx.x + step];
        __syncthreads();
    }
    if (threadIdx.x == 0) out[0] = red[0];
}

// ---------------------------------------------------------------------------
extern "C" void kernel_launch(void* const* d_in, const int* in_sizes, int n_in,
                              void* d_out, int out_size) {
    const float* state = (const float*)d_in[0];  // [8, 64, 16, 64]
    const float* layer = (const float*)d_in[1];  // [1, 8, 16, 16, 16, 16]
    const float* oper  = (const float*)d_in[2];  // [8, 4, 16, 16, 4]
    float* out = (float*)d_out;

    bf16 *TA, *TB, *envA, *envB, *S, *U, *Ud, *O;
    cudaGetSymbolAddress((void**)&TA,   g_TA);
    cudaGetSymbolAddress((void**)&TB,   g_TB);
    cudaGetSymbolAddress((void**)&envA, g_envA);
    cudaGetSymbolAddress((void**)&envB, g_envB);
    cudaGetSymbolAddress((void**)&S,    g_S);
    cudaGetSymbolAddress((void**)&U,    g_U);
    cudaGetSymbolAddress((void**)&Ud,   g_Ud);
    cudaGetSymbolAddress((void**)&O,    g_O);

    // fp32 scratch carved from TB (used only after main loop frees it)
    float* fB = (float*)TB;
    float* X1 = fB, *X2 = fB + 32768, *X3 = fB + 131072;
    float* partial = fB + 1310720;

    constexpr int SMEM128 = 3 * (2 * (32 * 136) + 2 * (32 * 136)) * 2;  // 104448
    constexpr int SMEMMID = 2 * (2 * (32 * 72) + 2 * (32 * 136)) * 2;   // 53248
    constexpr int SMEM64  = 3 * (2 * (32 * 72) + 2 * (32 * 72)) * 2;    // 55296
    constexpr int SMEM_S0 = 17664 * 4;                                  // 70656
    cudaFuncSetAttribute(gemm_big, cudaFuncAttributeMaxDynamicSharedMemorySize, SMEM128);
    cudaFuncSetAttribute(gemm_mid, cudaFuncAttributeMaxDynamicSharedMemorySize, SMEMMID);
    cudaFuncSetAttribute(gemm_sm,  cudaFuncAttributeMaxDynamicSharedMemorySize, SMEM64);
    cudaFuncSetAttribute(s0_all,   cudaFuncAttributeMaxDynamicSharedMemorySize, SMEM_S0);

    prep_all<<<6272, 256>>>(state, layer, oper);
    s0_all<<<64, 256, SMEM_S0>>>(state, layer, oper, envA);

    bf16* envc = envA;
    bf16* envn = envB;

    for (int q = 1; q <= 6; q++) {
        const bf16* Sq  = S  + (size_t)q * 65536;
        const bf16* Uq  = U  + (size_t)q * 65536;
        const bf16* Udq = Ud + (size_t)q * 65536;
        const bf16* Oq  = O  + (size_t)q * 4096;

        // G1: T1 = env x S      M=65536 N=1024 K=64   (env -> TA)
        {
            Scat rs = {{64, 16, 4, 16}, {64, 4096, 65536, 4194304}};
            Scat cs = {{64, 16, 1, 1}, {1, 262144, 0, 0}};
            gemm_big<<<dim3(65536 / 128, 1024 / 128), 256, SMEM128>>>(
                envc, Sq, TA, 65536, 1024, 64, ESZ, 524288, TSZ, rs, cs);
        }
        // G2: T2 = T1 x Ud      M=262144 N=256 K=256  (TA -> TB), 3 CTA/SM
        {
            Scat rs = {{64, 64, 16, 4}, {16, 1024, 65536, 16777216}};
            Scat cs = {{16, 16, 1, 1}, {1, 1048576, 0, 0}};
            gemm_mid<<<dim3(262144 / 64, 256 / 128), 256, SMEMMID>>>(
                TA, Udq, TB, 262144, 256, 256, TSZ, 524288, TSZ, rs, cs);
        }
        // G3: T3 = T2 x O       M=1048576 N=64 K=64   (TB -> TA), small tiles
        {
            Scat rs = {{16, 64, 64, 16}, {4, 64, 4096, 4194304}};
            Scat cs = {{4, 16, 1, 1}, {1, 262144, 0, 0}};
            gemm_sm<<<dim3(1048576 / 64, 1), 256, SMEM64>>>(
                TB, Oq, TA, 1048576, 64, 64, TSZ, 32768, TSZ, rs, cs);
        }
        // G4: T4 = T3 x U       M=262144 N=256 K=256  (TA -> TB), 3 CTA/SM
        {
            Scat rs = {{4, 16, 64, 64}, {16, 64, 1024, 1048576}};
            Scat cs = {{16, 16, 1, 1}, {1, 65536, 0, 0}};
            gemm_mid<<<dim3(262144 / 64, 256 / 128), 256, SMEMMID>>>(
                TA, Uq, TB, 262144, 256, 256, TSZ, 524288, TSZ, rs, cs);
        }
        // G5: env' = T4 x S     M=65536 N=64 K=1024   (TB -> env), small tiles
        {
            Scat rs = {{16, 4, 16, 64}, {64, 1024, 4096, 65536}};
            Scat cs = {{64, 1, 1, 1}, {1, 0, 0, 0}};
            gemm_sm<<<dim3(65536 / 64, 1), 256, SMEM64>>>(
                TB, Sq, envn, 65536, 64, 1024, TSZ, 524288, ESZ, rs, cs);
        }

        bf16* t = envc; envc = envn; envn = t;
    }

    // Site 7 boundary
    const float* st7 = state + 7 * 65536;
    const float* ly7 = layer + 7 * 65536;
    const float* op7 = oper  + 7 * 4096;
    s7_x1<<<64, 256>>>(st7, ly7, X1);
    s7_x2<<<256, 256>>>(X1, op7, X2);
    s7_x3<<<4096, 256>>>(X2, ly7, X3);
    s7_dot<<<256, 256>>>(X3, st7, envc, partial);
    s7_reduce<<<1, 256>>>(partial, out);
}

// round 12
// speedup vs baseline: 1.0778x; 1.0778x over previous
#include <cuda_runtime.h>
#include <cuda_bf16.h>
#include <cstdint>

using bf16 = __nv_bfloat16;

#define NQ 8
#define TSZ 67108864UL   // elements per T plane
#define ESZ 4194304UL    // elements per env plane

// Static device scratch. hi plane [0,P), lo plane [P,2P).
__device__ bf16 g_TA[2 * TSZ];
__device__ bf16 g_TB[2 * TSZ];
__device__ bf16 g_envA[2 * ESZ];
__device__ bf16 g_envB[2 * ESZ];
__device__ bf16 g_S[2 * 524288];   // state split  (native layout)
__device__ bf16 g_U[2 * 524288];   // layer split  (native layout)
__device__ bf16 g_Ud[2 * 524288];  // permuted U-dagger split
__device__ bf16 g_O[2 * 32768];    // operator split (native layout)

struct Scat { int radix[4]; int stride[4]; };

__device__ __forceinline__ int scat_off(int idx, const Scat s) {
    int off = 0;
#pragma unroll
    for (int d = 0; d < 4; d++) {
        off += (idx % s.radix[d]) * s.stride[d];
        idx /= s.radix[d];
    }
    return off;
}

// ---------------------------------------------------------------------------
// PTX helpers
// ---------------------------------------------------------------------------
__device__ __forceinline__ uint32_t s2u(const void* p) {
    return (uint32_t)__cvta_generic_to_shared(p);
}
__device__ __forceinline__ void cpa16(uint32_t saddr, const void* g) {
    asm volatile("cp.async.cg.shared.global [%0], [%1], 16;\n" :: "r"(saddr), "l"(g));
}
#define CP_COMMIT() asm volatile("cp.async.commit_group;\n")
#define CP_WAIT1()  asm volatile("cp.async.wait_group 1;\n")
#define CP_WAIT0()  asm volatile("cp.async.wait_group 0;\n")

__device__ __forceinline__ void ldsm4t(uint32_t* r, uint32_t addr) {
    asm volatile("ldmatrix.sync.aligned.m8n8.x4.trans.shared.b16 {%0,%1,%2,%3}, [%4];"
                 : "=r"(r[0]), "=r"(r[1]), "=r"(r[2]), "=r"(r[3]) : "r"(addr));
}
__device__ __forceinline__ void mma16816(float* d, const uint32_t* a, const uint32_t* b) {
    asm volatile(
        "mma.sync.aligned.m16n8k16.row.col.f32.bf16.bf16.f32 "
        "{%0,%1,%2,%3},{%4,%5,%6,%7},{%8,%9},{%0,%1,%2,%3};"
        : "+f"(d[0]), "+f"(d[1]), "+f"(d[2]), "+f"(d[3])
        : "r"(a[0]), "r"(a[1]), "r"(a[2]), "r"(a[3]), "r"(b[0]), "r"(b[1]));
}

__device__ __forceinline__ void store_pair(bf16* C, size_t Cplane, size_t off,
                                           float v0, float v1) {
    __nv_bfloat162 ph, pl;
    ph.x = __float2bfloat16(v0);
    ph.y = __float2bfloat16(v1);
    pl.x = __float2bfloat16(v0 - __bfloat162float(ph.x));
    pl.y = __float2bfloat16(v1 - __bfloat162float(ph.y));
    *(__nv_bfloat162*)(C + off) = ph;
    *(__nv_bfloat162*)(C + Cplane + off) = pl;
}

// ---------------------------------------------------------------------------
// gemm_big: BM=128, BN=128, 2 CTAs/SM, 3-stage (R10 engine). Used: G2, G4.
// ---------------------------------------------------------------------------
__global__ void __launch_bounds__(256, 2) gemm_big(
    const bf16* __restrict__ A, const bf16* __restrict__ B,
    bf16* __restrict__ C, int M, int N, int K,
    size_t Aplane, size_t Bplane, size_t Cplane, Scat rs, Scat cs)
{
    constexpr int BM = 128, BN = 128, BK = 32;
    constexpr int APITCH = BM + 8;
    constexpr int BPITCH = BN + 8;
    constexpr int AS_PLANE = BK * APITCH;
    constexpr int BS_PLANE = BK * BPITCH;
    constexpr int STAGE = 2 * AS_PLANE + 2 * BS_PLANE;
    constexpr int NSTG = 3;
    constexpr int NT = BN / 16;   // 8
    constexpr int MT = 2;

    extern __shared__ bf16 sm[];

    const int tid  = threadIdx.x;
    const int lane = tid & 31;
    const int warp = tid >> 5;
    const int wm = (warp & 3) * 32;
    const int wn = (warp >> 2) * (BN / 2);
    const int m0 = blockIdx.x * BM;
    const int n0 = blockIdx.y * BN;

    float acc[MT][NT][4];
#pragma unroll
    for (int mt = 0; mt < MT; mt++)
#pragma unroll
        for (int nt = 0; nt < NT; nt++)
#pragma unroll
            for (int i = 0; i < 4; i++) acc[mt][nt][i] = 0.f;

    const int lk   = tid >> 3;
    const int mseg = (tid & 7) * 16;

    auto load_stage = [&](int s, int k0) {
        bf16* base = sm + s * STAGE;
        const bf16* Ag = A + (size_t)(k0 + lk) * (size_t)M + (size_t)(m0 + mseg);
        uint32_t da = s2u(base + lk * APITCH + mseg);
        cpa16(da,      Ag);
        cpa16(da + 16, Ag + 8);
        uint32_t dal = s2u(base + AS_PLANE + lk * APITCH + mseg);
        cpa16(dal,      Ag + Aplane);
        cpa16(dal + 16, Ag + Aplane + 8);
        bf16* bb = base + 2 * AS_PLANE;
        const bf16* Bg = B + (size_t)(k0 + lk) * (size_t)N + (size_t)(n0 + mseg);
        uint32_t db = s2u(bb + lk * BPITCH + mseg);
        cpa16(db,      Bg);
        cpa16(db + 16, Bg + 8);
        uint32_t dbl = s2u(bb + BS_PLANE + lk * BPITCH + mseg);
        cpa16(dbl,      Bg + Bplane);
        cpa16(dbl + 16, Bg + Bplane + 8);
    };

    const int nchunks = K / BK;
    load_stage(0, 0);
    CP_COMMIT();
    if (nchunks > 1) load_stage(1, BK);
    CP_COMMIT();

    for (int c = 0; c < nchunks; c++) {
        CP_WAIT1();
        __syncthreads();

        if (c + 2 < nchunks) load_stage((c + 2) % NSTG, (c + 2) * BK);
        CP_COMMIT();

        const bf16* base = sm + (c % NSTG) * STAGE;
        const bf16* Ah = base;
        const bf16* Al = base + AS_PLANE;
        const bf16* Bh = base + 2 * AS_PLANE;
        const bf16* Bl = base + 2 * AS_PLANE + BS_PLANE;

#pragma unroll
        for (int kk = 0; kk < BK; kk += 16) {
            uint32_t a[MT][4];
            uint32_t bh[NT / 2][4], bl[NT / 2][4];
            const int akr = kk + (lane & 7) + ((lane >> 4) & 1) * 8;
            const int amc = wm + ((lane >> 3) & 1) * 8;
            const int bkr = kk + (lane & 7) + ((lane >> 3) & 1) * 8;
            const int bnc = wn + ((lane >> 4) & 1) * 8;
#pragma unroll
            for (int mt = 0; mt < MT; mt++)
                ldsm4t(a[mt], s2u(Ah + akr * APITCH + amc + mt * 16));
#pragma unroll
            for (int np = 0; np < NT / 2; np++) {
                ldsm4t(bh[np], s2u(Bh + bkr * BPITCH + bnc + np * 16));
                ldsm4t(bl[np], s2u(Bl + bkr * BPITCH + bnc + np * 16));
            }
#pragma unroll
            for (int mt = 0; mt < MT; mt++)
#pragma unroll
                for (int nt = 0; nt < NT; nt++)
                    mma16816(acc[mt][nt], a[mt], &bh[nt >> 1][(nt & 1) * 2]);
#pragma unroll
            for (int mt = 0; mt < MT; mt++)
#pragma unroll
                for (int nt = 0; nt < NT; nt++)
                    mma16816(acc[mt][nt], a[mt], &bl[nt >> 1][(nt & 1) * 2]);
#pragma unroll
            for (int mt = 0; mt < MT; mt++)
                ldsm4t(a[mt], s2u(Al + akr * APITCH + amc + mt * 16));
#pragma unroll
            for (int mt = 0; mt < MT; mt++)
#pragma unroll
                for (int nt = 0; nt < NT; nt++)
                    mma16816(acc[mt][nt], a[mt], &bh[nt >> 1][(nt & 1) * 2]);
        }
    }

    const int r  = lane >> 2;
    const int c2 = (lane & 3) * 2;
    int fo[MT][2], go[NT];
#pragma unroll
    for (int mt = 0; mt < MT; mt++) {
        fo[mt][0] = scat_off(m0 + wm + mt * 16 + r,     rs);
        fo[mt][1] = scat_off(m0 + wm + mt * 16 + r + 8, rs);
    }
#pragma unroll
    for (int nt = 0; nt < NT; nt++)
        go[nt] = scat_off(n0 + wn + nt * 8 + c2, cs);

#pragma unroll
    for (int mt = 0; mt < MT; mt++)
#pragma unroll
        for (int nt = 0; nt < NT; nt++)
#pragma unroll
            for (int h = 0; h < 2; h++)
                store_pair(C, Cplane, (size_t)(fo[mt][h] + go[nt]),
                           acc[mt][nt][h * 2], acc[mt][nt][h * 2 + 1]);
}

// ---------------------------------------------------------------------------
// gemm_big64: BM=128, BN=128, K=64 resident in smem, single stage, 2 CTAs/SM.
// One load, one wait, one barrier, 4 kk steps. Used: G1.
// ---------------------------------------------------------------------------
__global__ void __launch_bounds__(256, 2) gemm_big64(
    const bf16* __restrict__ A, const bf16* __restrict__ B,
    bf16* __restrict__ C, int M, int N,
    size_t Aplane, size_t Bplane, size_t Cplane, Scat rs, Scat cs)
{
    constexpr int BM = 128, BN = 128, KK = 64;
    constexpr int APITCH = BM + 8;
    constexpr int BPITCH = BN + 8;
    constexpr int AS_PLANE = KK * APITCH;
    constexpr int BS_PLANE = KK * BPITCH;
    constexpr int NT = BN / 16;
    constexpr int MT = 2;

    extern __shared__ bf16 sm[];

    const int tid  = threadIdx.x;
    const int lane = tid & 31;
    const int warp = tid >> 5;
    const int wm = (warp & 3) * 32;
    const int wn = (warp >> 2) * (BN / 2);
    const int m0 = blockIdx.x * BM;
    const int n0 = blockIdx.y * BN;

    float acc[MT][NT][4];
#pragma unroll
    for (int mt = 0; mt < MT; mt++)
#pragma unroll
        for (int nt = 0; nt < NT; nt++)
#pragma unroll
            for (int i = 0; i < 4; i++) acc[mt][nt][i] = 0.f;

    bf16* Ah = sm;
    bf16* Al = sm + AS_PLANE;
    bf16* Bh = sm + 2 * AS_PLANE;
    bf16* Bl = sm + 2 * AS_PLANE + BS_PLANE;

    const int lk   = tid >> 3;        // 0..31
    const int mseg = (tid & 7) * 16;

#pragma unroll
    for (int h = 0; h < 2; h++) {
        int row = lk + 32 * h;
        const bf16* Ag = A + (size_t)row * (size_t)M + (size_t)(m0 + mseg);
        uint32_t da = s2u(Ah + row * APITCH + mseg);
        cpa16(da,      Ag);
        cpa16(da + 16, Ag + 8);
        uint32_t dal = s2u(Al + row * APITCH + mseg);
        cpa16(dal,      Ag + Aplane);
        cpa16(dal + 16, Ag + Aplane + 8);
        const bf16* Bg = B + (size_t)row * (size_t)N + (size_t)(n0 + mseg);
        uint32_t db = s2u(Bh + row * BPITCH + mseg);
        cpa16(db,      Bg);
        cpa16(db + 16, Bg + 8);
        uint32_t dbl = s2u(Bl + row * BPITCH + mseg);
        cpa16(dbl,      Bg + Bplane);
        cpa16(dbl + 16, Bg + Bplane + 8);
    }
    CP_COMMIT();
    CP_WAIT0();
    __syncthreads();

#pragma unroll
    for (int kk = 0; kk < KK; kk += 16) {
        uint32_t a[MT][4];
        uint32_t bh[NT / 2][4], bl[NT / 2][4];
        const int akr = kk + (lane & 7) + ((lane >> 4) & 1) * 8;
        const int amc = wm + ((lane >> 3) & 1) * 8;
        const int bkr = kk + (lane & 7) + ((lane >> 3) & 1) * 8;
        const int bnc = wn + ((lane >> 4) & 1) * 8;
#pragma unroll
        for (int mt = 0; mt < MT; mt++)
            ldsm4t(a[mt], s2u(Ah + akr * APITCH + amc + mt * 16));
#pragma unroll
        for (int np = 0; np < NT / 2; np++) {
            ldsm4t(bh[np], s2u(Bh + bkr * BPITCH + bnc + np * 16));
            ldsm4t(bl[np], s2u(Bl + bkr * BPITCH + bnc + np * 16));
        }
#pragma unroll
        for (int mt = 0; mt < MT; mt++)
#pragma unroll
            for (int nt = 0; nt < NT; nt++)
                mma16816(acc[mt][nt], a[mt], &bh[nt >> 1][(nt & 1) * 2]);
#pragma unroll
        for (int mt = 0; mt < MT; mt++)
#pragma unroll
            for (int nt = 0; nt < NT; nt++)
                mma16816(acc[mt][nt], a[mt], &bl[nt >> 1][(nt & 1) * 2]);
#pragma unroll
        for (int mt = 0; mt < MT; mt++)
            ldsm4t(a[mt], s2u(Al + akr * APITCH + amc + mt * 16));
#pragma unroll
        for (int mt = 0; mt < MT; mt++)
#pragma unroll
            for (int nt = 0; nt < NT; nt++)
                mma16816(acc[mt][nt], a[mt], &bh[nt >> 1][(nt & 1) * 2]);
    }

    const int r  = lane >> 2;
    const int c2 = (lane & 3) * 2;
    int fo[MT][2], go[NT];
#pragma unroll
    for (int mt = 0; mt < MT; mt++) {
        fo[mt][0] = scat_off(m0 + wm + mt * 16 + r,     rs);
        fo[mt][1] = scat_off(m0 + wm + mt * 16 + r + 8, rs);
    }
#pragma unroll
    for (int nt = 0; nt < NT; nt++)
        go[nt] = scat_off(n0 + wn + nt * 8 + c2, cs);

#pragma unroll
    for (int mt = 0; mt < MT; mt++)
#pragma unroll
        for (int nt = 0; nt < NT; nt++)
#pragma unroll
            for (int h = 0; h < 2; h++)
                store_pair(C, Cplane, (size_t)(fo[mt][h] + go[nt]),
                           acc[mt][nt][h * 2], acc[mt][nt][h * 2 + 1]);
}

// ---------------------------------------------------------------------------
// gemm_sm: BM=64, BN=64, 3 CTAs/SM, 3-stage (R10). Used: G5 (K=1024).
// ---------------------------------------------------------------------------
__global__ void __launch_bounds__(256, 3) gemm_sm(
    const bf16* __restrict__ A, const bf16* __restrict__ B,
    bf16* __restrict__ C, int M, int N, int K,
    size_t Aplane, size_t Bplane, size_t Cplane, Scat rs, Scat cs)
{
    constexpr int BM = 64, BN = 64, BK = 32;
    constexpr int APITCH = BM + 8;      // 72
    constexpr int BPITCH = BN + 8;      // 72
    constexpr int AS_PLANE = BK * APITCH;
    constexpr int BS_PLANE = BK * BPITCH;
    constexpr int STAGE = 2 * AS_PLANE + 2 * BS_PLANE;
    constexpr int NSTG = 3;
    constexpr int NT = 4;
    (void)N;

    extern __shared__ bf16 sm[];

    const int tid  = threadIdx.x;
    const int lane = tid & 31;
    const int warp = tid >> 5;
    const int wm = (warp & 3) * 16;
    const int wn = (warp >> 2) * 32;
    const int m0 = blockIdx.x * BM;
    const int n0 = 0;

    float acc[NT][4];
#pragma unroll
    for (int nt = 0; nt < NT; nt++)
#pragma unroll
        for (int i = 0; i < 4; i++) acc[nt][i] = 0.f;

    const int lk  = tid >> 3;
    const int seg = (tid & 7) * 8;

    auto load_stage = [&](int s, int k0) {
        bf16* base = sm + s * STAGE;
        const bf16* Ag = A + (size_t)(k0 + lk) * (size_t)M + (size_t)(m0 + seg);
        cpa16(s2u(base + lk * APITCH + seg), Ag);
        cpa16(s2u(base + AS_PLANE + lk * APITCH + seg), Ag + Aplane);
        bf16* bb = base + 2 * AS_PLANE;
        const bf16* Bg = B + (size_t)(k0 + lk) * 64 + seg;
        cpa16(s2u(bb + lk * BPITCH + seg), Bg);
        cpa16(s2u(bb + BS_PLANE + lk * BPITCH + seg), Bg + Bplane);
    };

    const int nchunks = K / BK;
    load_stage(0, 0);
    CP_COMMIT();
    if (nchunks > 1) load_stage(1, BK);
    CP_COMMIT();

    for (int c = 0; c < nchunks; c++) {
        CP_WAIT1();
        __syncthreads();

        if (c + 2 < nchunks) load_stage((c + 2) % NSTG, (c + 2) * BK);
        CP_COMMIT();

        const bf16* base = sm + (c % NSTG) * STAGE;
        const bf16* Ah = base;
        const bf16* Al = base + AS_PLANE;
        const bf16* Bh = base + 2 * AS_PLANE;
        const bf16* Bl = base + 2 * AS_PLANE + BS_PLANE;

#pragma unroll
        for (int kk = 0; kk < BK; kk += 16) {
            uint32_t a[4];
            uint32_t bh[NT / 2][4], bl[NT / 2][4];
            const int akr = kk + (lane & 7) + ((lane >> 4) & 1) * 8;
            const int amc = wm + ((lane >> 3) & 1) * 8;
            const int bkr = kk + (lane & 7) + ((lane >> 3) & 1) * 8;
            const int bnc = wn + ((lane >> 4) & 1) * 8;
            ldsm4t(a, s2u(Ah + akr * APITCH + amc));
#pragma unroll
            for (int np = 0; np < NT / 2; np++) {
                ldsm4t(bh[np], s2u(Bh + bkr * BPITCH + bnc + np * 16));
                ldsm4t(bl[np], s2u(Bl + bkr * BPITCH + bnc + np * 16));
            }
#pragma unroll
            for (int nt = 0; nt < NT; nt++)
                mma16816(acc[nt], a, &bh[nt >> 1][(nt & 1) * 2]);
#pragma unroll
            for (int nt = 0; nt < NT; nt++)
                mma16816(acc[nt], a, &bl[nt >> 1][(nt & 1) * 2]);
            ldsm4t(a, s2u(Al + akr * APITCH + amc));
#pragma unroll
            for (int nt = 0; nt < NT; nt++)
                mma16816(acc[nt], a, &bh[nt >> 1][(nt & 1) * 2]);
        }
    }

    const int r  = lane >> 2;
    const int c2 = (lane & 3) * 2;
    int fo[2], go[NT];
    fo[0] = scat_off(m0 + wm + r,     rs);
    fo[1] = scat_off(m0 + wm + r + 8, rs);
#pragma unroll
    for (int nt = 0; nt < NT; nt++)
        go[nt] = scat_off(n0 + wn + nt * 8 + c2, cs);

#pragma unroll
    for (int nt = 0; nt < NT; nt++)
#pragma unroll
        for (int h = 0; h < 2; h++)
            store_pair(C, Cplane, (size_t)(fo[h] + go[nt]),
                       acc[nt][h * 2], acc[nt][h * 2 + 1]);
}

// ---------------------------------------------------------------------------
// gemm_sm64: BM=64, BN=64, K=64 resident, single stage, 3 CTAs/SM. Used: G3.
// ---------------------------------------------------------------------------
__global__ void __launch_bounds__(256, 3) gemm_sm64(
    const bf16* __restrict__ A, const bf16* __restrict__ B,
    bf16* __restrict__ C, int M,
    size_t Aplane, size_t Bplane, size_t Cplane, Scat rs, Scat cs)
{
    constexpr int BM = 64, KK = 64;
    constexpr int APITCH = BM + 8;      // 72
    constexpr int BPITCH = 64 + 8;      // 72
    constexpr int AS_PLANE = KK * APITCH;
    constexpr int BS_PLANE = KK * BPITCH;
    constexpr int NT = 4;

    extern __shared__ bf16 sm[];

    const int tid  = threadIdx.x;
    const int lane = tid & 31;
    const int warp = tid >> 5;
    const int wm = (warp & 3) * 16;
    const int wn = (warp >> 2) * 32;
    const int m0 = blockIdx.x * BM;

    float acc[NT][4];
#pragma unroll
    for (int nt = 0; nt < NT; nt++)
#pragma unroll
        for (int i = 0; i < 4; i++) acc[nt][i] = 0.f;

    bf16* Ah = sm;
    bf16* Al = sm + AS_PLANE;
    bf16* Bh = sm + 2 * AS_PLANE;
    bf16* Bl = sm + 2 * AS_PLANE + BS_PLANE;

    const int lk  = tid >> 3;
    const int seg = (tid & 7) * 8;

#pragma unroll
    for (int h = 0; h < 2; h++) {
        int row = lk + 32 * h;
        const bf16* Ag = A + (size_t)row * (size_t)M + (size_t)(m0 + seg);
        cpa16(s2u(Ah + row * APITCH + seg), Ag);
        cpa16(s2u(Al + row * APITCH + seg), Ag + Aplane);
        const bf16* Bg = B + (size_t)row * 64 + seg;
        cpa16(s2u(Bh + row * BPITCH + seg), Bg);
        cpa16(s2u(Bl + row * BPITCH + seg), Bg + Bplane);
    }
    CP_COMMIT();
    CP_WAIT0();
    __syncthreads();

#pragma unroll
    for (int kk = 0; kk < KK; kk += 16) {
        uint32_t a[4];
        uint32_t bh[NT / 2][4], bl[NT / 2][4];
        const int akr = kk + (lane & 7) + ((lane >> 4) & 1) * 8;
        const int amc = wm + ((lane >> 3) & 1) * 8;
        const int bkr = kk + (lane & 7) + ((lane >> 3) & 1) * 8;
        const int bnc = wn + ((lane >> 4) & 1) * 8;
        ldsm4t(a, s2u(Ah + akr * APITCH + amc));
#pragma unroll
        for (int np = 0; np < NT / 2; np++) {
            ldsm4t(bh[np], s2u(Bh + bkr * BPITCH + bnc + np * 16));
            ldsm4t(bl[np], s2u(Bl + bkr * BPITCH + bnc + np * 16));
        }
#pragma unroll
        for (int nt = 0; nt < NT; nt++)
            mma16816(acc[nt], a, &bh[nt >> 1][(nt & 1) * 2]);
#pragma unroll
        for (int nt = 0; nt < NT; nt++)
            mma16816(acc[nt], a, &bl[nt >> 1][(nt & 1) * 2]);
        ldsm4t(a, s2u(Al + akr * APITCH + amc));
#pragma unroll
        for (int nt = 0; nt < NT; nt++)
            mma16816(acc[nt], a, &bh[nt >> 1][(nt & 1) * 2]);
    }

    const int r  = lane >> 2;
    const int c2 = (lane & 3) * 2;
    int fo[2], go[NT];
    fo[0] = scat_off(m0 + wm + r,     rs);
    fo[1] = scat_off(m0 + wm + r + 8, rs);
#pragma unroll
    for (int nt = 0; nt < NT; nt++)
        go[nt] = scat_off(wn + nt * 8 + c2, cs);

#pragma unroll
    for (int nt = 0; nt < NT; nt++)
#pragma unroll
        for (int h = 0; h < 2; h++)
            store_pair(C, Cplane, (size_t)(fo[h] + go[nt]),
                       acc[nt][h * 2], acc[nt][h * 2 + 1]);
}

// ---------------------------------------------------------------------------
// Fused prep kernel: split inputs into bf16 hi/lo pairs.
// ---------------------------------------------------------------------------
__device__ __forceinline__ void put_split_g(bf16* dst, size_t plane, size_t i, float x) {
    bf16 h = __float2bfloat16(x);
    dst[i] = h;
    dst[plane + i] = __float2bfloat16(x - __bfloat162float(h));
}

__global__ void prep_all(const float* __restrict__ state,
                         const float* __restrict__ layer,
                         const float* __restrict__ oper) {
    int idx = blockIdx.x * blockDim.x + threadIdx.x;   // 1,605,632 total
    if (idx < 524288) {
        put_split_g(g_S, 524288, idx, state[idx]);
    } else if (idx < 1048576) {
        int i = idx - 524288;
        put_split_g(g_U, 524288, i, layer[i]);
    } else if (idx < 1081344) {
        int i = idx - 1048576;
        put_split_g(g_O, 32768, i, oper[i]);
    } else {
        int i = idx - 1081344;
        int Lb = i & 15; int t = i >> 4;
        int j  = t & 15;   t >>= 4;
        int ii = t & 15;   t >>= 4;
        int l  = t & 15;   t >>= 4;
        int q  = t;
        float x = layer[((((size_t)q * 16 + l) * 16 + j) * 16 + ii) * 16 + Lb];
        put_split_g(g_Ud, 524288, i, x);
    }
}

// ---------------------------------------------------------------------------
// Fused site-0 boundary (exact fp32)
// ---------------------------------------------------------------------------
__global__ void s0_all(const float* __restrict__ st, const float* __restrict__ ly,
                       const float* __restrict__ op, bf16* __restrict__ env) {
    extern __shared__ float sf[];
    float* sY  = sf;           // [k*1024 + M*64 + B]
    float* sC2 = sf + 16384;   // [L*64 + k*4 + O]
    float* sC1 = sf + 17408;   // [j*16 + L]
    const int t = threadIdx.x;
    const int A = blockIdx.x;

    {
        int j = t >> 4, L = t & 15;
        float s = 0.f;
        for (int i = 0; i < 16; i++)
            s += st[i * 64 + A] * ly[j * 256 + i * 16 + L];
        sC1[t] = s;
    }
    for (int e = t; e < 16384; e += 256) {
        int k = e >> 10, M = (e >> 6) & 15, B = e & 63;
        float s = 0.f;
        for (int sx = 0; sx < 16; sx++)
            s += ly[k * 256 + sx * 16 + M] * st[sx * 64 + B];
        sY[e] = s;
    }
    __syncthreads();
    for (int e = t; e < 1024; e += 256) {
        int L = e >> 6, k = (e >> 2) & 15, O = e & 3;
        float s = 0.f;
        for (int j = 0; j < 16; j++)
            s += sC1[j * 16 + L] * op[j * 64 + k * 4 + O];
        sC2[e] = s;
    }
    __syncthreads();
    for (int e = t; e < 65536; e += 256) {
        int B = e & 63, M = (e >> 6) & 15, O = (e >> 10) & 3, L = e >> 12;
        float v = 0.f;
#pragma unroll
        for (int k = 0; k < 16; k++)
            v += sC2[L * 64 + k * 4 + O] * sY[k * 1024 + M * 64 + B];
        size_t off = (size_t)A * 65536 + e;
        bf16 h = __float2bfloat16(v);
        env[off] = h;
        env[ESZ + off] = __float2bfloat16(v - __bfloat162float(h));
    }
}

// ---------------------------------------------------------------------------
// Site-7 boundary
// ---------------------------------------------------------------------------
__global__ void s7_x1(const float* __restrict__ st, const float* __restrict__ ly,
                      float* __restrict__ X1) {
    int idx = blockIdx.x * blockDim.x + threadIdx.x;
    if (idx >= 16384) return;
    int j = idx & 15, l = (idx >> 4) & 15, a = idx >> 8;
    float s = 0.f;
    for (int i = 0; i < 16; i++)
        s += st[a * 1024 + i * 64] * ly[l * 4096 + j * 256 + i * 16];
    X1[idx] = s;
}
__global__ void s7_x2(const float* __restrict__ X1, const float* __restrict__ op,
                      float* __restrict__ X2) {
    int idx = blockIdx.x * blockDim.x + threadIdx.x;
    if (idx >= 65536) return;
    int k = idx & 15, o = (idx >> 4) & 3, l = (idx >> 6) & 15, a = idx >> 10;
    float s = 0.f;
    for (int j = 0; j < 16; j++)
        s += X1[(a * 16 + l) * 16 + j] * op[o * 1024 + j * 64 + k * 4];
    X2[idx] = s;
}
__global__ void s7_x3(const float* __restrict__ X2, const float* __restrict__ ly,
                      float* __restrict__ X3) {
    int idx = blockIdx.x * blockDim.x + threadIdx.x;
    if (idx >= 1048576) return;
    int s5 = idx & 15, m = (idx >> 4) & 15, o = (idx >> 8) & 3,
        l = (idx >> 10) & 15, a = idx >> 14;
    float s = 0.f;
    for (int k = 0; k < 16; k++)
        s += X2[((a * 16 + l) * 4 + o) * 16 + k] * ly[m * 4096 + k * 256 + s5 * 16];
    X3[idx] = s;
}
__global__ void s7_dot(const float* __restrict__ X3, const float* __restrict__ st,
                       const bf16* __restrict__ env, float* __restrict__ partial) {
    __shared__ float red[256];
    int t = blockIdx.x * 256 + threadIdx.x;
    float x3[16];
#pragma unroll
    for (int s = 0; s < 16; s++) x3[s] = X3[t * 16 + s];
    size_t base = (size_t)t * 64;
    float acc = 0.f;
    for (int b = 0; b < 64; b++) {
        float w = 0.f;
#pragma unroll
        for (int s = 0; s < 16; s++) w += x3[s] * st[b * 1024 + s * 64];
        float e = __bfloat162float(env[base + b]) + __bfloat162float(env[ESZ + base + b]);
        acc += e * w;
    }
    red[threadIdx.x] = acc;
    __syncthreads();
    for (int step = 128; step > 0; step >>= 1) {
        if (threadIdx.x < step) red[threadIdx.x] += red[threadIdx.x + step];
        __syncthreads();
    }
    if (threadIdx.x == 0) partial[blockIdx.x] = red[0];
}
__global__ void s7_reduce(const float* __restrict__ partial, float* __restrict__ out) {
    __shared__ float red[256];
    red[threadIdx.x] = partial[threadIdx.x];
    __syncthreads();
    for (int step = 128; step > 0; step >>= 1) {
        if (threadIdx.x < step) red[threadIdx.x] += red[threadIdx.x + step];
        __syncthreads();
    }
    if (threadIdx.x == 0) out[0] = red[0];
}

// ---------------------------------------------------------------------------
extern "C" void kernel_launch(void* const* d_in, const int* in_sizes, int n_in,
                              void* d_out, int out_size) {
    const float* state = (const float*)d_in[0];  // [8, 64, 16, 64]
    const float* layer = (const float*)d_in[1];  // [1, 8, 16, 16, 16, 16]
    const float* oper  = (const float*)d_in[2];  // [8, 4, 16, 16, 4]
    float* out = (float*)d_out;

    bf16 *TA, *TB, *envA, *envB, *S, *U, *Ud, *O;
    cudaGetSymbolAddress((void**)&TA,   g_TA);
    cudaGetSymbolAddress((void**)&TB,   g_TB);
    cudaGetSymbolAddress((void**)&envA, g_envA);
    cudaGetSymbolAddress((void**)&envB, g_envB);
    cudaGetSymbolAddress((void**)&S,    g_S);
    cudaGetSymbolAddress((void**)&U,    g_U);
    cudaGetSymbolAddress((void**)&Ud,   g_Ud);
    cudaGetSymbolAddress((void**)&O,    g_O);

    // fp32 scratch carved from TB (used only after main loop frees it)
    float* fB = (float*)TB;
    float* X1 = fB, *X2 = fB + 32768, *X3 = fB + 131072;
    float* partial = fB + 1310720;

    constexpr int SMEM128  = 3 * (2 * (32 * 136) + 2 * (32 * 136)) * 2;  // 104448
    constexpr int SMEMB64  = (2 * (64 * 136) + 2 * (64 * 136)) * 2;      // 69632
    constexpr int SMEM64   = 3 * (2 * (32 * 72) + 2 * (32 * 72)) * 2;    // 55296
    constexpr int SMEMS64  = (2 * (64 * 72) + 2 * (64 * 72)) * 2;        // 36864
    constexpr int SMEM_S0  = 17664 * 4;                                  // 70656
    cudaFuncSetAttribute(gemm_big,   cudaFuncAttributeMaxDynamicSharedMemorySize, SMEM128);
    cudaFuncSetAttribute(gemm_big64, cudaFuncAttributeMaxDynamicSharedMemorySize, SMEMB64);
    cudaFuncSetAttribute(gemm_sm,    cudaFuncAttributeMaxDynamicSharedMemorySize, SMEM64);
    cudaFuncSetAttribute(gemm_sm64,  cudaFuncAttributeMaxDynamicSharedMemorySize, SMEMS64);
    cudaFuncSetAttribute(s0_all,     cudaFuncAttributeMaxDynamicSharedMemorySize, SMEM_S0);

    prep_all<<<6272, 256>>>(state, layer, oper);
    s0_all<<<64, 256, SMEM_S0>>>(state, layer, oper, envA);

    bf16* envc = envA;
    bf16* envn = envB;

    for (int q = 1; q <= 6; q++) {
        const bf16* Sq  = S  + (size_t)q * 65536;
        const bf16* Uq  = U  + (size_t)q * 65536;
        const bf16* Udq = Ud + (size_t)q * 65536;
        const bf16* Oq  = O  + (size_t)q * 4096;

        // G1: T1 = env x S      M=65536 N=1024 K=64  (single-stage K-resident)
        {
            Scat rs = {{64, 16, 4, 16}, {64, 4096, 65536, 4194304}};
            Scat cs = {{64, 16, 1, 1}, {1, 262144, 0, 0}};
            gemm_big64<<<dim3(65536 / 128, 1024 / 128), 256, SMEMB64>>>(
                envc, Sq, TA, 65536, 1024, ESZ, 524288, TSZ, rs, cs);
        }
        // G2: T2 = T1 x Ud      M=262144 N=256 K=256  (R10 engine)
        {
            Scat rs = {{64, 64, 16, 4}, {16, 1024, 65536, 16777216}};
            Scat cs = {{16, 16, 1, 1}, {1, 1048576, 0, 0}};
            gemm_big<<<dim3(262144 / 128, 256 / 128), 256, SMEM128>>>(
                TA, Udq, TB, 262144, 256, 256, TSZ, 524288, TSZ, rs, cs);
        }
        // G3: T3 = T2 x O       M=1048576 N=64 K=64  (single-stage K-resident)
        {
            Scat rs = {{16, 64, 64, 16}, {4, 64, 4096, 4194304}};
            Scat cs = {{4, 16, 1, 1}, {1, 262144, 0, 0}};
            gemm_sm64<<<dim3(1048576 / 64, 1), 256, SMEMS64>>>(
                TB, Oq, TA, 1048576, TSZ, 32768, TSZ, rs, cs);
        }
        // G4: T4 = T3 x U       M=262144 N=256 K=256  (R10 engine)
        {
            Scat rs = {{4, 16, 64, 64}, {16, 64, 1024, 1048576}};
            Scat cs = {{16, 16, 1, 1}, {1, 65536, 0, 0}};
            gemm_big<<<dim3(262144 / 128, 256 / 128), 256, SMEM128>>>(
                TA, Uq, TB, 262144, 256, 256, TSZ, 524288, TSZ, rs, cs);
        }
        // G5: env' = T4 x S     M=65536 N=64 K=1024   (3-stage pipeline)
        {
            Scat rs = {{16, 4, 16, 64}, {64, 1024, 4096, 65536}};
            Scat cs = {{64, 1, 1, 1}, {1, 0, 0, 0}};
            gemm_sm<<<dim3(65536 / 64, 1), 256, SMEM64>>>(
                TB, Sq, envn, 65536, 64, 1024, TSZ, 524288, ESZ, rs, cs);
        }

        bf16* t = envc; envc = envn; envn = t;
    }

    // Site 7 boundary
    const float* st7 = state + 7 * 65536;
    const float* ly7 = layer + 7 * 65536;
    const float* op7 = oper  + 7 * 4096;
    s7_x1<<<64, 256>>>(st7, ly7, X1);
    s7_x2<<<256, 256>>>(X1, op7, X2);
    s7_x3<<<4096, 256>>>(X2, ly7, X3);
    s7_dot<<<256, 256>>>(X3, st7, envc, partial);
    s7_reduce<<<1, 256>>>(partial, out);
}

// round 13
// speedup vs baseline: 1.1051x; 1.0253x over previous
#include <cuda_runtime.h>
#include <cuda_bf16.h>
#include <cstdint>

using bf16 = __nv_bfloat16;

#define NQ 8
#define TSZ 67108864UL   // elements per T plane
#define ESZ 4194304UL    // elements per env plane

// Static device scratch. hi plane [0,P), lo plane [P,2P).
__device__ bf16 g_TA[2 * TSZ];
__device__ bf16 g_TB[2 * TSZ];
__device__ bf16 g_envA[2 * ESZ];
__device__ bf16 g_envB[2 * ESZ];
__device__ bf16 g_S[2 * 524288];   // state split  (native layout)
__device__ bf16 g_U[2 * 524288];   // layer split  (native layout)
__device__ bf16 g_Ud[2 * 524288];  // permuted U-dagger split
__device__ bf16 g_O[2 * 32768];    // operator split (native layout)

struct Scat { int radix[4]; int stride[4]; };

__device__ __forceinline__ int scat_off(int idx, const Scat s) {
    int off = 0;
#pragma unroll
    for (int d = 0; d < 4; d++) {
        off += (idx % s.radix[d]) * s.stride[d];
        idx /= s.radix[d];
    }
    return off;
}

// ---------------------------------------------------------------------------
// PTX helpers
// ---------------------------------------------------------------------------
__device__ __forceinline__ uint32_t s2u(const void* p) {
    return (uint32_t)__cvta_generic_to_shared(p);
}
__device__ __forceinline__ void cpa16(uint32_t saddr, const void* g) {
    asm volatile("cp.async.cg.shared.global [%0], [%1], 16;\n" :: "r"(saddr), "l"(g));
}
#define CP_COMMIT() asm volatile("cp.async.commit_group;\n")
#define CP_WAIT1()  asm volatile("cp.async.wait_group 1;\n")
#define CP_WAIT0()  asm volatile("cp.async.wait_group 0;\n")

__device__ __forceinline__ void ldsm4t(uint32_t* r, uint32_t addr) {
    asm volatile("ldmatrix.sync.aligned.m8n8.x4.trans.shared.b16 {%0,%1,%2,%3}, [%4];"
                 : "=r"(r[0]), "=r"(r[1]), "=r"(r[2]), "=r"(r[3]) : "r"(addr));
}
__device__ __forceinline__ void mma16816(float* d, const uint32_t* a, const uint32_t* b) {
    asm volatile(
        "mma.sync.aligned.m16n8k16.row.col.f32.bf16.bf16.f32 "
        "{%0,%1,%2,%3},{%4,%5,%6,%7},{%8,%9},{%0,%1,%2,%3};"
        : "+f"(d[0]), "+f"(d[1]), "+f"(d[2]), "+f"(d[3])
        : "r"(a[0]), "r"(a[1]), "r"(a[2]), "r"(a[3]), "r"(b[0]), "r"(b[1]));
}

__device__ __forceinline__ void store_pair(bf16* C, size_t Cplane, size_t off,
                                           float v0, float v1) {
    __nv_bfloat162 ph, pl;
    ph.x = __float2bfloat16(v0);
    ph.y = __float2bfloat16(v1);
    pl.x = __float2bfloat16(v0 - __bfloat162float(ph.x));
    pl.y = __float2bfloat16(v1 - __bfloat162float(ph.y));
    *(__nv_bfloat162*)(C + off) = ph;
    *(__nv_bfloat162*)(C + Cplane + off) = pl;
}

// ---------------------------------------------------------------------------
// gemm_big: BM=128, BN=128, 2 CTAs/SM, 3-stage (R10 engine). Used: G2, G4.
// ---------------------------------------------------------------------------
__global__ void __launch_bounds__(256, 2) gemm_big(
    const bf16* __restrict__ A, const bf16* __restrict__ B,
    bf16* __restrict__ C, int M, int N, int K,
    size_t Aplane, size_t Bplane, size_t Cplane, Scat rs, Scat cs)
{
    constexpr int BM = 128, BN = 128, BK = 32;
    constexpr int APITCH = BM + 8;
    constexpr int BPITCH = BN + 8;
    constexpr int AS_PLANE = BK * APITCH;
    constexpr int BS_PLANE = BK * BPITCH;
    constexpr int STAGE = 2 * AS_PLANE + 2 * BS_PLANE;
    constexpr int NSTG = 3;
    constexpr int NT = BN / 16;   // 8
    constexpr int MT = 2;

    extern __shared__ bf16 sm[];

    const int tid  = threadIdx.x;
    const int lane = tid & 31;
    const int warp = tid >> 5;
    const int wm = (warp & 3) * 32;
    const int wn = (warp >> 2) * (BN / 2);
    const int m0 = blockIdx.x * BM;
    const int n0 = blockIdx.y * BN;

    float acc[MT][NT][4];
#pragma unroll
    for (int mt = 0; mt < MT; mt++)
#pragma unroll
        for (int nt = 0; nt < NT; nt++)
#pragma unroll
            for (int i = 0; i < 4; i++) acc[mt][nt][i] = 0.f;

    const int lk   = tid >> 3;
    const int mseg = (tid & 7) * 16;

    auto load_stage = [&](int s, int k0) {
        bf16* base = sm + s * STAGE;
        const bf16* Ag = A + (size_t)(k0 + lk) * (size_t)M + (size_t)(m0 + mseg);
        uint32_t da = s2u(base + lk * APITCH + mseg);
        cpa16(da,      Ag);
        cpa16(da + 16, Ag + 8);
        uint32_t dal = s2u(base + AS_PLANE + lk * APITCH + mseg);
        cpa16(dal,      Ag + Aplane);
        cpa16(dal + 16, Ag + Aplane + 8);
        bf16* bb = base + 2 * AS_PLANE;
        const bf16* Bg = B + (size_t)(k0 + lk) * (size_t)N + (size_t)(n0 + mseg);
        uint32_t db = s2u(bb + lk * BPITCH + mseg);
        cpa16(db,      Bg);
        cpa16(db + 16, Bg + 8);
        uint32_t dbl = s2u(bb + BS_PLANE + lk * BPITCH + mseg);
        cpa16(dbl,      Bg + Bplane);
        cpa16(dbl + 16, Bg + Bplane + 8);
    };

    const int nchunks = K / BK;
    load_stage(0, 0);
    CP_COMMIT();
    if (nchunks > 1) load_stage(1, BK);
    CP_COMMIT();

    for (int c = 0; c < nchunks; c++) {
        CP_WAIT1();
        __syncthreads();

        if (c + 2 < nchunks) load_stage((c + 2) % NSTG, (c + 2) * BK);
        CP_COMMIT();

        const bf16* base = sm + (c % NSTG) * STAGE;
        const bf16* Ah = base;
        const bf16* Al = base + AS_PLANE;
        const bf16* Bh = base + 2 * AS_PLANE;
        const bf16* Bl = base + 2 * AS_PLANE + BS_PLANE;

#pragma unroll
        for (int kk = 0; kk < BK; kk += 16) {
            uint32_t a[MT][4];
            uint32_t bh[NT / 2][4], bl[NT / 2][4];
            const int akr = kk + (lane & 7) + ((lane >> 4) & 1) * 8;
            const int amc = wm + ((lane >> 3) & 1) * 8;
            const int bkr = kk + (lane & 7) + ((lane >> 3) & 1) * 8;
            const int bnc = wn + ((lane >> 4) & 1) * 8;
#pragma unroll
            for (int mt = 0; mt < MT; mt++)
                ldsm4t(a[mt], s2u(Ah + akr * APITCH + amc + mt * 16));
#pragma unroll
            for (int np = 0; np < NT / 2; np++) {
                ldsm4t(bh[np], s2u(Bh + bkr * BPITCH + bnc + np * 16));
                ldsm4t(bl[np], s2u(Bl + bkr * BPITCH + bnc + np * 16));
            }
#pragma unroll
            for (int mt = 0; mt < MT; mt++)
#pragma unroll
                for (int nt = 0; nt < NT; nt++)
                    mma16816(acc[mt][nt], a[mt], &bh[nt >> 1][(nt & 1) * 2]);
#pragma unroll
            for (int mt = 0; mt < MT; mt++)
#pragma unroll
                for (int nt = 0; nt < NT; nt++)
                    mma16816(acc[mt][nt], a[mt], &bl[nt >> 1][(nt & 1) * 2]);
#pragma unroll
            for (int mt = 0; mt < MT; mt++)
                ldsm4t(a[mt], s2u(Al + akr * APITCH + amc + mt * 16));
#pragma unroll
            for (int mt = 0; mt < MT; mt++)
#pragma unroll
                for (int nt = 0; nt < NT; nt++)
                    mma16816(acc[mt][nt], a[mt], &bh[nt >> 1][(nt & 1) * 2]);
        }
    }

    const int r  = lane >> 2;
    const int c2 = (lane & 3) * 2;
    int fo[MT][2], go[NT];
#pragma unroll
    for (int mt = 0; mt < MT; mt++) {
        fo[mt][0] = scat_off(m0 + wm + mt * 16 + r,     rs);
        fo[mt][1] = scat_off(m0 + wm + mt * 16 + r + 8, rs);
    }
#pragma unroll
    for (int nt = 0; nt < NT; nt++)
        go[nt] = scat_off(n0 + wn + nt * 8 + c2, cs);

#pragma unroll
    for (int mt = 0; mt < MT; mt++)
#pragma unroll
        for (int nt = 0; nt < NT; nt++)
#pragma unroll
            for (int h = 0; h < 2; h++)
                store_pair(C, Cplane, (size_t)(fo[mt][h] + go[nt]),
                           acc[mt][nt][h * 2], acc[mt][nt][h * 2 + 1]);
}

// ---------------------------------------------------------------------------
// gemm_big64: BM=128, BN=128, K=64 resident, single stage, 2 CTAs/SM. Used: G1.
// ---------------------------------------------------------------------------
__global__ void __launch_bounds__(256, 2) gemm_big64(
    const bf16* __restrict__ A, const bf16* __restrict__ B,
    bf16* __restrict__ C, int M, int N,
    size_t Aplane, size_t Bplane, size_t Cplane, Scat rs, Scat cs)
{
    constexpr int BM = 128, BN = 128, KK = 64;
    constexpr int APITCH = BM + 8;
    constexpr int BPITCH = BN + 8;
    constexpr int AS_PLANE = KK * APITCH;
    constexpr int BS_PLANE = KK * BPITCH;
    constexpr int NT = BN / 16;
    constexpr int MT = 2;

    extern __shared__ bf16 sm[];

    const int tid  = threadIdx.x;
    const int lane = tid & 31;
    const int warp = tid >> 5;
    const int wm = (warp & 3) * 32;
    const int wn = (warp >> 2) * (BN / 2);
    const int m0 = blockIdx.x * BM;
    const int n0 = blockIdx.y * BN;

    float acc[MT][NT][4];
#pragma unroll
    for (int mt = 0; mt < MT; mt++)
#pragma unroll
        for (int nt = 0; nt < NT; nt++)
#pragma unroll
            for (int i = 0; i < 4; i++) acc[mt][nt][i] = 0.f;

    bf16* Ah = sm;
    bf16* Al = sm + AS_PLANE;
    bf16* Bh = sm + 2 * AS_PLANE;
    bf16* Bl = sm + 2 * AS_PLANE + BS_PLANE;

    const int lk   = tid >> 3;
    const int mseg = (tid & 7) * 16;

#pragma unroll
    for (int h = 0; h < 2; h++) {
        int row = lk + 32 * h;
        const bf16* Ag = A + (size_t)row * (size_t)M + (size_t)(m0 + mseg);
        uint32_t da = s2u(Ah + row * APITCH + mseg);
        cpa16(da,      Ag);
        cpa16(da + 16, Ag + 8);
        uint32_t dal = s2u(Al + row * APITCH + mseg);
        cpa16(dal,      Ag + Aplane);
        cpa16(dal + 16, Ag + Aplane + 8);
        const bf16* Bg = B + (size_t)row * (size_t)N + (size_t)(n0 + mseg);
        uint32_t db = s2u(Bh + row * BPITCH + mseg);
        cpa16(db,      Bg);
        cpa16(db + 16, Bg + 8);
        uint32_t dbl = s2u(Bl + row * BPITCH + mseg);
        cpa16(dbl,      Bg + Bplane);
        cpa16(dbl + 16, Bg + Bplane + 8);
    }
    CP_COMMIT();
    CP_WAIT0();
    __syncthreads();

#pragma unroll
    for (int kk = 0; kk < KK; kk += 16) {
        uint32_t a[MT][4];
        uint32_t bh[NT / 2][4], bl[NT / 2][4];
        const int akr = kk + (lane & 7) + ((lane >> 4) & 1) * 8;
        const int amc = wm + ((lane >> 3) & 1) * 8;
        const int bkr = kk + (lane & 7) + ((lane >> 3) & 1) * 8;
        const int bnc = wn + ((lane >> 4) & 1) * 8;
#pragma unroll
        for (int mt = 0; mt < MT; mt++)
            ldsm4t(a[mt], s2u(Ah + akr * APITCH + amc + mt * 16));
#pragma unroll
        for (int np = 0; np < NT / 2; np++) {
            ldsm4t(bh[np], s2u(Bh + bkr * BPITCH + bnc + np * 16));
            ldsm4t(bl[np], s2u(Bl + bkr * BPITCH + bnc + np * 16));
        }
#pragma unroll
        for (int mt = 0; mt < MT; mt++)
#pragma unroll
            for (int nt = 0; nt < NT; nt++)
                mma16816(acc[mt][nt], a[mt], &bh[nt >> 1][(nt & 1) * 2]);
#pragma unroll
        for (int mt = 0; mt < MT; mt++)
#pragma unroll
            for (int nt = 0; nt < NT; nt++)
                mma16816(acc[mt][nt], a[mt], &bl[nt >> 1][(nt & 1) * 2]);
#pragma unroll
        for (int mt = 0; mt < MT; mt++)
            ldsm4t(a[mt], s2u(Al + akr * APITCH + amc + mt * 16));
#pragma unroll
        for (int mt = 0; mt < MT; mt++)
#pragma unroll
            for (int nt = 0; nt < NT; nt++)
                mma16816(acc[mt][nt], a[mt], &bh[nt >> 1][(nt & 1) * 2]);
    }

    const int r  = lane >> 2;
    const int c2 = (lane & 3) * 2;
    int fo[MT][2], go[NT];
#pragma unroll
    for (int mt = 0; mt < MT; mt++) {
        fo[mt][0] = scat_off(m0 + wm + mt * 16 + r,     rs);
        fo[mt][1] = scat_off(m0 + wm + mt * 16 + r + 8, rs);
    }
#pragma unroll
    for (int nt = 0; nt < NT; nt++)
        go[nt] = scat_off(n0 + wn + nt * 8 + c2, cs);

#pragma unroll
    for (int mt = 0; mt < MT; mt++)
#pragma unroll
        for (int nt = 0; nt < NT; nt++)
#pragma unroll
            for (int h = 0; h < 2; h++)
                store_pair(C, Cplane, (size_t)(fo[mt][h] + go[nt]),
                           acc[mt][nt][h * 2], acc[mt][nt][h * 2 + 1]);
}

// ---------------------------------------------------------------------------
// gemm_w64k: BM=128, BN=64, K=64 resident single stage, 3 CTAs/SM. Used: G3.
// Warp tile 32m x 32n (4m x 2n warps): 24 MMAs per 8 ldsm (3:1).
// ---------------------------------------------------------------------------
__global__ void __launch_bounds__(256, 3) gemm_w64k(
    const bf16* __restrict__ A, const bf16* __restrict__ B,
    bf16* __restrict__ C, int M,
    size_t Aplane, size_t Bplane, size_t Cplane, Scat rs, Scat cs)
{
    constexpr int BM = 128, KK = 64;
    constexpr int APITCH = BM + 8;      // 136
    constexpr int BPITCH = 64 + 8;      // 72
    constexpr int AS_PLANE = KK * APITCH;
    constexpr int BS_PLANE = KK * BPITCH;
    constexpr int NT = 4;
    constexpr int MT = 2;

    extern __shared__ bf16 sm[];

    const int tid  = threadIdx.x;
    const int lane = tid & 31;
    const int warp = tid >> 5;
    const int wm = (warp & 3) * 32;
    const int wn = (warp >> 2) * 32;
    const int m0 = blockIdx.x * BM;

    float acc[MT][NT][4];
#pragma unroll
    for (int mt = 0; mt < MT; mt++)
#pragma unroll
        for (int nt = 0; nt < NT; nt++)
#pragma unroll
            for (int i = 0; i < 4; i++) acc[mt][nt][i] = 0.f;

    bf16* Ah = sm;
    bf16* Al = sm + AS_PLANE;
    bf16* Bh = sm + 2 * AS_PLANE;
    bf16* Bl = sm + 2 * AS_PLANE + BS_PLANE;

    const int lk   = tid >> 3;        // 0..31
    const int mseg = (tid & 7) * 16;  // A: 16 elems (2x16B)
    const int bseg = (tid & 7) * 8;   // B: 8 elems (16B)

#pragma unroll
    for (int h = 0; h < 2; h++) {
        int row = lk + 32 * h;
        const bf16* Ag = A + (size_t)row * (size_t)M + (size_t)(m0 + mseg);
        uint32_t da = s2u(Ah + row * APITCH + mseg);
        cpa16(da,      Ag);
        cpa16(da + 16, Ag + 8);
        uint32_t dal = s2u(Al + row * APITCH + mseg);
        cpa16(dal,      Ag + Aplane);
        cpa16(dal + 16, Ag + Aplane + 8);
        const bf16* Bg = B + (size_t)row * 64 + bseg;
        cpa16(s2u(Bh + row * BPITCH + bseg), Bg);
        cpa16(s2u(Bl + row * BPITCH + bseg), Bg + Bplane);
    }
    CP_COMMIT();
    CP_WAIT0();
    __syncthreads();

#pragma unroll
    for (int kk = 0; kk < KK; kk += 16) {
        uint32_t a[MT][4];
        uint32_t bh[NT / 2][4], bl[NT / 2][4];
        const int akr = kk + (lane & 7) + ((lane >> 4) & 1) * 8;
        const int amc = wm + ((lane >> 3) & 1) * 8;
        const int bkr = kk + (lane & 7) + ((lane >> 3) & 1) * 8;
        const int bnc = wn + ((lane >> 4) & 1) * 8;
#pragma unroll
        for (int mt = 0; mt < MT; mt++)
            ldsm4t(a[mt], s2u(Ah + akr * APITCH + amc + mt * 16));
#pragma unroll
        for (int np = 0; np < NT / 2; np++) {
            ldsm4t(bh[np], s2u(Bh + bkr * BPITCH + bnc + np * 16));
            ldsm4t(bl[np], s2u(Bl + bkr * BPITCH + bnc + np * 16));
        }
#pragma unroll
        for (int mt = 0; mt < MT; mt++)
#pragma unroll
            for (int nt = 0; nt < NT; nt++)
                mma16816(acc[mt][nt], a[mt], &bh[nt >> 1][(nt & 1) * 2]);
#pragma unroll
        for (int mt = 0; mt < MT; mt++)
#pragma unroll
            for (int nt = 0; nt < NT; nt++)
                mma16816(acc[mt][nt], a[mt], &bl[nt >> 1][(nt & 1) * 2]);
#pragma unroll
        for (int mt = 0; mt < MT; mt++)
            ldsm4t(a[mt], s2u(Al + akr * APITCH + amc + mt * 16));
#pragma unroll
        for (int mt = 0; mt < MT; mt++)
#pragma unroll
            for (int nt = 0; nt < NT; nt++)
                mma16816(acc[mt][nt], a[mt], &bh[nt >> 1][(nt & 1) * 2]);
    }

    const int r  = lane >> 2;
    const int c2 = (lane & 3) * 2;
    int fo[MT][2], go[NT];
#pragma unroll
    for (int mt = 0; mt < MT; mt++) {
        fo[mt][0] = scat_off(m0 + wm + mt * 16 + r,     rs);
        fo[mt][1] = scat_off(m0 + wm + mt * 16 + r + 8, rs);
    }
#pragma unroll
    for (int nt = 0; nt < NT; nt++)
        go[nt] = scat_off(wn + nt * 8 + c2, cs);

#pragma unroll
    for (int mt = 0; mt < MT; mt++)
#pragma unroll
        for (int nt = 0; nt < NT; nt++)
#pragma unroll
            for (int h = 0; h < 2; h++)
                store_pair(C, Cplane, (size_t)(fo[mt][h] + go[nt]),
                           acc[mt][nt][h * 2], acc[mt][nt][h * 2 + 1]);
}

// ---------------------------------------------------------------------------
// gemm_wide64: BM=128, BN=64, 3-stage pipelined, 2 CTAs/SM. Used: G5 (K=1024).
// Warp tile 32m x 32n; 24 MMAs per 8 ldsm (3:1).
// ---------------------------------------------------------------------------
__global__ void __launch_bounds__(256, 2) gemm_wide64(
    const bf16* __restrict__ A, const bf16* __restrict__ B,
    bf16* __restrict__ C, int M, int K,
    size_t Aplane, size_t Bplane, size_t Cplane, Scat rs, Scat cs)
{
    constexpr int BM = 128, BK = 32;
    constexpr int APITCH = BM + 8;      // 136
    constexpr int BPITCH = 64 + 8;      // 72
    constexpr int AS_PLANE = BK * APITCH;
    constexpr int BS_PLANE = BK * BPITCH;
    constexpr int STAGE = 2 * AS_PLANE + 2 * BS_PLANE;
    constexpr int NSTG = 3;
    constexpr int NT = 4;
    constexpr int MT = 2;

    extern __shared__ bf16 sm[];

    const int tid  = threadIdx.x;
    const int lane = tid & 31;
    const int warp = tid >> 5;
    const int wm = (warp & 3) * 32;
    const int wn = (warp >> 2) * 32;
    const int m0 = blockIdx.x * BM;

    float acc[MT][NT][4];
#pragma unroll
    for (int mt = 0; mt < MT; mt++)
#pragma unroll
        for (int nt = 0; nt < NT; nt++)
#pragma unroll
            for (int i = 0; i < 4; i++) acc[mt][nt][i] = 0.f;

    const int lk   = tid >> 3;        // 0..31
    const int mseg = (tid & 7) * 16;
    const int bseg = (tid & 7) * 8;

    auto load_stage = [&](int s, int k0) {
        bf16* base = sm + s * STAGE;
        const bf16* Ag = A + (size_t)(k0 + lk) * (size_t)M + (size_t)(m0 + mseg);
        uint32_t da = s2u(base + lk * APITCH + mseg);
        cpa16(da,      Ag);
        cpa16(da + 16, Ag + 8);
        uint32_t dal = s2u(base + AS_PLANE + lk * APITCH + mseg);
        cpa16(dal,      Ag + Aplane);
        cpa16(dal + 16, Ag + Aplane + 8);
        bf16* bb = base + 2 * AS_PLANE;
        const bf16* Bg = B + (size_t)(k0 + lk) * 64 + bseg;
        cpa16(s2u(bb + lk * BPITCH + bseg), Bg);
        cpa16(s2u(bb + BS_PLANE + lk * BPITCH + bseg), Bg + Bplane);
    };

    const int nchunks = K / BK;
    load_stage(0, 0);
    CP_COMMIT();
    if (nchunks > 1) load_stage(1, BK);
    CP_COMMIT();

    for (int c = 0; c < nchunks; c++) {
        CP_WAIT1();
        __syncthreads();

        if (c + 2 < nchunks) load_stage((c + 2) % NSTG, (c + 2) * BK);
        CP_COMMIT();

        const bf16* base = sm + (c % NSTG) * STAGE;
        const bf16* Ah = base;
        const bf16* Al = base + AS_PLANE;
        const bf16* Bh = base + 2 * AS_PLANE;
        const bf16* Bl = base + 2 * AS_PLANE + BS_PLANE;

#pragma unroll
        for (int kk = 0; kk < BK; kk += 16) {
            uint32_t a[MT][4];
            uint32_t bh[NT / 2][4], bl[NT / 2][4];
            const int akr = kk + (lane & 7) + ((lane >> 4) & 1) * 8;
            const int amc = wm + ((lane >> 3) & 1) * 8;
            const int bkr = kk + (lane & 7) + ((lane >> 3) & 1) * 8;
            const int bnc = wn + ((lane >> 4) & 1) * 8;
#pragma unroll
            for (int mt = 0; mt < MT; mt++)
                ldsm4t(a[mt], s2u(Ah + akr * APITCH + amc + mt * 16));
#pragma unroll
            for (int np = 0; np < NT / 2; np++) {
                ldsm4t(bh[np], s2u(Bh + bkr * BPITCH + bnc + np * 16));
                ldsm4t(bl[np], s2u(Bl + bkr * BPITCH + bnc + np * 16));
            }
#pragma unroll
            for (int mt = 0; mt < MT; mt++)
#pragma unroll
                for (int nt = 0; nt < NT; nt++)
                    mma16816(acc[mt][nt], a[mt], &bh[nt >> 1][(nt & 1) * 2]);
#pragma unroll
            for (int mt = 0; mt < MT; mt++)
#pragma unroll
                for (int nt = 0; nt < NT; nt++)
                    mma16816(acc[mt][nt], a[mt], &bl[nt >> 1][(nt & 1) * 2]);
#pragma unroll
            for (int mt = 0; mt < MT; mt++)
                ldsm4t(a[mt], s2u(Al + akr * APITCH + amc + mt * 16));
#pragma unroll
            for (int mt = 0; mt < MT; mt++)
#pragma unroll
                for (int nt = 0; nt < NT; nt++)
                    mma16816(acc[mt][nt], a[mt], &bh[nt >> 1][(nt & 1) * 2]);
        }
    }

    const int r  = lane >> 2;
    const int c2 = (lane & 3) * 2;
    int fo[MT][2], go[NT];
#pragma unroll
    for (int mt = 0; mt < MT; mt++) {
        fo[mt][0] = scat_off(m0 + wm + mt * 16 + r,     rs);
        fo[mt][1] = scat_off(m0 + wm + mt * 16 + r + 8, rs);
    }
#pragma unroll
    for (int nt = 0; nt < NT; nt++)
        go[nt] = scat_off(wn + nt * 8 + c2, cs);

#pragma unroll
    for (int mt = 0; mt < MT; mt++)
#pragma unroll
        for (int nt = 0; nt < NT; nt++)
#pragma unroll
            for (int h = 0; h < 2; h++)
                store_pair(C, Cplane, (size_t)(fo[mt][h] + go[nt]),
                           acc[mt][nt][h * 2], acc[mt][nt][h * 2 + 1]);
}

// ---------------------------------------------------------------------------
// Fused prep kernel: split inputs into bf16 hi/lo pairs.
// ---------------------------------------------------------------------------
__device__ __forceinline__ void put_split_g(bf16* dst, size_t plane, size_t i, float x) {
    bf16 h = __float2bfloat16(x);
    dst[i] = h;
    dst[plane + i] = __float2bfloat16(x - __bfloat162float(h));
}

__global__ void prep_all(const float* __restrict__ state,
                         const float* __restrict__ layer,
                         const float* __restrict__ oper) {
    int idx = blockIdx.x * blockDim.x + threadIdx.x;   // 1,605,632 total
    if (idx < 524288) {
        put_split_g(g_S, 524288, idx, state[idx]);
    } else if (idx < 1048576) {
        int i = idx - 524288;
        put_split_g(g_U, 524288, i, layer[i]);
    } else if (idx < 1081344) {
        int i = idx - 1048576;
        put_split_g(g_O, 32768, i, oper[i]);
    } else {
        int i = idx - 1081344;
        int Lb = i & 15; int t = i >> 4;
        int j  = t & 15;   t >>= 4;
        int ii = t & 15;   t >>= 4;
        int l  = t & 15;   t >>= 4;
        int q  = t;
        float x = layer[((((size_t)q * 16 + l) * 16 + j) * 16 + ii) * 16 + Lb];
        put_split_g(g_Ud, 524288, i, x);
    }
}

// ---------------------------------------------------------------------------
// Fused site-0 boundary (exact fp32)
// ---------------------------------------------------------------------------
__global__ void s0_all(const float* __restrict__ st, const float* __restrict__ ly,
                       const float* __restrict__ op, bf16* __restrict__ env) {
    extern __shared__ float sf[];
    float* sY  = sf;           // [k*1024 + M*64 + B]
    float* sC2 = sf + 16384;   // [L*64 + k*4 + O]
    float* sC1 = sf + 17408;   // [j*16 + L]
    const int t = threadIdx.x;
    const int A = blockIdx.x;

    {
        int j = t >> 4, L = t & 15;
        float s = 0.f;
        for (int i = 0; i < 16; i++)
            s += st[i * 64 + A] * ly[j * 256 + i * 16 + L];
        sC1[t] = s;
    }
    for (int e = t; e < 16384; e += 256) {
        int k = e >> 10, M = (e >> 6) & 15, B = e & 63;
        float s = 0.f;
        for (int sx = 0; sx < 16; sx++)
            s += ly[k * 256 + sx * 16 + M] * st[sx * 64 + B];
        sY[e] = s;
    }
    __syncthreads();
    for (int e = t; e < 1024; e += 256) {
        int L = e >> 6, k = (e >> 2) & 15, O = e & 3;
        float s = 0.f;
        for (int j = 0; j < 16; j++)
            s += sC1[j * 16 + L] * op[j * 64 + k * 4 + O];
        sC2[e] = s;
    }
    __syncthreads();
    for (int e = t; e < 65536; e += 256) {
        int B = e & 63, M = (e >> 6) & 15, O = (e >> 10) & 3, L = e >> 12;
        float v = 0.f;
#pragma unroll
        for (int k = 0; k < 16; k++)
            v += sC2[L * 64 + k * 4 + O] * sY[k * 1024 + M * 64 + B];
        size_t off = (size_t)A * 65536 + e;
        bf16 h = __float2bfloat16(v);
        env[off] = h;
        env[ESZ + off] = __float2bfloat16(v - __bfloat162float(h));
    }
}

// ---------------------------------------------------------------------------
// Site-7 boundary
// ---------------------------------------------------------------------------
__global__ void s7_x1(const float* __restrict__ st, const float* __restrict__ ly,
                      float* __restrict__ X1) {
    int idx = blockIdx.x * blockDim.x + threadIdx.x;
    if (idx >= 16384) return;
    int j = idx & 15, l = (idx >> 4) & 15, a = idx >> 8;
    float s = 0.f;
    for (int i = 0; i < 16; i++)
        s += st[a * 1024 + i * 64] * ly[l * 4096 + j * 256 + i * 16];
    X1[idx] = s;
}
__global__ void s7_x2(const float* __restrict__ X1, const float* __restrict__ op,
                      float* __restrict__ X2) {
    int idx = blockIdx.x * blockDim.x + threadIdx.x;
    if (idx >= 65536) return;
    int k = idx & 15, o = (idx >> 4) & 3, l = (idx >> 6) & 15, a = idx >> 10;
    float s = 0.f;
    for (int j = 0; j < 16; j++)
        s += X1[(a * 16 + l) * 16 + j] * op[o * 1024 + j * 64 + k * 4];
    X2[idx] = s;
}
__global__ void s7_x3(const float* __restrict__ X2, const float* __restrict__ ly,
                      float* __restrict__ X3) {
    int idx = blockIdx.x * blockDim.x + threadIdx.x;
    if (idx >= 1048576) return;
    int s5 = idx & 15, m = (idx >> 4) & 15, o = (idx >> 8) & 3,
        l = (idx >> 10) & 15, a = idx >> 14;
    float s = 0.f;
    for (int k = 0; k < 16; k++)
        s += X2[((a * 16 + l) * 4 + o) * 16 + k] * ly[m * 4096 + k * 256 + s5 * 16];
    X3[idx] = s;
}
__global__ void s7_dot(const float* __restrict__ X3, const float* __restrict__ st,
                       const bf16* __restrict__ env, float* __restrict__ partial) {
    __shared__ float red[256];
    int t = blockIdx.x * 256 + threadIdx.x;
    float x3[16];
#pragma unroll
    for (int s = 0; s < 16; s++) x3[s] = X3[t * 16 + s];
    size_t base = (size_t)t * 64;
    float acc = 0.f;
    for (int b = 0; b < 64; b++) {
        float w = 0.f;
#pragma unroll
        for (int s = 0; s < 16; s++) w += x3[s] * st[b * 1024 + s * 64];
        float e = __bfloat162float(env[base + b]) + __bfloat162float(env[ESZ + base + b]);
        acc += e * w;
    }
    red[threadIdx.x] = acc;
    __syncthreads();
    for (int step = 128; step > 0; step >>= 1) {
        if (threadIdx.x < step) red[threadIdx.x] += red[threadIdx.x + step];
        __syncthreads();
    }
    if (threadIdx.x == 0) partial[blockIdx.x] = red[0];
}
__global__ void s7_reduce(const float* __restrict__ partial, float* __restrict__ out) {
    __shared__ float red[256];
    red[threadIdx.x] = partial[threadIdx.x];
    __syncthreads();
    for (int step = 128; step > 0; step >>= 1) {
        if (threadIdx.x < step) red[threadIdx.x] += red[threadIdx.x + step];
        __syncthreads();
    }
    if (threadIdx.x == 0) out[0] = red[0];
}

// ---------------------------------------------------------------------------
extern "C" void kernel_launch(void* const* d_in, const int* in_sizes, int n_in,
                              void* d_out, int out_size) {
    const float* state = (const float*)d_in[0];  // [8, 64, 16, 64]
    const float* layer = (const float*)d_in[1];  // [1, 8, 16, 16, 16, 16]
    const float* oper  = (const float*)d_in[2];  // [8, 4, 16, 16, 4]
    float* out = (float*)d_out;

    bf16 *TA, *TB, *envA, *envB, *S, *U, *Ud, *O;
    cudaGetSymbolAddress((void**)&TA,   g_TA);
    cudaGetSymbolAddress((void**)&TB,   g_TB);
    cudaGetSymbolAddress((void**)&envA, g_envA);
    cudaGetSymbolAddress((void**)&envB, g_envB);
    cudaGetSymbolAddress((void**)&S,    g_S);
    cudaGetSymbolAddress((void**)&U,    g_U);
    cudaGetSymbolAddress((void**)&Ud,   g_Ud);
    cudaGetSymbolAddress((void**)&O,    g_O);

    // fp32 scratch carved from TB (used only after main loop frees it)
    float* fB = (float*)TB;
    float* X1 = fB, *X2 = fB + 32768, *X3 = fB + 131072;
    float* partial = fB + 1310720;

    constexpr int SMEM128  = 3 * (2 * (32 * 136) + 2 * (32 * 136)) * 2;  // 104448
    constexpr int SMEMB64  = (2 * (64 * 136) + 2 * (64 * 136)) * 2;      // 69632
    constexpr int SMEMW64K = (2 * (64 * 136) + 2 * (64 * 72)) * 2;       // 53248
    constexpr int SMEMWIDE = 3 * (2 * (32 * 136) + 2 * (32 * 72)) * 2;   // 79872
    constexpr int SMEM_S0  = 17664 * 4;                                  // 70656
    cudaFuncSetAttribute(gemm_big,    cudaFuncAttributeMaxDynamicSharedMemorySize, SMEM128);
    cudaFuncSetAttribute(gemm_big64,  cudaFuncAttributeMaxDynamicSharedMemorySize, SMEMB64);
    cudaFuncSetAttribute(gemm_w64k,   cudaFuncAttributeMaxDynamicSharedMemorySize, SMEMW64K);
    cudaFuncSetAttribute(gemm_wide64, cudaFuncAttributeMaxDynamicSharedMemorySize, SMEMWIDE);
    cudaFuncSetAttribute(s0_all,      cudaFuncAttributeMaxDynamicSharedMemorySize, SMEM_S0);

    prep_all<<<6272, 256>>>(state, layer, oper);
    s0_all<<<64, 256, SMEM_S0>>>(state, layer, oper, envA);

    bf16* envc = envA;
    bf16* envn = envB;

    for (int q = 1; q <= 6; q++) {
        const bf16* Sq  = S  + (size_t)q * 65536;
        const bf16* Uq  = U  + (size_t)q * 65536;
        const bf16* Udq = Ud + (size_t)q * 65536;
        const bf16* Oq  = O  + (size_t)q * 4096;

        // G1: T1 = env x S      M=65536 N=1024 K=64  (single-stage K-resident)
        {
            Scat rs = {{64, 16, 4, 16}, {64, 4096, 65536, 4194304}};
            Scat cs = {{64, 16, 1, 1}, {1, 262144, 0, 0}};
            gemm_big64<<<dim3(65536 / 128, 1024 / 128), 256, SMEMB64>>>(
                envc, Sq, TA, 65536, 1024, ESZ, 524288, TSZ, rs, cs);
        }
        // G2: T2 = T1 x Ud      M=262144 N=256 K=256  (R10 engine)
        {
            Scat rs = {{64, 64, 16, 4}, {16, 1024, 65536, 16777216}};
            Scat cs = {{16, 16, 1, 1}, {1, 1048576, 0, 0}};
            gemm_big<<<dim3(262144 / 128, 256 / 128), 256, SMEM128>>>(
                TA, Udq, TB, 262144, 256, 256, TSZ, 524288, TSZ, rs, cs);
        }
        // G3: T3 = T2 x O       M=1048576 N=64 K=64  (BM=128 single-stage)
        {
            Scat rs = {{16, 64, 64, 16}, {4, 64, 4096, 4194304}};
            Scat cs = {{4, 16, 1, 1}, {1, 262144, 0, 0}};
            gemm_w64k<<<dim3(1048576 / 128, 1), 256, SMEMW64K>>>(
                TB, Oq, TA, 1048576, TSZ, 32768, TSZ, rs, cs);
        }
        // G4: T4 = T3 x U       M=262144 N=256 K=256  (R10 engine)
        {
            Scat rs = {{4, 16, 64, 64}, {16, 64, 1024, 1048576}};
            Scat cs = {{16, 16, 1, 1}, {1, 65536, 0, 0}};
            gemm_big<<<dim3(262144 / 128, 256 / 128), 256, SMEM128>>>(
                TA, Uq, TB, 262144, 256, 256, TSZ, 524288, TSZ, rs, cs);
        }
        // G5: env' = T4 x S     M=65536 N=64 K=1024  (BM=128 3-stage)
        {
            Scat rs = {{16, 4, 16, 64}, {64, 1024, 4096, 65536}};
            Scat cs = {{64, 1, 1, 1}, {1, 0, 0, 0}};
            gemm_wide64<<<dim3(65536 / 128, 1), 256, SMEMWIDE>>>(
                TB, Sq, envn, 65536, 1024, TSZ, 524288, ESZ, rs, cs);
        }

        bf16* t = envc; envc = envn; envn = t;
    }

    // Site 7 boundary
    const float* st7 = state + 7 * 65536;
    const float* ly7 = layer + 7 * 65536;
    const float* op7 = oper  + 7 * 4096;
    s7_x1<<<64, 256>>>(st7, ly7, X1);
    s7_x2<<<256, 256>>>(X1, op7, X2);
    s7_x3<<<4096, 256>>>(X2, ly7, X3);
    s7_dot<<<256, 256>>>(X3, st7, envc, partial);
    s7_reduce<<<1, 256>>>(partial, out);
}

// round 14
// speedup vs baseline: 1.1060x; 1.0009x over previous
#include <cuda_runtime.h>
#include <cuda_bf16.h>
#include <cstdint>

using bf16 = __nv_bfloat16;

#define NQ 8
#define TSZ 67108864UL   // elements per T plane
#define ESZ 4194304UL    // elements per env plane

// Static device scratch. hi plane [0,P), lo plane [P,2P).
__device__ bf16 g_TA[2 * TSZ];
__device__ bf16 g_TB[2 * TSZ];
__device__ bf16 g_envA[2 * ESZ];
__device__ bf16 g_envB[2 * ESZ];
__device__ bf16 g_S[2 * 524288];   // state split  (native layout)
__device__ bf16 g_U[2 * 524288];   // layer split  (native layout)
__device__ bf16 g_Ud[2 * 524288];  // permuted U-dagger split
__device__ bf16 g_O[2 * 32768];    // operator split (native layout)

struct Scat { int radix[4]; int stride[4]; };

__device__ __forceinline__ int scat_off(int idx, const Scat s) {
    int off = 0;
#pragma unroll
    for (int d = 0; d < 4; d++) {
        off += (idx % s.radix[d]) * s.stride[d];
        idx /= s.radix[d];
    }
    return off;
}

// ---------------------------------------------------------------------------
// PTX helpers
// ---------------------------------------------------------------------------
__device__ __forceinline__ uint32_t s2u(const void* p) {
    return (uint32_t)__cvta_generic_to_shared(p);
}
__device__ __forceinline__ void cpa16(uint32_t saddr, const void* g) {
    asm volatile("cp.async.cg.shared.global [%0], [%1], 16;\n" :: "r"(saddr), "l"(g));
}
#define CP_COMMIT() asm volatile("cp.async.commit_group;\n")
#define CP_WAIT1()  asm volatile("cp.async.wait_group 1;\n")
#define CP_WAIT0()  asm volatile("cp.async.wait_group 0;\n")

__device__ __forceinline__ void ldsm4t(uint32_t* r, uint32_t addr) {
    asm volatile("ldmatrix.sync.aligned.m8n8.x4.trans.shared.b16 {%0,%1,%2,%3}, [%4];"
                 : "=r"(r[0]), "=r"(r[1]), "=r"(r[2]), "=r"(r[3]) : "r"(addr));
}
__device__ __forceinline__ void mma16816(float* d, const uint32_t* a, const uint32_t* b) {
    asm volatile(
        "mma.sync.aligned.m16n8k16.row.col.f32.bf16.bf16.f32 "
        "{%0,%1,%2,%3},{%4,%5,%6,%7},{%8,%9},{%0,%1,%2,%3};"
        : "+f"(d[0]), "+f"(d[1]), "+f"(d[2]), "+f"(d[3])
        : "r"(a[0]), "r"(a[1]), "r"(a[2]), "r"(a[3]), "r"(b[0]), "r"(b[1]));
}

__device__ __forceinline__ void store_pair(bf16* C, size_t Cplane, size_t off,
                                           float v0, float v1) {
    __nv_bfloat162 ph, pl;
    ph.x = __float2bfloat16(v0);
    ph.y = __float2bfloat16(v1);
    pl.x = __float2bfloat16(v0 - __bfloat162float(ph.x));
    pl.y = __float2bfloat16(v1 - __bfloat162float(ph.y));
    *(__nv_bfloat162*)(C + off) = ph;
    *(__nv_bfloat162*)(C + Cplane + off) = pl;
}

// ---------------------------------------------------------------------------
// gemm_big: BM=128, BN=128, 2 CTAs/SM, 3-stage. Used: G2, G4.
// Grid: (N/BN, M/BM) — N-blocks on the fast axis so CTAs sharing an A-tile
// are launch-adjacent and the A re-read hits L2.
// ---------------------------------------------------------------------------
__global__ void __launch_bounds__(256, 2) gemm_big(
    const bf16* __restrict__ A, const bf16* __restrict__ B,
    bf16* __restrict__ C, int M, int N, int K,
    size_t Aplane, size_t Bplane, size_t Cplane, Scat rs, Scat cs)
{
    constexpr int BM = 128, BN = 128, BK = 32;
    constexpr int APITCH = BM + 8;
    constexpr int BPITCH = BN + 8;
    constexpr int AS_PLANE = BK * APITCH;
    constexpr int BS_PLANE = BK * BPITCH;
    constexpr int STAGE = 2 * AS_PLANE + 2 * BS_PLANE;
    constexpr int NSTG = 3;
    constexpr int NT = BN / 16;   // 8
    constexpr int MT = 2;

    extern __shared__ bf16 sm[];

    const int tid  = threadIdx.x;
    const int lane = tid & 31;
    const int warp = tid >> 5;
    const int wm = (warp & 3) * 32;
    const int wn = (warp >> 2) * (BN / 2);
    const int m0 = blockIdx.y * BM;   // M on slow axis
    const int n0 = blockIdx.x * BN;   // N on fast axis (A-tile L2 reuse)

    float acc[MT][NT][4];
#pragma unroll
    for (int mt = 0; mt < MT; mt++)
#pragma unroll
        for (int nt = 0; nt < NT; nt++)
#pragma unroll
            for (int i = 0; i < 4; i++) acc[mt][nt][i] = 0.f;

    const int lk   = tid >> 3;
    const int mseg = (tid & 7) * 16;

    auto load_stage = [&](int s, int k0) {
        bf16* base = sm + s * STAGE;
        const bf16* Ag = A + (size_t)(k0 + lk) * (size_t)M + (size_t)(m0 + mseg);
        uint32_t da = s2u(base + lk * APITCH + mseg);
        cpa16(da,      Ag);
        cpa16(da + 16, Ag + 8);
        uint32_t dal = s2u(base + AS_PLANE + lk * APITCH + mseg);
        cpa16(dal,      Ag + Aplane);
        cpa16(dal + 16, Ag + Aplane + 8);
        bf16* bb = base + 2 * AS_PLANE;
        const bf16* Bg = B + (size_t)(k0 + lk) * (size_t)N + (size_t)(n0 + mseg);
        uint32_t db = s2u(bb + lk * BPITCH + mseg);
        cpa16(db,      Bg);
        cpa16(db + 16, Bg + 8);
        uint32_t dbl = s2u(bb + BS_PLANE + lk * BPITCH + mseg);
        cpa16(dbl,      Bg + Bplane);
        cpa16(dbl + 16, Bg + Bplane + 8);
    };

    const int nchunks = K / BK;
    load_stage(0, 0);
    CP_COMMIT();
    if (nchunks > 1) load_stage(1, BK);
    CP_COMMIT();

    for (int c = 0; c < nchunks; c++) {
        CP_WAIT1();
        __syncthreads();

        if (c + 2 < nchunks) load_stage((c + 2) % NSTG, (c + 2) * BK);
        CP_COMMIT();

        const bf16* base = sm + (c % NSTG) * STAGE;
        const bf16* Ah = base;
        const bf16* Al = base + AS_PLANE;
        const bf16* Bh = base + 2 * AS_PLANE;
        const bf16* Bl = base + 2 * AS_PLANE + BS_PLANE;

#pragma unroll
        for (int kk = 0; kk < BK; kk += 16) {
            uint32_t a[MT][4];
            uint32_t bh[NT / 2][4], bl[NT / 2][4];
            const int akr = kk + (lane & 7) + ((lane >> 4) & 1) * 8;
            const int amc = wm + ((lane >> 3) & 1) * 8;
            const int bkr = kk + (lane & 7) + ((lane >> 3) & 1) * 8;
            const int bnc = wn + ((lane >> 4) & 1) * 8;
#pragma unroll
            for (int mt = 0; mt < MT; mt++)
                ldsm4t(a[mt], s2u(Ah + akr * APITCH + amc + mt * 16));
#pragma unroll
            for (int np = 0; np < NT / 2; np++) {
                ldsm4t(bh[np], s2u(Bh + bkr * BPITCH + bnc + np * 16));
                ldsm4t(bl[np], s2u(Bl + bkr * BPITCH + bnc + np * 16));
            }
#pragma unroll
            for (int mt = 0; mt < MT; mt++)
#pragma unroll
                for (int nt = 0; nt < NT; nt++)
                    mma16816(acc[mt][nt], a[mt], &bh[nt >> 1][(nt & 1) * 2]);
#pragma unroll
            for (int mt = 0; mt < MT; mt++)
#pragma unroll
                for (int nt = 0; nt < NT; nt++)
                    mma16816(acc[mt][nt], a[mt], &bl[nt >> 1][(nt & 1) * 2]);
#pragma unroll
            for (int mt = 0; mt < MT; mt++)
                ldsm4t(a[mt], s2u(Al + akr * APITCH + amc + mt * 16));
#pragma unroll
            for (int mt = 0; mt < MT; mt++)
#pragma unroll
                for (int nt = 0; nt < NT; nt++)
                    mma16816(acc[mt][nt], a[mt], &bh[nt >> 1][(nt & 1) * 2]);
        }
    }

    const int r  = lane >> 2;
    const int c2 = (lane & 3) * 2;
    int fo[MT][2], go[NT];
#pragma unroll
    for (int mt = 0; mt < MT; mt++) {
        fo[mt][0] = scat_off(m0 + wm + mt * 16 + r,     rs);
        fo[mt][1] = scat_off(m0 + wm + mt * 16 + r + 8, rs);
    }
#pragma unroll
    for (int nt = 0; nt < NT; nt++)
        go[nt] = scat_off(n0 + wn + nt * 8 + c2, cs);

#pragma unroll
    for (int mt = 0; mt < MT; mt++)
#pragma unroll
        for (int nt = 0; nt < NT; nt++)
#pragma unroll
            for (int h = 0; h < 2; h++)
                store_pair(C, Cplane, (size_t)(fo[mt][h] + go[nt]),
                           acc[mt][nt][h * 2], acc[mt][nt][h * 2 + 1]);
}

// ---------------------------------------------------------------------------
// gemm_big64: BM=128, BN=128, K=64 resident, single stage, 2 CTAs/SM. Used: G1.
// Grid: (N/BN, M/BM) — same L2-reuse axis order.
// ---------------------------------------------------------------------------
__global__ void __launch_bounds__(256, 2) gemm_big64(
    const bf16* __restrict__ A, const bf16* __restrict__ B,
    bf16* __restrict__ C, int M, int N,
    size_t Aplane, size_t Bplane, size_t Cplane, Scat rs, Scat cs)
{
    constexpr int BM = 128, BN = 128, KK = 64;
    constexpr int APITCH = BM + 8;
    constexpr int BPITCH = BN + 8;
    constexpr int AS_PLANE = KK * APITCH;
    constexpr int BS_PLANE = KK * BPITCH;
    constexpr int NT = BN / 16;
    constexpr int MT = 2;

    extern __shared__ bf16 sm[];

    const int tid  = threadIdx.x;
    const int lane = tid & 31;
    const int warp = tid >> 5;
    const int wm = (warp & 3) * 32;
    const int wn = (warp >> 2) * (BN / 2);
    const int m0 = blockIdx.y * BM;
    const int n0 = blockIdx.x * BN;

    float acc[MT][NT][4];
#pragma unroll
    for (int mt = 0; mt < MT; mt++)
#pragma unroll
        for (int nt = 0; nt < NT; nt++)
#pragma unroll
            for (int i = 0; i < 4; i++) acc[mt][nt][i] = 0.f;

    bf16* Ah = sm;
    bf16* Al = sm + AS_PLANE;
    bf16* Bh = sm + 2 * AS_PLANE;
    bf16* Bl = sm + 2 * AS_PLANE + BS_PLANE;

    const int lk   = tid >> 3;
    const int mseg = (tid & 7) * 16;

#pragma unroll
    for (int h = 0; h < 2; h++) {
        int row = lk + 32 * h;
        const bf16* Ag = A + (size_t)row * (size_t)M + (size_t)(m0 + mseg);
        uint32_t da = s2u(Ah + row * APITCH + mseg);
        cpa16(da,      Ag);
        cpa16(da + 16, Ag + 8);
        uint32_t dal = s2u(Al + row * APITCH + mseg);
        cpa16(dal,      Ag + Aplane);
        cpa16(dal + 16, Ag + Aplane + 8);
        const bf16* Bg = B + (size_t)row * (size_t)N + (size_t)(n0 + mseg);
        uint32_t db = s2u(Bh + row * BPITCH + mseg);
        cpa16(db,      Bg);
        cpa16(db + 16, Bg + 8);
        uint32_t dbl = s2u(Bl + row * BPITCH + mseg);
        cpa16(dbl,      Bg + Bplane);
        cpa16(dbl + 16, Bg + Bplane + 8);
    }
    CP_COMMIT();
    CP_WAIT0();
    __syncthreads();

#pragma unroll
    for (int kk = 0; kk < KK; kk += 16) {
        uint32_t a[MT][4];
        uint32_t bh[NT / 2][4], bl[NT / 2][4];
        const int akr = kk + (lane & 7) + ((lane >> 4) & 1) * 8;
        const int amc = wm + ((lane >> 3) & 1) * 8;
        const int bkr = kk + (lane & 7) + ((lane >> 3) & 1) * 8;
        const int bnc = wn + ((lane >> 4) & 1) * 8;
#pragma unroll
        for (int mt = 0; mt < MT; mt++)
            ldsm4t(a[mt], s2u(Ah + akr * APITCH + amc + mt * 16));
#pragma unroll
        for (int np = 0; np < NT / 2; np++) {
            ldsm4t(bh[np], s2u(Bh + bkr * BPITCH + bnc + np * 16));
            ldsm4t(bl[np], s2u(Bl + bkr * BPITCH + bnc + np * 16));
        }
#pragma unroll
        for (int mt = 0; mt < MT; mt++)
#pragma unroll
            for (int nt = 0; nt < NT; nt++)
                mma16816(acc[mt][nt], a[mt], &bh[nt >> 1][(nt & 1) * 2]);
#pragma unroll
        for (int mt = 0; mt < MT; mt++)
#pragma unroll
            for (int nt = 0; nt < NT; nt++)
                mma16816(acc[mt][nt], a[mt], &bl[nt >> 1][(nt & 1) * 2]);
#pragma unroll
        for (int mt = 0; mt < MT; mt++)
            ldsm4t(a[mt], s2u(Al + akr * APITCH + amc + mt * 16));
#pragma unroll
        for (int mt = 0; mt < MT; mt++)
#pragma unroll
            for (int nt = 0; nt < NT; nt++)
                mma16816(acc[mt][nt], a[mt], &bh[nt >> 1][(nt & 1) * 2]);
    }

    const int r  = lane >> 2;
    const int c2 = (lane & 3) * 2;
    int fo[MT][2], go[NT];
#pragma unroll
    for (int mt = 0; mt < MT; mt++) {
        fo[mt][0] = scat_off(m0 + wm + mt * 16 + r,     rs);
        fo[mt][1] = scat_off(m0 + wm + mt * 16 + r + 8, rs);
    }
#pragma unroll
    for (int nt = 0; nt < NT; nt++)
        go[nt] = scat_off(n0 + wn + nt * 8 + c2, cs);

#pragma unroll
    for (int mt = 0; mt < MT; mt++)
#pragma unroll
        for (int nt = 0; nt < NT; nt++)
#pragma unroll
            for (int h = 0; h < 2; h++)
                store_pair(C, Cplane, (size_t)(fo[mt][h] + go[nt]),
                           acc[mt][nt][h * 2], acc[mt][nt][h * 2 + 1]);
}

// ---------------------------------------------------------------------------
// gemm_w64k: BM=128, BN=64, K=64 resident single stage, 3 CTAs/SM. Used: G3.
// ---------------------------------------------------------------------------
__global__ void __launch_bounds__(256, 3) gemm_w64k(
    const bf16* __restrict__ A, const bf16* __restrict__ B,
    bf16* __restrict__ C, int M,
    size_t Aplane, size_t Bplane, size_t Cplane, Scat rs, Scat cs)
{
    constexpr int BM = 128, KK = 64;
    constexpr int APITCH = BM + 8;      // 136
    constexpr int BPITCH = 64 + 8;      // 72
    constexpr int AS_PLANE = KK * APITCH;
    constexpr int BS_PLANE = KK * BPITCH;
    constexpr int NT = 4;
    constexpr int MT = 2;

    extern __shared__ bf16 sm[];

    const int tid  = threadIdx.x;
    const int lane = tid & 31;
    const int warp = tid >> 5;
    const int wm = (warp & 3) * 32;
    const int wn = (warp >> 2) * 32;
    const int m0 = blockIdx.x * BM;

    float acc[MT][NT][4];
#pragma unroll
    for (int mt = 0; mt < MT; mt++)
#pragma unroll
        for (int nt = 0; nt < NT; nt++)
#pragma unroll
            for (int i = 0; i < 4; i++) acc[mt][nt][i] = 0.f;

    bf16* Ah = sm;
    bf16* Al = sm + AS_PLANE;
    bf16* Bh = sm + 2 * AS_PLANE;
    bf16* Bl = sm + 2 * AS_PLANE + BS_PLANE;

    const int lk   = tid >> 3;        // 0..31
    const int mseg = (tid & 7) * 16;  // A: 16 elems (2x16B)
    const int bseg = (tid & 7) * 8;   // B: 8 elems (16B)

#pragma unroll
    for (int h = 0; h < 2; h++) {
        int row = lk + 32 * h;
        const bf16* Ag = A + (size_t)row * (size_t)M + (size_t)(m0 + mseg);
        uint32_t da = s2u(Ah + row * APITCH + mseg);
        cpa16(da,      Ag);
        cpa16(da + 16, Ag + 8);
        uint32_t dal = s2u(Al + row * APITCH + mseg);
        cpa16(dal,      Ag + Aplane);
        cpa16(dal + 16, Ag + Aplane + 8);
        const bf16* Bg = B + (size_t)row * 64 + bseg;
        cpa16(s2u(Bh + row * BPITCH + bseg), Bg);
        cpa16(s2u(Bl + row * BPITCH + bseg), Bg + Bplane);
    }
    CP_COMMIT();
    CP_WAIT0();
    __syncthreads();

#pragma unroll
    for (int kk = 0; kk < KK; kk += 16) {
        uint32_t a[MT][4];
        uint32_t bh[NT / 2][4], bl[NT / 2][4];
        const int akr = kk + (lane & 7) + ((lane >> 4) & 1) * 8;
        const int amc = wm + ((lane >> 3) & 1) * 8;
        const int bkr = kk + (lane & 7) + ((lane >> 3) & 1) * 8;
        const int bnc = wn + ((lane >> 4) & 1) * 8;
#pragma unroll
        for (int mt = 0; mt < MT; mt++)
            ldsm4t(a[mt], s2u(Ah + akr * APITCH + amc + mt * 16));
#pragma unroll
        for (int np = 0; np < NT / 2; np++) {
            ldsm4t(bh[np], s2u(Bh + bkr * BPITCH + bnc + np * 16));
            ldsm4t(bl[np], s2u(Bl + bkr * BPITCH + bnc + np * 16));
        }
#pragma unroll
        for (int mt = 0; mt < MT; mt++)
#pragma unroll
            for (int nt = 0; nt < NT; nt++)
                mma16816(acc[mt][nt], a[mt], &bh[nt >> 1][(nt & 1) * 2]);
#pragma unroll
        for (int mt = 0; mt < MT; mt++)
#pragma unroll
            for (int nt = 0; nt < NT; nt++)
                mma16816(acc[mt][nt], a[mt], &bl[nt >> 1][(nt & 1) * 2]);
#pragma unroll
        for (int mt = 0; mt < MT; mt++)
            ldsm4t(a[mt], s2u(Al + akr * APITCH + amc + mt * 16));
#pragma unroll
        for (int mt = 0; mt < MT; mt++)
#pragma unroll
            for (int nt = 0; nt < NT; nt++)
                mma16816(acc[mt][nt], a[mt], &bh[nt >> 1][(nt & 1) * 2]);
    }

    const int r  = lane >> 2;
    const int c2 = (lane & 3) * 2;
    int fo[MT][2], go[NT];
#pragma unroll
    for (int mt = 0; mt < MT; mt++) {
        fo[mt][0] = scat_off(m0 + wm + mt * 16 + r,     rs);
        fo[mt][1] = scat_off(m0 + wm + mt * 16 + r + 8, rs);
    }
#pragma unroll
    for (int nt = 0; nt < NT; nt++)
        go[nt] = scat_off(wn + nt * 8 + c2, cs);

#pragma unroll
    for (int mt = 0; mt < MT; mt++)
#pragma unroll
        for (int nt = 0; nt < NT; nt++)
#pragma unroll
            for (int h = 0; h < 2; h++)
                store_pair(C, Cplane, (size_t)(fo[mt][h] + go[nt]),
                           acc[mt][nt][h * 2], acc[mt][nt][h * 2 + 1]);
}

// ---------------------------------------------------------------------------
// gemm_wide64: BM=128, BN=64, 3-stage pipelined, 2 CTAs/SM. Used: G5 (K=1024).
// ---------------------------------------------------------------------------
__global__ void __launch_bounds__(256, 2) gemm_wide64(
    const bf16* __restrict__ A, const bf16* __restrict__ B,
    bf16* __restrict__ C, int M, int K,
    size_t Aplane, size_t Bplane, size_t Cplane, Scat rs, Scat cs)
{
    constexpr int BM = 128, BK = 32;
    constexpr int APITCH = BM + 8;      // 136
    constexpr int BPITCH = 64 + 8;      // 72
    constexpr int AS_PLANE = BK * APITCH;
    constexpr int BS_PLANE = BK * BPITCH;
    constexpr int STAGE = 2 * AS_PLANE + 2 * BS_PLANE;
    constexpr int NSTG = 3;
    constexpr int NT = 4;
    constexpr int MT = 2;

    extern __shared__ bf16 sm[];

    const int tid  = threadIdx.x;
    const int lane = tid & 31;
    const int warp = tid >> 5;
    const int wm = (warp & 3) * 32;
    const int wn = (warp >> 2) * 32;
    const int m0 = blockIdx.x * BM;

    float acc[MT][NT][4];
#pragma unroll
    for (int mt = 0; mt < MT; mt++)
#pragma unroll
        for (int nt = 0; nt < NT; nt++)
#pragma unroll
            for (int i = 0; i < 4; i++) acc[mt][nt][i] = 0.f;

    const int lk   = tid >> 3;        // 0..31
    const int mseg = (tid & 7) * 16;
    const int bseg = (tid & 7) * 8;

    auto load_stage = [&](int s, int k0) {
        bf16* base = sm + s * STAGE;
        const bf16* Ag = A + (size_t)(k0 + lk) * (size_t)M + (size_t)(m0 + mseg);
        uint32_t da = s2u(base + lk * APITCH + mseg);
        cpa16(da,      Ag);
        cpa16(da + 16, Ag + 8);
        uint32_t dal = s2u(base + AS_PLANE + lk * APITCH + mseg);
        cpa16(dal,      Ag + Aplane);
        cpa16(dal + 16, Ag + Aplane + 8);
        bf16* bb = base + 2 * AS_PLANE;
        const bf16* Bg = B + (size_t)(k0 + lk) * 64 + bseg;
        cpa16(s2u(bb + lk * BPITCH + bseg), Bg);
        cpa16(s2u(bb + BS_PLANE + lk * BPITCH + bseg), Bg + Bplane);
    };

    const int nchunks = K / BK;
    load_stage(0, 0);
    CP_COMMIT();
    if (nchunks > 1) load_stage(1, BK);
    CP_COMMIT();

    for (int c = 0; c < nchunks; c++) {
        CP_WAIT1();
        __syncthreads();

        if (c + 2 < nchunks) load_stage((c + 2) % NSTG, (c + 2) * BK);
        CP_COMMIT();

        const bf16* base = sm + (c % NSTG) * STAGE;
        const bf16* Ah = base;
        const bf16* Al = base + AS_PLANE;
        const bf16* Bh = base + 2 * AS_PLANE;
        const bf16* Bl = base + 2 * AS_PLANE + BS_PLANE;

#pragma unroll
        for (int kk = 0; kk < BK; kk += 16) {
            uint32_t a[MT][4];
            uint32_t bh[NT / 2][4], bl[NT / 2][4];
            const int akr = kk + (lane & 7) + ((lane >> 4) & 1) * 8;
            const int amc = wm + ((lane >> 3) & 1) * 8;
            const int bkr = kk + (lane & 7) + ((lane >> 3) & 1) * 8;
            const int bnc = wn + ((lane >> 4) & 1) * 8;
#pragma unroll
            for (int mt = 0; mt < MT; mt++)
                ldsm4t(a[mt], s2u(Ah + akr * APITCH + amc + mt * 16));
#pragma unroll
            for (int np = 0; np < NT / 2; np++) {
                ldsm4t(bh[np], s2u(Bh + bkr * BPITCH + bnc + np * 16));
                ldsm4t(bl[np], s2u(Bl + bkr * BPITCH + bnc + np * 16));
            }
#pragma unroll
            for (int mt = 0; mt < MT; mt++)
#pragma unroll
                for (int nt = 0; nt < NT; nt++)
                    mma16816(acc[mt][nt], a[mt], &bh[nt >> 1][(nt & 1) * 2]);
#pragma unroll
            for (int mt = 0; mt < MT; mt++)
#pragma unroll
                for (int nt = 0; nt < NT; nt++)
                    mma16816(acc[mt][nt], a[mt], &bl[nt >> 1][(nt & 1) * 2]);
#pragma unroll
            for (int mt = 0; mt < MT; mt++)
                ldsm4t(a[mt], s2u(Al + akr * APITCH + amc + mt * 16));
#pragma unroll
            for (int mt = 0; mt < MT; mt++)
#pragma unroll
                for (int nt = 0; nt < NT; nt++)
                    mma16816(acc[mt][nt], a[mt], &bh[nt >> 1][(nt & 1) * 2]);
        }
    }

    const int r  = lane >> 2;
    const int c2 = (lane & 3) * 2;
    int fo[MT][2], go[NT];
#pragma unroll
    for (int mt = 0; mt < MT; mt++) {
        fo[mt][0] = scat_off(m0 + wm + mt * 16 + r,     rs);
        fo[mt][1] = scat_off(m0 + wm + mt * 16 + r + 8, rs);
    }
#pragma unroll
    for (int nt = 0; nt < NT; nt++)
        go[nt] = scat_off(wn + nt * 8 + c2, cs);

#pragma unroll
    for (int mt = 0; mt < MT; mt++)
#pragma unroll
        for (int nt = 0; nt < NT; nt++)
#pragma unroll
            for (int h = 0; h < 2; h++)
                store_pair(C, Cplane, (size_t)(fo[mt][h] + go[nt]),
                           acc[mt][nt][h * 2], acc[mt][nt][h * 2 + 1]);
}

// ---------------------------------------------------------------------------
// Fused prep kernel: split inputs into bf16 hi/lo pairs.
// ---------------------------------------------------------------------------
__device__ __forceinline__ void put_split_g(bf16* dst, size_t plane, size_t i, float x) {
    bf16 h = __float2bfloat16(x);
    dst[i] = h;
    dst[plane + i] = __float2bfloat16(x - __bfloat162float(h));
}

__global__ void prep_all(const float* __restrict__ state,
                         const float* __restrict__ layer,
                         const float* __restrict__ oper) {
    int idx = blockIdx.x * blockDim.x + threadIdx.x;   // 1,605,632 total
    if (idx < 524288) {
        put_split_g(g_S, 524288, idx, state[idx]);
    } else if (idx < 1048576) {
        int i = idx - 524288;
        put_split_g(g_U, 524288, i, layer[i]);
    } else if (idx < 1081344) {
        int i = idx - 1048576;
        put_split_g(g_O, 32768, i, oper[i]);
    } else {
        int i = idx - 1081344;
        int Lb = i & 15; int t = i >> 4;
        int j  = t & 15;   t >>= 4;
        int ii = t & 15;   t >>= 4;
        int l  = t & 15;   t >>= 4;
        int q  = t;
        float x = layer[((((size_t)q * 16 + l) * 16 + j) * 16 + ii) * 16 + Lb];
        put_split_g(g_Ud, 524288, i, x);
    }
}

// ---------------------------------------------------------------------------
// Fused site-0 boundary (exact fp32)
// ---------------------------------------------------------------------------
__global__ void s0_all(const float* __restrict__ st, const float* __restrict__ ly,
                       const float* __restrict__ op, bf16* __restrict__ env) {
    extern __shared__ float sf[];
    float* sY  = sf;           // [k*1024 + M*64 + B]
    float* sC2 = sf + 16384;   // [L*64 + k*4 + O]
    float* sC1 = sf + 17408;   // [j*16 + L]
    const int t = threadIdx.x;
    const int A = blockIdx.x;

    {
        int j = t >> 4, L = t & 15;
        float s = 0.f;
        for (int i = 0; i < 16; i++)
            s += st[i * 64 + A] * ly[j * 256 + i * 16 + L];
        sC1[t] = s;
    }
    for (int e = t; e < 16384; e += 256) {
        int k = e >> 10, M = (e >> 6) & 15, B = e & 63;
        float s = 0.f;
        for (int sx = 0; sx < 16; sx++)
            s += ly[k * 256 + sx * 16 + M] * st[sx * 64 + B];
        sY[e] = s;
    }
    __syncthreads();
    for (int e = t; e < 1024; e += 256) {
        int L = e >> 6, k = (e >> 2) & 15, O = e & 3;
        float s = 0.f;
        for (int j = 0; j < 16; j++)
            s += sC1[j * 16 + L] * op[j * 64 + k * 4 + O];
        sC2[e] = s;
    }
    __syncthreads();
    for (int e = t; e < 65536; e += 256) {
        int B = e & 63, M = (e >> 6) & 15, O = (e >> 10) & 3, L = e >> 12;
        float v = 0.f;
#pragma unroll
        for (int k = 0; k < 16; k++)
            v += sC2[L * 64 + k * 4 + O] * sY[k * 1024 + M * 64 + B];
        size_t off = (size_t)A * 65536 + e;
        bf16 h = __float2bfloat16(v);
        env[off] = h;
        env[ESZ + off] = __float2bfloat16(v - __bfloat162float(h));
    }
}

// ---------------------------------------------------------------------------
// Site-7 boundary
// ---------------------------------------------------------------------------
__global__ void s7_x1(const float* __restrict__ st, const float* __restrict__ ly,
                      float* __restrict__ X1) {
    int idx = blockIdx.x * blockDim.x + threadIdx.x;
    if (idx >= 16384) return;
    int j = idx & 15, l = (idx >> 4) & 15, a = idx >> 8;
    float s = 0.f;
    for (int i = 0; i < 16; i++)
        s += st[a * 1024 + i * 64] * ly[l * 4096 + j * 256 + i * 16];
    X1[idx] = s;
}
__global__ void s7_x2(const float* __restrict__ X1, const float* __restrict__ op,
                      float* __restrict__ X2) {
    int idx = blockIdx.x * blockDim.x + threadIdx.x;
    if (idx >= 65536) return;
    int k = idx & 15, o = (idx >> 4) & 3, l = (idx >> 6) & 15, a = idx >> 10;
    float s = 0.f;
    for (int j = 0; j < 16; j++)
        s += X1[(a * 16 + l) * 16 + j] * op[o * 1024 + j * 64 + k * 4];
    X2[idx] = s;
}
__global__ void s7_x3(const float* __restrict__ X2, const float* __restrict__ ly,
                      float* __restrict__ X3) {
    int idx = blockIdx.x * blockDim.x + threadIdx.x;
    if (idx >= 1048576) return;
    int s5 = idx & 15, m = (idx >> 4) & 15, o = (idx >> 8) & 3,
        l = (idx >> 10) & 15, a = idx >> 14;
    float s = 0.f;
    for (int k = 0; k < 16; k++)
        s += X2[((a * 16 + l) * 4 + o) * 16 + k] * ly[m * 4096 + k * 256 + s5 * 16];
    X3[idx] = s;
}
__global__ void s7_dot(const float* __restrict__ X3, const float* __restrict__ st,
                       const bf16* __restrict__ env, float* __restrict__ partial) {
    __shared__ float red[256];
    int t = blockIdx.x * 256 + threadIdx.x;
    float x3[16];
#pragma unroll
    for (int s = 0; s < 16; s++) x3[s] = X3[t * 16 + s];
    size_t base = (size_t)t * 64;
    float acc = 0.f;
    for (int b = 0; b < 64; b++) {
        float w = 0.f;
#pragma unroll
        for (int s = 0; s < 16; s++) w += x3[s] * st[b * 1024 + s * 64];
        float e = __bfloat162float(env[base + b]) + __bfloat162float(env[ESZ + base + b]);
        acc += e * w;
    }
    red[threadIdx.x] = acc;
    __syncthreads();
    for (int step = 128; step > 0; step >>= 1) {
        if (threadIdx.x < step) red[threadIdx.x] += red[threadIdx.x + step];
        __syncthreads();
    }
    if (threadIdx.x == 0) partial[blockIdx.x] = red[0];
}
__global__ void s7_reduce(const float* __restrict__ partial, float* __restrict__ out) {
    __shared__ float red[256];
    red[threadIdx.x] = partial[threadIdx.x];
    __syncthreads();
    for (int step = 128; step > 0; step >>= 1) {
        if (threadIdx.x < step) red[threadIdx.x] += red[threadIdx.x + step];
        __syncthreads();
    }
    if (threadIdx.x == 0) out[0] = red[0];
}

// ---------------------------------------------------------------------------
extern "C" void kernel_launch(void* const* d_in, const int* in_sizes, int n_in,
                              void* d_out, int out_size) {
    const float* state = (const float*)d_in[0];  // [8, 64, 16, 64]
    const float* layer = (const float*)d_in[1];  // [1, 8, 16, 16, 16, 16]
    const float* oper  = (const float*)d_in[2];  // [8, 4, 16, 16, 4]
    float* out = (float*)d_out;

    bf16 *TA, *TB, *envA, *envB, *S, *U, *Ud, *O;
    cudaGetSymbolAddress((void**)&TA,   g_TA);
    cudaGetSymbolAddress((void**)&TB,   g_TB);
    cudaGetSymbolAddress((void**)&envA, g_envA);
    cudaGetSymbolAddress((void**)&envB, g_envB);
    cudaGetSymbolAddress((void**)&S,    g_S);
    cudaGetSymbolAddress((void**)&U,    g_U);
    cudaGetSymbolAddress((void**)&Ud,   g_Ud);
    cudaGetSymbolAddress((void**)&O,    g_O);

    // fp32 scratch carved from TB (used only after main loop frees it)
    float* fB = (float*)TB;
    float* X1 = fB, *X2 = fB + 32768, *X3 = fB + 131072;
    float* partial = fB + 1310720;

    constexpr int SMEM128  = 3 * (2 * (32 * 136) + 2 * (32 * 136)) * 2;  // 104448
    constexpr int SMEMB64  = (2 * (64 * 136) + 2 * (64 * 136)) * 2;      // 69632
    constexpr int SMEMW64K = (2 * (64 * 136) + 2 * (64 * 72)) * 2;       // 53248
    constexpr int SMEMWIDE = 3 * (2 * (32 * 136) + 2 * (32 * 72)) * 2;   // 79872
    constexpr int SMEM_S0  = 17664 * 4;                                  // 70656
    cudaFuncSetAttribute(gemm_big,    cudaFuncAttributeMaxDynamicSharedMemorySize, SMEM128);
    cudaFuncSetAttribute(gemm_big64,  cudaFuncAttributeMaxDynamicSharedMemorySize, SMEMB64);
    cudaFuncSetAttribute(gemm_w64k,   cudaFuncAttributeMaxDynamicSharedMemorySize, SMEMW64K);
    cudaFuncSetAttribute(gemm_wide64, cudaFuncAttributeMaxDynamicSharedMemorySize, SMEMWIDE);
    cudaFuncSetAttribute(s0_all,      cudaFuncAttributeMaxDynamicSharedMemorySize, SMEM_S0);

    prep_all<<<6272, 256>>>(state, layer, oper);
    s0_all<<<64, 256, SMEM_S0>>>(state, layer, oper, envA);

    bf16* envc = envA;
    bf16* envn = envB;

    for (int q = 1; q <= 6; q++) {
        const bf16* Sq  = S  + (size_t)q * 65536;
        const bf16* Uq  = U  + (size_t)q * 65536;
        const bf16* Udq = Ud + (size_t)q * 65536;
        const bf16* Oq  = O  + (size_t)q * 4096;

        // G1: T1 = env x S      M=65536 N=1024 K=64   grid=(N-blocks, M-blocks)
        {
            Scat rs = {{64, 16, 4, 16}, {64, 4096, 65536, 4194304}};
            Scat cs = {{64, 16, 1, 1}, {1, 262144, 0, 0}};
            gemm_big64<<<dim3(1024 / 128, 65536 / 128), 256, SMEMB64>>>(
                envc, Sq, TA, 65536, 1024, ESZ, 524288, TSZ, rs, cs);
        }
        // G2: T2 = T1 x Ud      M=262144 N=256 K=256   grid=(N-blocks, M-blocks)
        {
            Scat rs = {{64, 64, 16, 4}, {16, 1024, 65536, 16777216}};
            Scat cs = {{16, 16, 1, 1}, {1, 1048576, 0, 0}};
            gemm_big<<<dim3(256 / 128, 262144 / 128), 256, SMEM128>>>(
                TA, Udq, TB, 262144, 256, 256, TSZ, 524288, TSZ, rs, cs);
        }
        // G3: T3 = T2 x O       M=1048576 N=64 K=64  (BM=128 single-stage)
        {
            Scat rs = {{16, 64, 64, 16}, {4, 64, 4096, 4194304}};
            Scat cs = {{4, 16, 1, 1}, {1, 262144, 0, 0}};
            gemm_w64k<<<dim3(1048576 / 128, 1), 256, SMEMW64K>>>(
                TB, Oq, TA, 1048576, TSZ, 32768, TSZ, rs, cs);
        }
        // G4: T4 = T3 x U       M=262144 N=256 K=256   grid=(N-blocks, M-blocks)
        {
            Scat rs = {{4, 16, 64, 64}, {16, 64, 1024, 1048576}};
            Scat cs = {{16, 16, 1, 1}, {1, 65536, 0, 0}};
            gemm_big<<<dim3(256 / 128, 262144 / 128), 256, SMEM128>>>(
                TA, Uq, TB, 262144, 256, 256, TSZ, 524288, TSZ, rs, cs);
        }
        // G5: env' = T4 x S     M=65536 N=64 K=1024  (BM=128 3-stage)
        {
            Scat rs = {{16, 4, 16, 64}, {64, 1024, 4096, 65536}};
            Scat cs = {{64, 1, 1, 1}, {1, 0, 0, 0}};
            gemm_wide64<<<dim3(65536 / 128, 1), 256, SMEMWIDE>>>(
                TB, Sq, envn, 65536, 1024, TSZ, 524288, ESZ, rs, cs);
        }

        bf16* t = envc; envc = envn; envn = t;
    }

    // Site 7 boundary
    const float* st7 = state + 7 * 65536;
    const float* ly7 = layer + 7 * 65536;
    const float* op7 = oper  + 7 * 4096;
    s7_x1<<<64, 256>>>(st7, ly7, X1);
    s7_x2<<<256, 256>>>(X1, op7, X2);
    s7_x3<<<4096, 256>>>(X2, ly7, X3);
    s7_dot<<<256, 256>>>(X3, st7, envc, partial);
    s7_reduce<<<1, 256>>>(partial, out);
}

// round 15
// speedup vs baseline: 1.1461x; 1.0363x over previous
#include <cuda_runtime.h>
#include <cuda_bf16.h>
#include <cstdint>

using bf16 = __nv_bfloat16;

#define NQ 8
#define TSZ 67108864UL   // elements per T plane
#define ESZ 4194304UL    // elements per env plane

// Static device scratch. hi plane [0,P), lo plane [P,2P).
__device__ bf16 g_TA[2 * TSZ];
__device__ bf16 g_TB[2 * TSZ];
__device__ bf16 g_envA[2 * ESZ];
__device__ bf16 g_envB[2 * ESZ];
__device__ bf16 g_S[2 * 524288];   // state split  (native layout)
__device__ bf16 g_U[2 * 524288];   // layer split  (native layout)
__device__ bf16 g_Ud[2 * 524288];  // permuted U-dagger split
__device__ bf16 g_O[2 * 32768];    // operator split (native layout)

// Mixed-radix scatter, power-of-two radices -> mask/shift form (no divides).
struct Scat { int mask[4]; int shift[4]; int stride[4]; };

__device__ __forceinline__ int scat_off(int idx, const Scat s) {
    int off = 0;
#pragma unroll
    for (int d = 0; d < 4; d++) {
        off += (idx & s.mask[d]) * s.stride[d];
        idx >>= s.shift[d];
    }
    return off;
}

static Scat mk(int r0, int s0, int r1, int s1, int r2, int s2, int r3, int s3) {
    Scat s;
    int rr[4] = {r0, r1, r2, r3}, ss[4] = {s0, s1, s2, s3};
    for (int i = 0; i < 4; i++) {
        s.mask[i] = rr[i] - 1;
        int sh = 0; while ((1 << sh) < rr[i]) sh++;
        s.shift[i] = sh;
        s.stride[i] = ss[i];
    }
    return s;
}

// ---------------------------------------------------------------------------
// PTX helpers
// ---------------------------------------------------------------------------
__device__ __forceinline__ uint32_t s2u(const void* p) {
    return (uint32_t)__cvta_generic_to_shared(p);
}
__device__ __forceinline__ void cpa16(uint32_t saddr, const void* g) {
    asm volatile("cp.async.cg.shared.global [%0], [%1], 16;\n" :: "r"(saddr), "l"(g));
}
#define CP_COMMIT() asm volatile("cp.async.commit_group;\n")
#define CP_WAIT1()  asm volatile("cp.async.wait_group 1;\n")
#define CP_WAIT0()  asm volatile("cp.async.wait_group 0;\n")

__device__ __forceinline__ void ldsm4t(uint32_t* r, uint32_t addr) {
    asm volatile("ldmatrix.sync.aligned.m8n8.x4.trans.shared.b16 {%0,%1,%2,%3}, [%4];"
                 : "=r"(r[0]), "=r"(r[1]), "=r"(r[2]), "=r"(r[3]) : "r"(addr));
}
__device__ __forceinline__ void mma16816(float* d, const uint32_t* a, const uint32_t* b) {
    asm volatile(
        "mma.sync.aligned.m16n8k16.row.col.f32.bf16.bf16.f32 "
        "{%0,%1,%2,%3},{%4,%5,%6,%7},{%8,%9},{%0,%1,%2,%3};"
        : "+f"(d[0]), "+f"(d[1]), "+f"(d[2]), "+f"(d[3])
        : "r"(a[0]), "r"(a[1]), "r"(a[2]), "r"(a[3]), "r"(b[0]), "r"(b[1]));
}

__device__ __forceinline__ void store_pair(bf16* C, size_t Cplane, size_t off,
                                           float v0, float v1) {
    __nv_bfloat162 ph, pl;
    ph.x = __float2bfloat16(v0);
    ph.y = __float2bfloat16(v1);
    pl.x = __float2bfloat16(v0 - __bfloat162float(ph.x));
    pl.y = __float2bfloat16(v1 - __bfloat162float(ph.y));
    *(__nv_bfloat162*)(C + off) = ph;
    *(__nv_bfloat162*)(C + Cplane + off) = pl;
}

// ---------------------------------------------------------------------------
// gemm_big: BM=128, BN=128, 2 CTAs/SM, 3-stage. Used: G2, G4.
// Grid (N/BN, M/BM): N-fast for A-tile L2 reuse. Strength-reduced addressing.
// ---------------------------------------------------------------------------
__global__ void __launch_bounds__(256, 2) gemm_big(
    const bf16* __restrict__ A, const bf16* __restrict__ B,
    bf16* __restrict__ C, int M, int N, int K,
    size_t Aplane, size_t Bplane, size_t Cplane, Scat rs, Scat cs)
{
    constexpr int BM = 128, BN = 128, BK = 32;
    constexpr int APITCH = BM + 8;
    constexpr int BPITCH = BN + 8;
    constexpr int AS_PLANE = BK * APITCH;
    constexpr int BS_PLANE = BK * BPITCH;
    constexpr int STAGE = 2 * AS_PLANE + 2 * BS_PLANE;
    constexpr int NSTG = 3;
    constexpr int NT = BN / 16;   // 8
    constexpr int MT = 2;

    extern __shared__ bf16 sm[];

    const int tid  = threadIdx.x;
    const int lane = tid & 31;
    const int warp = tid >> 5;
    const int wm = (warp & 3) * 32;
    const int wn = (warp >> 2) * (BN / 2);
    const int m0 = blockIdx.y * BM;
    const int n0 = blockIdx.x * BN;

    float acc[MT][NT][4];
#pragma unroll
    for (int mt = 0; mt < MT; mt++)
#pragma unroll
        for (int nt = 0; nt < NT; nt++)
#pragma unroll
            for (int i = 0; i < 4; i++) acc[mt][nt][i] = 0.f;

    const int lk   = tid >> 3;
    const int mseg = (tid & 7) * 16;

    // lane-dependent ldsm element offsets (hoisted; bytes)
    const uint32_t aoffB =
        (uint32_t)((((lane & 7) + ((lane >> 4) & 1) * 8) * APITCH
                    + wm + ((lane >> 3) & 1) * 8) * 2);
    const uint32_t boffB =
        (uint32_t)((((lane & 7) + ((lane >> 3) & 1) * 8) * BPITCH
                    + wn + ((lane >> 4) & 1) * 8) * 2);
    const uint32_t smBase = s2u(sm);

    auto load_stage = [&](int s, int k0) {
        bf16* base = sm + s * STAGE;
        const bf16* Ag = A + (size_t)(k0 + lk) * (size_t)M + (size_t)(m0 + mseg);
        uint32_t da = s2u(base + lk * APITCH + mseg);
        cpa16(da,      Ag);
        cpa16(da + 16, Ag + 8);
        uint32_t dal = da + AS_PLANE * 2;
        cpa16(dal,      Ag + Aplane);
        cpa16(dal + 16, Ag + Aplane + 8);
        const bf16* Bg = B + (size_t)(k0 + lk) * (size_t)N + (size_t)(n0 + mseg);
        uint32_t db = s2u(base + 2 * AS_PLANE + lk * BPITCH + mseg);
        cpa16(db,      Bg);
        cpa16(db + 16, Bg + 8);
        uint32_t dbl = db + BS_PLANE * 2;
        cpa16(dbl,      Bg + Bplane);
        cpa16(dbl + 16, Bg + Bplane + 8);
    };

    const int nchunks = K / BK;
    load_stage(0, 0);
    CP_COMMIT();
    if (nchunks > 1) load_stage(1, BK);
    CP_COMMIT();

    for (int c = 0; c < nchunks; c++) {
        CP_WAIT1();
        __syncthreads();

        if (c + 2 < nchunks) load_stage((c + 2) % NSTG, (c + 2) * BK);
        CP_COMMIT();

        // per-chunk base addresses (bytes)
        const uint32_t stB = smBase + (uint32_t)((c % NSTG) * STAGE * 2);
        const uint32_t aH = stB + aoffB;
        const uint32_t aL = aH + (uint32_t)(AS_PLANE * 2);
        const uint32_t bH = stB + (uint32_t)(2 * AS_PLANE * 2) + boffB;
        const uint32_t bL = bH + (uint32_t)(BS_PLANE * 2);

#pragma unroll
        for (int kk = 0; kk < BK; kk += 16) {
            const uint32_t akk = (uint32_t)(kk * APITCH * 2);
            const uint32_t bkk = (uint32_t)(kk * BPITCH * 2);
            uint32_t a[MT][4];
            uint32_t bh[NT / 2][4], bl[NT / 2][4];
#pragma unroll
            for (int mt = 0; mt < MT; mt++)
                ldsm4t(a[mt], aH + akk + mt * 32);
#pragma unroll
            for (int np = 0; np < NT / 2; np++) {
                ldsm4t(bh[np], bH + bkk + np * 32);
                ldsm4t(bl[np], bL + bkk + np * 32);
            }
#pragma unroll
            for (int mt = 0; mt < MT; mt++)
#pragma unroll
                for (int nt = 0; nt < NT; nt++)
                    mma16816(acc[mt][nt], a[mt], &bh[nt >> 1][(nt & 1) * 2]);
#pragma unroll
            for (int mt = 0; mt < MT; mt++)
#pragma unroll
                for (int nt = 0; nt < NT; nt++)
                    mma16816(acc[mt][nt], a[mt], &bl[nt >> 1][(nt & 1) * 2]);
#pragma unroll
            for (int mt = 0; mt < MT; mt++)
                ldsm4t(a[mt], aL + akk + mt * 32);
#pragma unroll
            for (int mt = 0; mt < MT; mt++)
#pragma unroll
                for (int nt = 0; nt < NT; nt++)
                    mma16816(acc[mt][nt], a[mt], &bh[nt >> 1][(nt & 1) * 2]);
        }
    }

    const int r  = lane >> 2;
    const int c2 = (lane & 3) * 2;
    int fo[MT][2], go[NT];
#pragma unroll
    for (int mt = 0; mt < MT; mt++) {
        fo[mt][0] = scat_off(m0 + wm + mt * 16 + r,     rs);
        fo[mt][1] = scat_off(m0 + wm + mt * 16 + r + 8, rs);
    }
#pragma unroll
    for (int nt = 0; nt < NT; nt++)
        go[nt] = scat_off(n0 + wn + nt * 8 + c2, cs);

#pragma unroll
    for (int mt = 0; mt < MT; mt++)
#pragma unroll
        for (int nt = 0; nt < NT; nt++)
#pragma unroll
            for (int h = 0; h < 2; h++)
                store_pair(C, Cplane, (size_t)(fo[mt][h] + go[nt]),
                           acc[mt][nt][h * 2], acc[mt][nt][h * 2 + 1]);
}

// ---------------------------------------------------------------------------
// gemm_big64: BM=128, BN=128, K=64 resident, single stage, 2 CTAs/SM. Used: G1.
// ---------------------------------------------------------------------------
__global__ void __launch_bounds__(256, 2) gemm_big64(
    const bf16* __restrict__ A, const bf16* __restrict__ B,
    bf16* __restrict__ C, int M, int N,
    size_t Aplane, size_t Bplane, size_t Cplane, Scat rs, Scat cs)
{
    constexpr int BM = 128, BN = 128, KK = 64;
    constexpr int APITCH = BM + 8;
    constexpr int BPITCH = BN + 8;
    constexpr int AS_PLANE = KK * APITCH;
    constexpr int BS_PLANE = KK * BPITCH;
    constexpr int NT = BN / 16;
    constexpr int MT = 2;

    extern __shared__ bf16 sm[];

    const int tid  = threadIdx.x;
    const int lane = tid & 31;
    const int warp = tid >> 5;
    const int wm = (warp & 3) * 32;
    const int wn = (warp >> 2) * (BN / 2);
    const int m0 = blockIdx.y * BM;
    const int n0 = blockIdx.x * BN;

    float acc[MT][NT][4];
#pragma unroll
    for (int mt = 0; mt < MT; mt++)
#pragma unroll
        for (int nt = 0; nt < NT; nt++)
#pragma unroll
            for (int i = 0; i < 4; i++) acc[mt][nt][i] = 0.f;

    bf16* Ah = sm;
    bf16* Al = sm + AS_PLANE;
    bf16* Bh = sm + 2 * AS_PLANE;
    bf16* Bl = sm + 2 * AS_PLANE + BS_PLANE;

    const int lk   = tid >> 3;
    const int mseg = (tid & 7) * 16;

#pragma unroll
    for (int h = 0; h < 2; h++) {
        int row = lk + 32 * h;
        const bf16* Ag = A + (size_t)row * (size_t)M + (size_t)(m0 + mseg);
        uint32_t da = s2u(Ah + row * APITCH + mseg);
        cpa16(da,      Ag);
        cpa16(da + 16, Ag + 8);
        uint32_t dal = s2u(Al + row * APITCH + mseg);
        cpa16(dal,      Ag + Aplane);
        cpa16(dal + 16, Ag + Aplane + 8);
        const bf16* Bg = B + (size_t)row * (size_t)N + (size_t)(n0 + mseg);
        uint32_t db = s2u(Bh + row * BPITCH + mseg);
        cpa16(db,      Bg);
        cpa16(db + 16, Bg + 8);
        uint32_t dbl = s2u(Bl + row * BPITCH + mseg);
        cpa16(dbl,      Bg + Bplane);
        cpa16(dbl + 16, Bg + Bplane + 8);
    }
    CP_COMMIT();
    CP_WAIT0();
    __syncthreads();

#pragma unroll
    for (int kk = 0; kk < KK; kk += 16) {
        uint32_t a[MT][4];
        uint32_t bh[NT / 2][4], bl[NT / 2][4];
        const int akr = kk + (lane & 7) + ((lane >> 4) & 1) * 8;
        const int amc = wm + ((lane >> 3) & 1) * 8;
        const int bkr = kk + (lane & 7) + ((lane >> 3) & 1) * 8;
        const int bnc = wn + ((lane >> 4) & 1) * 8;
#pragma unroll
        for (int mt = 0; mt < MT; mt++)
            ldsm4t(a[mt], s2u(Ah + akr * APITCH + amc + mt * 16));
#pragma unroll
        for (int np = 0; np < NT / 2; np++) {
            ldsm4t(bh[np], s2u(Bh + bkr * BPITCH + bnc + np * 16));
            ldsm4t(bl[np], s2u(Bl + bkr * BPITCH + bnc + np * 16));
        }
#pragma unroll
        for (int mt = 0; mt < MT; mt++)
#pragma unroll
            for (int nt = 0; nt < NT; nt++)
                mma16816(acc[mt][nt], a[mt], &bh[nt >> 1][(nt & 1) * 2]);
#pragma unroll
        for (int mt = 0; mt < MT; mt++)
#pragma unroll
            for (int nt = 0; nt < NT; nt++)
                mma16816(acc[mt][nt], a[mt], &bl[nt >> 1][(nt & 1) * 2]);
#pragma unroll
        for (int mt = 0; mt < MT; mt++)
            ldsm4t(a[mt], s2u(Al + akr * APITCH + amc + mt * 16));
#pragma unroll
        for (int mt = 0; mt < MT; mt++)
#pragma unroll
            for (int nt = 0; nt < NT; nt++)
                mma16816(acc[mt][nt], a[mt], &bh[nt >> 1][(nt & 1) * 2]);
    }

    const int r  = lane >> 2;
    const int c2 = (lane & 3) * 2;
    int fo[MT][2], go[NT];
#pragma unroll
    for (int mt = 0; mt < MT; mt++) {
        fo[mt][0] = scat_off(m0 + wm + mt * 16 + r,     rs);
        fo[mt][1] = scat_off(m0 + wm + mt * 16 + r + 8, rs);
    }
#pragma unroll
    for (int nt = 0; nt < NT; nt++)
        go[nt] = scat_off(n0 + wn + nt * 8 + c2, cs);

#pragma unroll
    for (int mt = 0; mt < MT; mt++)
#pragma unroll
        for (int nt = 0; nt < NT; nt++)
#pragma unroll
            for (int h = 0; h < 2; h++)
                store_pair(C, Cplane, (size_t)(fo[mt][h] + go[nt]),
                           acc[mt][nt][h * 2], acc[mt][nt][h * 2 + 1]);
}

// ---------------------------------------------------------------------------
// gemm_w64k: BM=128, BN=64, K=64 resident single stage, 3 CTAs/SM. Used: G3.
// ---------------------------------------------------------------------------
__global__ void __launch_bounds__(256, 3) gemm_w64k(
    const bf16* __restrict__ A, const bf16* __restrict__ B,
    bf16* __restrict__ C, int M,
    size_t Aplane, size_t Bplane, size_t Cplane, Scat rs, Scat cs)
{
    constexpr int BM = 128, KK = 64;
    constexpr int APITCH = BM + 8;      // 136
    constexpr int BPITCH = 64 + 8;      // 72
    constexpr int AS_PLANE = KK * APITCH;
    constexpr int BS_PLANE = KK * BPITCH;
    constexpr int NT = 4;
    constexpr int MT = 2;

    extern __shared__ bf16 sm[];

    const int tid  = threadIdx.x;
    const int lane = tid & 31;
    const int warp = tid >> 5;
    const int wm = (warp & 3) * 32;
    const int wn = (warp >> 2) * 32;
    const int m0 = blockIdx.x * BM;

    float acc[MT][NT][4];
#pragma unroll
    for (int mt = 0; mt < MT; mt++)
#pragma unroll
        for (int nt = 0; nt < NT; nt++)
#pragma unroll
            for (int i = 0; i < 4; i++) acc[mt][nt][i] = 0.f;

    bf16* Ah = sm;
    bf16* Al = sm + AS_PLANE;
    bf16* Bh = sm + 2 * AS_PLANE;
    bf16* Bl = sm + 2 * AS_PLANE + BS_PLANE;

    const int lk   = tid >> 3;
    const int mseg = (tid & 7) * 16;
    const int bseg = (tid & 7) * 8;

#pragma unroll
    for (int h = 0; h < 2; h++) {
        int row = lk + 32 * h;
        const bf16* Ag = A + (size_t)row * (size_t)M + (size_t)(m0 + mseg);
        uint32_t da = s2u(Ah + row * APITCH + mseg);
        cpa16(da,      Ag);
        cpa16(da + 16, Ag + 8);
        uint32_t dal = s2u(Al + row * APITCH + mseg);
        cpa16(dal,      Ag + Aplane);
        cpa16(dal + 16, Ag + Aplane + 8);
        const bf16* Bg = B + (size_t)row * 64 + bseg;
        cpa16(s2u(Bh + row * BPITCH + bseg), Bg);
        cpa16(s2u(Bl + row * BPITCH + bseg), Bg + Bplane);
    }
    CP_COMMIT();
    CP_WAIT0();
    __syncthreads();

#pragma unroll
    for (int kk = 0; kk < KK; kk += 16) {
        uint32_t a[MT][4];
        uint32_t bh[NT / 2][4], bl[NT / 2][4];
        const int akr = kk + (lane & 7) + ((lane >> 4) & 1) * 8;
        const int amc = wm + ((lane >> 3) & 1) * 8;
        const int bkr = kk + (lane & 7) + ((lane >> 3) & 1) * 8;
        const int bnc = wn + ((lane >> 4) & 1) * 8;
#pragma unroll
        for (int mt = 0; mt < MT; mt++)
            ldsm4t(a[mt], s2u(Ah + akr * APITCH + amc + mt * 16));
#pragma unroll
        for (int np = 0; np < NT / 2; np++) {
            ldsm4t(bh[np], s2u(Bh + bkr * BPITCH + bnc + np * 16));
            ldsm4t(bl[np], s2u(Bl + bkr * BPITCH + bnc + np * 16));
        }
#pragma unroll
        for (int mt = 0; mt < MT; mt++)
#pragma unroll
            for (int nt = 0; nt < NT; nt++)
                mma16816(acc[mt][nt], a[mt], &bh[nt >> 1][(nt & 1) * 2]);
#pragma unroll
        for (int mt = 0; mt < MT; mt++)
#pragma unroll
            for (int nt = 0; nt < NT; nt++)
                mma16816(acc[mt][nt], a[mt], &bl[nt >> 1][(nt & 1) * 2]);
#pragma unroll
        for (int mt = 0; mt < MT; mt++)
            ldsm4t(a[mt], s2u(Al + akr * APITCH + amc + mt * 16));
#pragma unroll
        for (int mt = 0; mt < MT; mt++)
#pragma unroll
            for (int nt = 0; nt < NT; nt++)
                mma16816(acc[mt][nt], a[mt], &bh[nt >> 1][(nt & 1) * 2]);
    }

    const int r  = lane >> 2;
    const int c2 = (lane & 3) * 2;
    int fo[MT][2], go[NT];
#pragma unroll
    for (int mt = 0; mt < MT; mt++) {
        fo[mt][0] = scat_off(m0 + wm + mt * 16 + r,     rs);
        fo[mt][1] = scat_off(m0 + wm + mt * 16 + r + 8, rs);
    }
#pragma unroll
    for (int nt = 0; nt < NT; nt++)
        go[nt] = scat_off(wn + nt * 8 + c2, cs);

#pragma unroll
    for (int mt = 0; mt < MT; mt++)
#pragma unroll
        for (int nt = 0; nt < NT; nt++)
#pragma unroll
            for (int h = 0; h < 2; h++)
                store_pair(C, Cplane, (size_t)(fo[mt][h] + go[nt]),
                           acc[mt][nt][h * 2], acc[mt][nt][h * 2 + 1]);
}

// ---------------------------------------------------------------------------
// gemm_wide64: BM=128, BN=64, 3-stage pipelined, 2 CTAs/SM. Used: G5 (K=1024).
// ---------------------------------------------------------------------------
__global__ void __launch_bounds__(256, 2) gemm_wide64(
    const bf16* __restrict__ A, const bf16* __restrict__ B,
    bf16* __restrict__ C, int M, int K,
    size_t Aplane, size_t Bplane, size_t Cplane, Scat rs, Scat cs)
{
    constexpr int BM = 128, BK = 32;
    constexpr int APITCH = BM + 8;
    constexpr int BPITCH = 64 + 8;
    constexpr int AS_PLANE = BK * APITCH;
    constexpr int BS_PLANE = BK * BPITCH;
    constexpr int STAGE = 2 * AS_PLANE + 2 * BS_PLANE;
    constexpr int NSTG = 3;
    constexpr int NT = 4;
    constexpr int MT = 2;

    extern __shared__ bf16 sm[];

    const int tid  = threadIdx.x;
    const int lane = tid & 31;
    const int warp = tid >> 5;
    const int wm = (warp & 3) * 32;
    const int wn = (warp >> 2) * 32;
    const int m0 = blockIdx.x * BM;

    float acc[MT][NT][4];
#pragma unroll
    for (int mt = 0; mt < MT; mt++)
#pragma unroll
        for (int nt = 0; nt < NT; nt++)
#pragma unroll
            for (int i = 0; i < 4; i++) acc[mt][nt][i] = 0.f;

    const int lk   = tid >> 3;
    const int mseg = (tid & 7) * 16;
    const int bseg = (tid & 7) * 8;

    auto load_stage = [&](int s, int k0) {
        bf16* base = sm + s * STAGE;
        const bf16* Ag = A + (size_t)(k0 + lk) * (size_t)M + (size_t)(m0 + mseg);
        uint32_t da = s2u(base + lk * APITCH + mseg);
        cpa16(da,      Ag);
        cpa16(da + 16, Ag + 8);
        uint32_t dal = da + AS_PLANE * 2;
        cpa16(dal,      Ag + Aplane);
        cpa16(dal + 16, Ag + Aplane + 8);
        bf16* bb = base + 2 * AS_PLANE;
        const bf16* Bg = B + (size_t)(k0 + lk) * 64 + bseg;
        cpa16(s2u(bb + lk * BPITCH + bseg), Bg);
        cpa16(s2u(bb + BS_PLANE + lk * BPITCH + bseg), Bg + Bplane);
    };

    const int nchunks = K / BK;
    load_stage(0, 0);
    CP_COMMIT();
    if (nchunks > 1) load_stage(1, BK);
    CP_COMMIT();

    for (int c = 0; c < nchunks; c++) {
        CP_WAIT1();
        __syncthreads();

        if (c + 2 < nchunks) load_stage((c + 2) % NSTG, (c + 2) * BK);
        CP_COMMIT();

        const bf16* base = sm + (c % NSTG) * STAGE;
        const bf16* Ah = base;
        const bf16* Al = base + AS_PLANE;
        const bf16* Bh = base + 2 * AS_PLANE;
        const bf16* Bl = base + 2 * AS_PLANE + BS_PLANE;

#pragma unroll
        for (int kk = 0; kk < BK; kk += 16) {
            uint32_t a[MT][4];
            uint32_t bh[NT / 2][4], bl[NT / 2][4];
            const int akr = kk + (lane & 7) + ((lane >> 4) & 1) * 8;
            const int amc = wm + ((lane >> 3) & 1) * 8;
            const int bkr = kk + (lane & 7) + ((lane >> 3) & 1) * 8;
            const int bnc = wn + ((lane >> 4) & 1) * 8;
#pragma unroll
            for (int mt = 0; mt < MT; mt++)
                ldsm4t(a[mt], s2u(Ah + akr * APITCH + amc + mt * 16));
#pragma unroll
            for (int np = 0; np < NT / 2; np++) {
                ldsm4t(bh[np], s2u(Bh + bkr * BPITCH + bnc + np * 16));
                ldsm4t(bl[np], s2u(Bl + bkr * BPITCH + bnc + np * 16));
            }
#pragma unroll
            for (int mt = 0; mt < MT; mt++)
#pragma unroll
                for (int nt = 0; nt < NT; nt++)
                    mma16816(acc[mt][nt], a[mt], &bh[nt >> 1][(nt & 1) * 2]);
#pragma unroll
            for (int mt = 0; mt < MT; mt++)
#pragma unroll
                for (int nt = 0; nt < NT; nt++)
                    mma16816(acc[mt][nt], a[mt], &bl[nt >> 1][(nt & 1) * 2]);
#pragma unroll
            for (int mt = 0; mt < MT; mt++)
                ldsm4t(a[mt], s2u(Al + akr * APITCH + amc + mt * 16));
#pragma unroll
            for (int mt = 0; mt < MT; mt++)
#pragma unroll
                for (int nt = 0; nt < NT; nt++)
                    mma16816(acc[mt][nt], a[mt], &bh[nt >> 1][(nt & 1) * 2]);
        }
    }

    const int r  = lane >> 2;
    const int c2 = (lane & 3) * 2;
    int fo[MT][2], go[NT];
#pragma unroll
    for (int mt = 0; mt < MT; mt++) {
        fo[mt][0] = scat_off(m0 + wm + mt * 16 + r,     rs);
        fo[mt][1] = scat_off(m0 + wm + mt * 16 + r + 8, rs);
    }
#pragma unroll
    for (int nt = 0; nt < NT; nt++)
        go[nt] = scat_off(wn + nt * 8 + c2, cs);

#pragma unroll
    for (int mt = 0; mt < MT; mt++)
#pragma unroll
        for (int nt = 0; nt < NT; nt++)
#pragma unroll
            for (int h = 0; h < 2; h++)
                store_pair(C, Cplane, (size_t)(fo[mt][h] + go[nt]),
                           acc[mt][nt][h * 2], acc[mt][nt][h * 2 + 1]);
}

// ---------------------------------------------------------------------------
// Fused prep kernel: split inputs into bf16 hi/lo pairs.
// ---------------------------------------------------------------------------
__device__ __forceinline__ void put_split_g(bf16* dst, size_t plane, size_t i, float x) {
    bf16 h = __float2bfloat16(x);
    dst[i] = h;
    dst[plane + i] = __float2bfloat16(x - __bfloat162float(h));
}

__global__ void prep_all(const float* __restrict__ state,
                         const float* __restrict__ layer,
                         const float* __restrict__ oper) {
    int idx = blockIdx.x * blockDim.x + threadIdx.x;   // 1,605,632 total
    if (idx < 524288) {
        put_split_g(g_S, 524288, idx, state[idx]);
    } else if (idx < 1048576) {
        int i = idx - 524288;
        put_split_g(g_U, 524288, i, layer[i]);
    } else if (idx < 1081344) {
        int i = idx - 1048576;
        put_split_g(g_O, 32768, i, oper[i]);
    } else {
        int i = idx - 1081344;
        int Lb = i & 15; int t = i >> 4;
        int j  = t & 15;   t >>= 4;
        int ii = t & 15;   t >>= 4;
        int l  = t & 15;   t >>= 4;
        int q  = t;
        float x = layer[((((size_t)q * 16 + l) * 16 + j) * 16 + ii) * 16 + Lb];
        put_split_g(g_Ud, 524288, i, x);
    }
}

// ---------------------------------------------------------------------------
// Fused site-0 boundary (exact fp32)
// ---------------------------------------------------------------------------
__global__ void s0_all(const float* __restrict__ st, const float* __restrict__ ly,
                       const float* __restrict__ op, bf16* __restrict__ env) {
    extern __shared__ float sf[];
    float* sY  = sf;           // [k*1024 + M*64 + B]
    float* sC2 = sf + 16384;   // [L*64 + k*4 + O]
    float* sC1 = sf + 17408;   // [j*16 + L]
    const int t = threadIdx.x;
    const int A = blockIdx.x;

    {
        int j = t >> 4, L = t & 15;
        float s = 0.f;
        for (int i = 0; i < 16; i++)
            s += st[i * 64 + A] * ly[j * 256 + i * 16 + L];
        sC1[t] = s;
    }
    for (int e = t; e < 16384; e += 256) {
        int k = e >> 10, M = (e >> 6) & 15, B = e & 63;
        float s = 0.f;
        for (int sx = 0; sx < 16; sx++)
            s += ly[k * 256 + sx * 16 + M] * st[sx * 64 + B];
        sY[e] = s;
    }
    __syncthreads();
    for (int e = t; e < 1024; e += 256) {
        int L = e >> 6, k = (e >> 2) & 15, O = e & 3;
        float s = 0.f;
        for (int j = 0; j < 16; j++)
            s += sC1[j * 16 + L] * op[j * 64 + k * 4 + O];
        sC2[e] = s;
    }
    __syncthreads();
    for (int e = t; e < 65536; e += 256) {
        int B = e & 63, M = (e >> 6) & 15, O = (e >> 10) & 3, L = e >> 12;
        float v = 0.f;
#pragma unroll
        for (int k = 0; k < 16; k++)
            v += sC2[L * 64 + k * 4 + O] * sY[k * 1024 + M * 64 + B];
        size_t off = (size_t)A * 65536 + e;
        bf16 h = __float2bfloat16(v);
        env[off] = h;
        env[ESZ + off] = __float2bfloat16(v - __bfloat162float(h));
    }
}

// ---------------------------------------------------------------------------
// Site-7 boundary
// ---------------------------------------------------------------------------
__global__ void s7_x1(const float* __restrict__ st, const float* __restrict__ ly,
                      float* __restrict__ X1) {
    int idx = blockIdx.x * blockDim.x + threadIdx.x;
    if (idx >= 16384) return;
    int j = idx & 15, l = (idx >> 4) & 15, a = idx >> 8;
    float s = 0.f;
    for (int i = 0; i < 16; i++)
        s += st[a * 1024 + i * 64] * ly[l * 4096 + j * 256 + i * 16];
    X1[idx] = s;
}
__global__ void s7_x2(const float* __restrict__ X1, const float* __restrict__ op,
                      float* __restrict__ X2) {
    int idx = blockIdx.x * blockDim.x + threadIdx.x;
    if (idx >= 65536) return;
    int k = idx & 15, o = (idx >> 4) & 3, l = (idx >> 6) & 15, a = idx >> 10;
    float s = 0.f;
    for (int j = 0; j < 16; j++)
        s += X1[(a * 16 + l) * 16 + j] * op[o * 1024 + j * 64 + k * 4];
    X2[idx] = s;
}
__global__ void s7_x3(const float* __restrict__ X2, const float* __restrict__ ly,
                      float* __restrict__ X3) {
    int idx = blockIdx.x * blockDim.x + threadIdx.x;
    if (idx >= 1048576) return;
    int s5 = idx & 15, m = (idx >> 4) & 15, o = (idx >> 8) & 3,
        l = (idx >> 10) & 15, a = idx >> 14;
    float s = 0.f;
    for (int k = 0; k < 16; k++)
        s += X2[((a * 16 + l) * 4 + o) * 16 + k] * ly[m * 4096 + k * 256 + s5 * 16];
    X3[idx] = s;
}
__global__ void s7_dot(const float* __restrict__ X3, const float* __restrict__ st,
                       const bf16* __restrict__ env, float* __restrict__ partial) {
    __shared__ float red[256];
    int t = blockIdx.x * 256 + threadIdx.x;
    float x3[16];
#pragma unroll
    for (int s = 0; s < 16; s++) x3[s] = X3[t * 16 + s];
    size_t base = (size_t)t * 64;
    float acc = 0.f;
    for (int b = 0; b < 64; b++) {
        float w = 0.f;
#pragma unroll
        for (int s = 0; s < 16; s++) w += x3[s] * st[b * 1024 + s * 64];
        float e = __bfloat162float(env[base + b]) + __bfloat162float(env[ESZ + base + b]);
        acc += e * w;
    }
    red[threadIdx.x] = acc;
    __syncthreads();
    for (int step = 128; step > 0; step >>= 1) {
        if (threadIdx.x < step) red[threadIdx.x] += red[threadIdx.x + step];
        __syncthreads();
    }
    if (threadIdx.x == 0) partial[blockIdx.x] = red[0];
}
__global__ void s7_reduce(const float* __restrict__ partial, float* __restrict__ out) {
    __shared__ float red[256];
    red[threadIdx.x] = partial[threadIdx.x];
    __syncthreads();
    for (int step = 128; step > 0; step >>= 1) {
        if (threadIdx.x < step) red[threadIdx.x] += red[threadIdx.x + step];
        __syncthreads();
    }
    if (threadIdx.x == 0) out[0] = red[0];
}

// ---------------------------------------------------------------------------
extern "C" void kernel_launch(void* const* d_in, const int* in_sizes, int n_in,
                              void* d_out, int out_size) {
    const float* state = (const float*)d_in[0];  // [8, 64, 16, 64]
    const float* layer = (const float*)d_in[1];  // [1, 8, 16, 16, 16, 16]
    const float* oper  = (const float*)d_in[2];  // [8, 4, 16, 16, 4]
    float* out = (float*)d_out;

    bf16 *TA, *TB, *envA, *envB, *S, *U, *Ud, *O;
    cudaGetSymbolAddress((void**)&TA,   g_TA);
    cudaGetSymbolAddress((void**)&TB,   g_TB);
    cudaGetSymbolAddress((void**)&envA, g_envA);
    cudaGetSymbolAddress((void**)&envB, g_envB);
    cudaGetSymbolAddress((void**)&S,    g_S);
    cudaGetSymbolAddress((void**)&U,    g_U);
    cudaGetSymbolAddress((void**)&Ud,   g_Ud);
    cudaGetSymbolAddress((void**)&O,    g_O);

    // fp32 scratch carved from TB (used only after main loop frees it)
    float* fB = (float*)TB;
    float* X1 = fB, *X2 = fB + 32768, *X3 = fB + 131072;
    float* partial = fB + 1310720;

    constexpr int SMEM128  = 3 * (2 * (32 * 136) + 2 * (32 * 136)) * 2;  // 104448
    constexpr int SMEMB64  = (2 * (64 * 136) + 2 * (64 * 136)) * 2;      // 69632
    constexpr int SMEMW64K = (2 * (64 * 136) + 2 * (64 * 72)) * 2;       // 53248
    constexpr int SMEMWIDE = 3 * (2 * (32 * 136) + 2 * (32 * 72)) * 2;   // 79872
    constexpr int SMEM_S0  = 17664 * 4;                                  // 70656
    cudaFuncSetAttribute(gemm_big,    cudaFuncAttributeMaxDynamicSharedMemorySize, SMEM128);
    cudaFuncSetAttribute(gemm_big64,  cudaFuncAttributeMaxDynamicSharedMemorySize, SMEMB64);
    cudaFuncSetAttribute(gemm_w64k,   cudaFuncAttributeMaxDynamicSharedMemorySize, SMEMW64K);
    cudaFuncSetAttribute(gemm_wide64, cudaFuncAttributeMaxDynamicSharedMemorySize, SMEMWIDE);
    cudaFuncSetAttribute(s0_all,      cudaFuncAttributeMaxDynamicSharedMemorySize, SMEM_S0);

    prep_all<<<6272, 256>>>(state, layer, oper);
    s0_all<<<64, 256, SMEM_S0>>>(state, layer, oper, envA);

    bf16* envc = envA;
    bf16* envn = envB;

    for (int q = 1; q <= 6; q++) {
        const bf16* Sq  = S  + (size_t)q * 65536;
        const bf16* Uq  = U  + (size_t)q * 65536;
        const bf16* Udq = Ud + (size_t)q * 65536;
        const bf16* Oq  = O  + (size_t)q * 4096;

        // G1: T1 = env x S      M=65536 N=1024 K=64
        gemm_big64<<<dim3(1024 / 128, 65536 / 128), 256, SMEMB64>>>(
            envc, Sq, TA, 65536, 1024, ESZ, 524288, TSZ,
            mk(64, 64, 16, 4096, 4, 65536, 16, 4194304),
            mk(64, 1, 16, 262144, 1, 0, 1, 0));

        // G2: T2 = T1 x Ud      M=262144 N=256 K=256
        gemm_big<<<dim3(256 / 128, 262144 / 128), 256, SMEM128>>>(
            TA, Udq, TB, 262144, 256, 256, TSZ, 524288, TSZ,
            mk(64, 16, 64, 1024, 16, 65536, 4, 16777216),
            mk(16, 1, 16, 1048576, 1, 0, 1, 0));

        // G3: T3 = T2 x O       M=1048576 N=64 K=64
        gemm_w64k<<<dim3(1048576 / 128, 1), 256, SMEMW64K>>>(
            TB, Oq, TA, 1048576, TSZ, 32768, TSZ,
            mk(16, 4, 64, 64, 64, 4096, 16, 4194304),
            mk(4, 1, 16, 262144, 1, 0, 1, 0));

        // G4: T4 = T3 x U       M=262144 N=256 K=256
        gemm_big<<<dim3(256 / 128, 262144 / 128), 256, SMEM128>>>(
            TA, Uq, TB, 262144, 256, 256, TSZ, 524288, TSZ,
            mk(4, 16, 16, 64, 64, 1024, 64, 1048576),
            mk(16, 1, 16, 65536, 1, 0, 1, 0));

        // G5: env' = T4 x S     M=65536 N=64 K=1024
        gemm_wide64<<<dim3(65536 / 128, 1), 256, SMEMWIDE>>>(
            TB, Sq, envn, 65536, 1024, TSZ, 524288, ESZ,
            mk(16, 64, 4, 1024, 16, 4096, 64, 65536),
            mk(64, 1, 1, 0, 1, 0, 1, 0));

        bf16* t = envc; envc = envn; envn = t;
    }

    // Site 7 boundary
    const float* st7 = state + 7 * 65536;
    const float* ly7 = layer + 7 * 65536;
    const float* op7 = oper  + 7 * 4096;
    s7_x1<<<64, 256>>>(st7, ly7, X1);
    s7_x2<<<256, 256>>>(X1, op7, X2);
    s7_x3<<<4096, 256>>>(X2, ly7, X3);
    s7_dot<<<256, 256>>>(X3, st7, envc, partial);
    s7_reduce<<<1, 256>>>(partial, out);
}

// round 16
// speedup vs baseline: 1.1478x; 1.0014x over previous
#include <cuda_runtime.h>
#include <cuda_bf16.h>
#include <cstdint>

using bf16 = __nv_bfloat16;

#define NQ 8
#define TSZ 67108864UL   // elements per T plane
#define ESZ 4194304UL    // elements per env plane

// Static device scratch. hi plane [0,P), lo plane [P,2P).
__device__ bf16 g_TA[2 * TSZ];
__device__ bf16 g_TB[2 * TSZ];
__device__ bf16 g_envA[2 * ESZ];
__device__ bf16 g_envB[2 * ESZ];
__device__ bf16 g_S[2 * 524288];   // state split  (native layout)
__device__ bf16 g_U[2 * 524288];   // layer split  (native layout)
__device__ bf16 g_Ud[2 * 524288];  // permuted U-dagger split
__device__ bf16 g_O[2 * 32768];    // operator split (native layout)

// Mixed-radix scatter, power-of-two radices -> mask/shift form (no divides).
struct Scat { int mask[4]; int shift[4]; int stride[4]; };

__device__ __forceinline__ int scat_off(int idx, const Scat s) {
    int off = 0;
#pragma unroll
    for (int d = 0; d < 4; d++) {
        off += (idx & s.mask[d]) * s.stride[d];
        idx >>= s.shift[d];
    }
    return off;
}

static Scat mk(int r0, int s0, int r1, int s1, int r2, int s2, int r3, int s3) {
    Scat s;
    int rr[4] = {r0, r1, r2, r3}, ss[4] = {s0, s1, s2, s3};
    for (int i = 0; i < 4; i++) {
        s.mask[i] = rr[i] - 1;
        int sh = 0; while ((1 << sh) < rr[i]) sh++;
        s.shift[i] = sh;
        s.stride[i] = ss[i];
    }
    return s;
}

// ---------------------------------------------------------------------------
// PTX helpers
// ---------------------------------------------------------------------------
__device__ __forceinline__ uint32_t s2u(const void* p) {
    return (uint32_t)__cvta_generic_to_shared(p);
}
__device__ __forceinline__ void cpa16(uint32_t saddr, const void* g) {
    asm volatile("cp.async.cg.shared.global [%0], [%1], 16;\n" :: "r"(saddr), "l"(g));
}
#define CP_COMMIT() asm volatile("cp.async.commit_group;\n")
#define CP_WAIT1()  asm volatile("cp.async.wait_group 1;\n")
#define CP_WAIT0()  asm volatile("cp.async.wait_group 0;\n")

__device__ __forceinline__ void ldsm4t(uint32_t* r, uint32_t addr) {
    asm volatile("ldmatrix.sync.aligned.m8n8.x4.trans.shared.b16 {%0,%1,%2,%3}, [%4];"
                 : "=r"(r[0]), "=r"(r[1]), "=r"(r[2]), "=r"(r[3]) : "r"(addr));
}
__device__ __forceinline__ void mma16816(float* d, const uint32_t* a, const uint32_t* b) {
    asm volatile(
        "mma.sync.aligned.m16n8k16.row.col.f32.bf16.bf16.f32 "
        "{%0,%1,%2,%3},{%4,%5,%6,%7},{%8,%9},{%0,%1,%2,%3};"
        : "+f"(d[0]), "+f"(d[1]), "+f"(d[2]), "+f"(d[3])
        : "r"(a[0]), "r"(a[1]), "r"(a[2]), "r"(a[3]), "r"(b[0]), "r"(b[1]));
}

__device__ __forceinline__ void store_pair(bf16* C, size_t Cplane, size_t off,
                                           float v0, float v1) {
    __nv_bfloat162 ph, pl;
    ph.x = __float2bfloat16(v0);
    ph.y = __float2bfloat16(v1);
    pl.x = __float2bfloat16(v0 - __bfloat162float(ph.x));
    pl.y = __float2bfloat16(v1 - __bfloat162float(ph.y));
    *(__nv_bfloat162*)(C + off) = ph;
    *(__nv_bfloat162*)(C + Cplane + off) = pl;
}

// Hoisted lane offsets (bytes) for trans-ldmatrix addressing.
__device__ __forceinline__ uint32_t a_lane_off(int lane, int wm, int pitch) {
    return (uint32_t)((((lane & 7) + ((lane >> 4) & 1) * 8) * pitch
                       + wm + ((lane >> 3) & 1) * 8) * 2);
}
__device__ __forceinline__ uint32_t b_lane_off(int lane, int wn, int pitch) {
    return (uint32_t)((((lane & 7) + ((lane >> 3) & 1) * 8) * pitch
                       + wn + ((lane >> 4) & 1) * 8) * 2);
}

// ---------------------------------------------------------------------------
// gemm_big: BM=128, BN=128, 2 CTAs/SM, 3-stage. Used: G2, G4. (R15 engine)
// ---------------------------------------------------------------------------
__global__ void __launch_bounds__(256, 2) gemm_big(
    const bf16* __restrict__ A, const bf16* __restrict__ B,
    bf16* __restrict__ C, int M, int N, int K,
    size_t Aplane, size_t Bplane, size_t Cplane, Scat rs, Scat cs)
{
    constexpr int BM = 128, BN = 128, BK = 32;
    constexpr int APITCH = BM + 8;
    constexpr int BPITCH = BN + 8;
    constexpr int AS_PLANE = BK * APITCH;
    constexpr int BS_PLANE = BK * BPITCH;
    constexpr int STAGE = 2 * AS_PLANE + 2 * BS_PLANE;
    constexpr int NSTG = 3;
    constexpr int NT = BN / 16;   // 8
    constexpr int MT = 2;

    extern __shared__ bf16 sm[];

    const int tid  = threadIdx.x;
    const int lane = tid & 31;
    const int warp = tid >> 5;
    const int wm = (warp & 3) * 32;
    const int wn = (warp >> 2) * (BN / 2);
    const int m0 = blockIdx.y * BM;
    const int n0 = blockIdx.x * BN;

    float acc[MT][NT][4];
#pragma unroll
    for (int mt = 0; mt < MT; mt++)
#pragma unroll
        for (int nt = 0; nt < NT; nt++)
#pragma unroll
            for (int i = 0; i < 4; i++) acc[mt][nt][i] = 0.f;

    const int lk   = tid >> 3;
    const int mseg = (tid & 7) * 16;

    const uint32_t aoffB = a_lane_off(lane, wm, APITCH);
    const uint32_t boffB = b_lane_off(lane, wn, BPITCH);
    const uint32_t smBase = s2u(sm);

    auto load_stage = [&](int s, int k0) {
        bf16* base = sm + s * STAGE;
        const bf16* Ag = A + (size_t)(k0 + lk) * (size_t)M + (size_t)(m0 + mseg);
        uint32_t da = s2u(base + lk * APITCH + mseg);
        cpa16(da,      Ag);
        cpa16(da + 16, Ag + 8);
        uint32_t dal = da + AS_PLANE * 2;
        cpa16(dal,      Ag + Aplane);
        cpa16(dal + 16, Ag + Aplane + 8);
        const bf16* Bg = B + (size_t)(k0 + lk) * (size_t)N + (size_t)(n0 + mseg);
        uint32_t db = s2u(base + 2 * AS_PLANE + lk * BPITCH + mseg);
        cpa16(db,      Bg);
        cpa16(db + 16, Bg + 8);
        uint32_t dbl = db + BS_PLANE * 2;
        cpa16(dbl,      Bg + Bplane);
        cpa16(dbl + 16, Bg + Bplane + 8);
    };

    const int nchunks = K / BK;
    load_stage(0, 0);
    CP_COMMIT();
    if (nchunks > 1) load_stage(1, BK);
    CP_COMMIT();

    for (int c = 0; c < nchunks; c++) {
        CP_WAIT1();
        __syncthreads();

        if (c + 2 < nchunks) load_stage((c + 2) % NSTG, (c + 2) * BK);
        CP_COMMIT();

        const uint32_t stB = smBase + (uint32_t)((c % NSTG) * STAGE * 2);
        const uint32_t aH = stB + aoffB;
        const uint32_t aL = aH + (uint32_t)(AS_PLANE * 2);
        const uint32_t bH = stB + (uint32_t)(2 * AS_PLANE * 2) + boffB;
        const uint32_t bL = bH + (uint32_t)(BS_PLANE * 2);

#pragma unroll
        for (int kk = 0; kk < BK; kk += 16) {
            const uint32_t akk = (uint32_t)(kk * APITCH * 2);
            const uint32_t bkk = (uint32_t)(kk * BPITCH * 2);
            uint32_t a[MT][4];
            uint32_t bh[NT / 2][4], bl[NT / 2][4];
#pragma unroll
            for (int mt = 0; mt < MT; mt++)
                ldsm4t(a[mt], aH + akk + mt * 32);
#pragma unroll
            for (int np = 0; np < NT / 2; np++) {
                ldsm4t(bh[np], bH + bkk + np * 32);
                ldsm4t(bl[np], bL + bkk + np * 32);
            }
#pragma unroll
            for (int mt = 0; mt < MT; mt++)
#pragma unroll
                for (int nt = 0; nt < NT; nt++)
                    mma16816(acc[mt][nt], a[mt], &bh[nt >> 1][(nt & 1) * 2]);
#pragma unroll
            for (int mt = 0; mt < MT; mt++)
#pragma unroll
                for (int nt = 0; nt < NT; nt++)
                    mma16816(acc[mt][nt], a[mt], &bl[nt >> 1][(nt & 1) * 2]);
#pragma unroll
            for (int mt = 0; mt < MT; mt++)
                ldsm4t(a[mt], aL + akk + mt * 32);
#pragma unroll
            for (int mt = 0; mt < MT; mt++)
#pragma unroll
                for (int nt = 0; nt < NT; nt++)
                    mma16816(acc[mt][nt], a[mt], &bh[nt >> 1][(nt & 1) * 2]);
        }
    }

    const int r  = lane >> 2;
    const int c2 = (lane & 3) * 2;
    int fo[MT][2], go[NT];
#pragma unroll
    for (int mt = 0; mt < MT; mt++) {
        fo[mt][0] = scat_off(m0 + wm + mt * 16 + r,     rs);
        fo[mt][1] = scat_off(m0 + wm + mt * 16 + r + 8, rs);
    }
#pragma unroll
    for (int nt = 0; nt < NT; nt++)
        go[nt] = scat_off(n0 + wn + nt * 8 + c2, cs);

#pragma unroll
    for (int mt = 0; mt < MT; mt++)
#pragma unroll
        for (int nt = 0; nt < NT; nt++)
#pragma unroll
            for (int h = 0; h < 2; h++)
                store_pair(C, Cplane, (size_t)(fo[mt][h] + go[nt]),
                           acc[mt][nt][h * 2], acc[mt][nt][h * 2 + 1]);
}

// ---------------------------------------------------------------------------
// gemm_big64: BM=128, BN=128, K=64 resident, single stage, 2 CTAs/SM. Used: G1.
// Hoisted byte addressing in the MMA loop.
// ---------------------------------------------------------------------------
__global__ void __launch_bounds__(256, 2) gemm_big64(
    const bf16* __restrict__ A, const bf16* __restrict__ B,
    bf16* __restrict__ C, int M, int N,
    size_t Aplane, size_t Bplane, size_t Cplane, Scat rs, Scat cs)
{
    constexpr int BM = 128, BN = 128, KK = 64;
    constexpr int APITCH = BM + 8;
    constexpr int BPITCH = BN + 8;
    constexpr int AS_PLANE = KK * APITCH;
    constexpr int BS_PLANE = KK * BPITCH;
    constexpr int NT = BN / 16;
    constexpr int MT = 2;

    extern __shared__ bf16 sm[];

    const int tid  = threadIdx.x;
    const int lane = tid & 31;
    const int warp = tid >> 5;
    const int wm = (warp & 3) * 32;
    const int wn = (warp >> 2) * (BN / 2);
    const int m0 = blockIdx.y * BM;
    const int n0 = blockIdx.x * BN;

    float acc[MT][NT][4];
#pragma unroll
    for (int mt = 0; mt < MT; mt++)
#pragma unroll
        for (int nt = 0; nt < NT; nt++)
#pragma unroll
            for (int i = 0; i < 4; i++) acc[mt][nt][i] = 0.f;

    const int lk   = tid >> 3;
    const int mseg = (tid & 7) * 16;

#pragma unroll
    for (int h = 0; h < 2; h++) {
        int row = lk + 32 * h;
        const bf16* Ag = A + (size_t)row * (size_t)M + (size_t)(m0 + mseg);
        uint32_t da = s2u(sm + row * APITCH + mseg);
        cpa16(da,      Ag);
        cpa16(da + 16, Ag + 8);
        uint32_t dal = da + AS_PLANE * 2;
        cpa16(dal,      Ag + Aplane);
        cpa16(dal + 16, Ag + Aplane + 8);
        const bf16* Bg = B + (size_t)row * (size_t)N + (size_t)(n0 + mseg);
        uint32_t db = s2u(sm + 2 * AS_PLANE + row * BPITCH + mseg);
        cpa16(db,      Bg);
        cpa16(db + 16, Bg + 8);
        uint32_t dbl = db + BS_PLANE * 2;
        cpa16(dbl,      Bg + Bplane);
        cpa16(dbl + 16, Bg + Bplane + 8);
    }
    CP_COMMIT();
    CP_WAIT0();
    __syncthreads();

    const uint32_t aH = s2u(sm) + a_lane_off(lane, wm, APITCH);
    const uint32_t aL = aH + (uint32_t)(AS_PLANE * 2);
    const uint32_t bH = s2u(sm) + (uint32_t)(2 * AS_PLANE * 2)
                        + b_lane_off(lane, wn, BPITCH);
    const uint32_t bL = bH + (uint32_t)(BS_PLANE * 2);

#pragma unroll
    for (int kk = 0; kk < KK; kk += 16) {
        const uint32_t akk = (uint32_t)(kk * APITCH * 2);
        const uint32_t bkk = (uint32_t)(kk * BPITCH * 2);
        uint32_t a[MT][4];
        uint32_t bh[NT / 2][4], bl[NT / 2][4];
#pragma unroll
        for (int mt = 0; mt < MT; mt++)
            ldsm4t(a[mt], aH + akk + mt * 32);
#pragma unroll
        for (int np = 0; np < NT / 2; np++) {
            ldsm4t(bh[np], bH + bkk + np * 32);
            ldsm4t(bl[np], bL + bkk + np * 32);
        }
#pragma unroll
        for (int mt = 0; mt < MT; mt++)
#pragma unroll
            for (int nt = 0; nt < NT; nt++)
                mma16816(acc[mt][nt], a[mt], &bh[nt >> 1][(nt & 1) * 2]);
#pragma unroll
        for (int mt = 0; mt < MT; mt++)
#pragma unroll
            for (int nt = 0; nt < NT; nt++)
                mma16816(acc[mt][nt], a[mt], &bl[nt >> 1][(nt & 1) * 2]);
#pragma unroll
        for (int mt = 0; mt < MT; mt++)
            ldsm4t(a[mt], aL + akk + mt * 32);
#pragma unroll
        for (int mt = 0; mt < MT; mt++)
#pragma unroll
            for (int nt = 0; nt < NT; nt++)
                mma16816(acc[mt][nt], a[mt], &bh[nt >> 1][(nt & 1) * 2]);
    }

    const int r  = lane >> 2;
    const int c2 = (lane & 3) * 2;
    int fo[MT][2], go[NT];
#pragma unroll
    for (int mt = 0; mt < MT; mt++) {
        fo[mt][0] = scat_off(m0 + wm + mt * 16 + r,     rs);
        fo[mt][1] = scat_off(m0 + wm + mt * 16 + r + 8, rs);
    }
#pragma unroll
    for (int nt = 0; nt < NT; nt++)
        go[nt] = scat_off(n0 + wn + nt * 8 + c2, cs);

#pragma unroll
    for (int mt = 0; mt < MT; mt++)
#pragma unroll
        for (int nt = 0; nt < NT; nt++)
#pragma unroll
            for (int h = 0; h < 2; h++)
                store_pair(C, Cplane, (size_t)(fo[mt][h] + go[nt]),
                           acc[mt][nt][h * 2], acc[mt][nt][h * 2 + 1]);
}

// ---------------------------------------------------------------------------
// gemm_w64k: BM=128, BN=64, K=64 resident single stage, 3 CTAs/SM. Used: G3.
// Hoisted byte addressing.
// ---------------------------------------------------------------------------
__global__ void __launch_bounds__(256, 3) gemm_w64k(
    const bf16* __restrict__ A, const bf16* __restrict__ B,
    bf16* __restrict__ C, int M,
    size_t Aplane, size_t Bplane, size_t Cplane, Scat rs, Scat cs)
{
    constexpr int BM = 128, KK = 64;
    constexpr int APITCH = BM + 8;      // 136
    constexpr int BPITCH = 64 + 8;      // 72
    constexpr int AS_PLANE = KK * APITCH;
    constexpr int BS_PLANE = KK * BPITCH;
    constexpr int NT = 4;
    constexpr int MT = 2;

    extern __shared__ bf16 sm[];

    const int tid  = threadIdx.x;
    const int lane = tid & 31;
    const int warp = tid >> 5;
    const int wm = (warp & 3) * 32;
    const int wn = (warp >> 2) * 32;
    const int m0 = blockIdx.x * BM;

    float acc[MT][NT][4];
#pragma unroll
    for (int mt = 0; mt < MT; mt++)
#pragma unroll
        for (int nt = 0; nt < NT; nt++)
#pragma unroll
            for (int i = 0; i < 4; i++) acc[mt][nt][i] = 0.f;

    const int lk   = tid >> 3;
    const int mseg = (tid & 7) * 16;
    const int bseg = (tid & 7) * 8;

#pragma unroll
    for (int h = 0; h < 2; h++) {
        int row = lk + 32 * h;
        const bf16* Ag = A + (size_t)row * (size_t)M + (size_t)(m0 + mseg);
        uint32_t da = s2u(sm + row * APITCH + mseg);
        cpa16(da,      Ag);
        cpa16(da + 16, Ag + 8);
        uint32_t dal = da + AS_PLANE * 2;
        cpa16(dal,      Ag + Aplane);
        cpa16(dal + 16, Ag + Aplane + 8);
        const bf16* Bg = B + (size_t)row * 64 + bseg;
        uint32_t db = s2u(sm + 2 * AS_PLANE + row * BPITCH + bseg);
        cpa16(db, Bg);
        cpa16(db + BS_PLANE * 2, Bg + Bplane);
    }
    CP_COMMIT();
    CP_WAIT0();
    __syncthreads();

    const uint32_t aH = s2u(sm) + a_lane_off(lane, wm, APITCH);
    const uint32_t aL = aH + (uint32_t)(AS_PLANE * 2);
    const uint32_t bH = s2u(sm) + (uint32_t)(2 * AS_PLANE * 2)
                        + b_lane_off(lane, wn, BPITCH);
    const uint32_t bL = bH + (uint32_t)(BS_PLANE * 2);

#pragma unroll
    for (int kk = 0; kk < KK; kk += 16) {
        const uint32_t akk = (uint32_t)(kk * APITCH * 2);
        const uint32_t bkk = (uint32_t)(kk * BPITCH * 2);
        uint32_t a[MT][4];
        uint32_t bh[NT / 2][4], bl[NT / 2][4];
#pragma unroll
        for (int mt = 0; mt < MT; mt++)
            ldsm4t(a[mt], aH + akk + mt * 32);
#pragma unroll
        for (int np = 0; np < NT / 2; np++) {
            ldsm4t(bh[np], bH + bkk + np * 32);
            ldsm4t(bl[np], bL + bkk + np * 32);
        }
#pragma unroll
        for (int mt = 0; mt < MT; mt++)
#pragma unroll
            for (int nt = 0; nt < NT; nt++)
                mma16816(acc[mt][nt], a[mt], &bh[nt >> 1][(nt & 1) * 2]);
#pragma unroll
        for (int mt = 0; mt < MT; mt++)
#pragma unroll
            for (int nt = 0; nt < NT; nt++)
                mma16816(acc[mt][nt], a[mt], &bl[nt >> 1][(nt & 1) * 2]);
#pragma unroll
        for (int mt = 0; mt < MT; mt++)
            ldsm4t(a[mt], aL + akk + mt * 32);
#pragma unroll
        for (int mt = 0; mt < MT; mt++)
#pragma unroll
            for (int nt = 0; nt < NT; nt++)
                mma16816(acc[mt][nt], a[mt], &bh[nt >> 1][(nt & 1) * 2]);
    }

    const int r  = lane >> 2;
    const int c2 = (lane & 3) * 2;
    int fo[MT][2], go[NT];
#pragma unroll
    for (int mt = 0; mt < MT; mt++) {
        fo[mt][0] = scat_off(m0 + wm + mt * 16 + r,     rs);
        fo[mt][1] = scat_off(m0 + wm + mt * 16 + r + 8, rs);
    }
#pragma unroll
    for (int nt = 0; nt < NT; nt++)
        go[nt] = scat_off(wn + nt * 8 + c2, cs);

#pragma unroll
    for (int mt = 0; mt < MT; mt++)
#pragma unroll
        for (int nt = 0; nt < NT; nt++)
#pragma unroll
            for (int h = 0; h < 2; h++)
                store_pair(C, Cplane, (size_t)(fo[mt][h] + go[nt]),
                           acc[mt][nt][h * 2], acc[mt][nt][h * 2 + 1]);
}

// ---------------------------------------------------------------------------
// gemm_wide64: BM=128, BN=64, 3-stage pipelined, 2 CTAs/SM. Used: G5 (K=1024).
// Hoisted byte addressing.
// ---------------------------------------------------------------------------
__global__ void __launch_bounds__(256, 2) gemm_wide64(
    const bf16* __restrict__ A, const bf16* __restrict__ B,
    bf16* __restrict__ C, int M, int K,
    size_t Aplane, size_t Bplane, size_t Cplane, Scat rs, Scat cs)
{
    constexpr int BM = 128, BK = 32;
    constexpr int APITCH = BM + 8;
    constexpr int BPITCH = 64 + 8;
    constexpr int AS_PLANE = BK * APITCH;
    constexpr int BS_PLANE = BK * BPITCH;
    constexpr int STAGE = 2 * AS_PLANE + 2 * BS_PLANE;
    constexpr int NSTG = 3;
    constexpr int NT = 4;
    constexpr int MT = 2;

    extern __shared__ bf16 sm[];

    const int tid  = threadIdx.x;
    const int lane = tid & 31;
    const int warp = tid >> 5;
    const int wm = (warp & 3) * 32;
    const int wn = (warp >> 2) * 32;
    const int m0 = blockIdx.x * BM;

    float acc[MT][NT][4];
#pragma unroll
    for (int mt = 0; mt < MT; mt++)
#pragma unroll
        for (int nt = 0; nt < NT; nt++)
#pragma unroll
            for (int i = 0; i < 4; i++) acc[mt][nt][i] = 0.f;

    const int lk   = tid >> 3;
    const int mseg = (tid & 7) * 16;
    const int bseg = (tid & 7) * 8;

    const uint32_t aoffB = a_lane_off(lane, wm, APITCH);
    const uint32_t boffB = b_lane_off(lane, wn, BPITCH);
    const uint32_t smBase = s2u(sm);

    auto load_stage = [&](int s, int k0) {
        bf16* base = sm + s * STAGE;
        const bf16* Ag = A + (size_t)(k0 + lk) * (size_t)M + (size_t)(m0 + mseg);
        uint32_t da = s2u(base + lk * APITCH + mseg);
        cpa16(da,      Ag);
        cpa16(da + 16, Ag + 8);
        uint32_t dal = da + AS_PLANE * 2;
        cpa16(dal,      Ag + Aplane);
        cpa16(dal + 16, Ag + Aplane + 8);
        const bf16* Bg = B + (size_t)(k0 + lk) * 64 + bseg;
        uint32_t db = s2u(base + 2 * AS_PLANE + lk * BPITCH + bseg);
        cpa16(db, Bg);
        cpa16(db + BS_PLANE * 2, Bg + Bplane);
    };

    const int nchunks = K / BK;
    load_stage(0, 0);
    CP_COMMIT();
    if (nchunks > 1) load_stage(1, BK);
    CP_COMMIT();

    for (int c = 0; c < nchunks; c++) {
        CP_WAIT1();
        __syncthreads();

        if (c + 2 < nchunks) load_stage((c + 2) % NSTG, (c + 2) * BK);
        CP_COMMIT();

        const uint32_t stB = smBase + (uint32_t)((c % NSTG) * STAGE * 2);
        const uint32_t aH = stB + aoffB;
        const uint32_t aL = aH + (uint32_t)(AS_PLANE * 2);
        const uint32_t bH = stB + (uint32_t)(2 * AS_PLANE * 2) + boffB;
        const uint32_t bL = bH + (uint32_t)(BS_PLANE * 2);

#pragma unroll
        for (int kk = 0; kk < BK; kk += 16) {
            const uint32_t akk = (uint32_t)(kk * APITCH * 2);
            const uint32_t bkk = (uint32_t)(kk * BPITCH * 2);
            uint32_t a[MT][4];
            uint32_t bh[NT / 2][4], bl[NT / 2][4];
#pragma unroll
            for (int mt = 0; mt < MT; mt++)
                ldsm4t(a[mt], aH + akk + mt * 32);
#pragma unroll
            for (int np = 0; np < NT / 2; np++) {
                ldsm4t(bh[np], bH + bkk + np * 32);
                ldsm4t(bl[np], bL + bkk + np * 32);
            }
#pragma unroll
            for (int mt = 0; mt < MT; mt++)
#pragma unroll
                for (int nt = 0; nt < NT; nt++)
                    mma16816(acc[mt][nt], a[mt], &bh[nt >> 1][(nt & 1) * 2]);
#pragma unroll
            for (int mt = 0; mt < MT; mt++)
#pragma unroll
                for (int nt = 0; nt < NT; nt++)
                    mma16816(acc[mt][nt], a[mt], &bl[nt >> 1][(nt & 1) * 2]);
#pragma unroll
            for (int mt = 0; mt < MT; mt++)
                ldsm4t(a[mt], aL + akk + mt * 32);
#pragma unroll
            for (int mt = 0; mt < MT; mt++)
#pragma unroll
                for (int nt = 0; nt < NT; nt++)
                    mma16816(acc[mt][nt], a[mt], &bh[nt >> 1][(nt & 1) * 2]);
        }
    }

    const int r  = lane >> 2;
    const int c2 = (lane & 3) * 2;
    int fo[MT][2], go[NT];
#pragma unroll
    for (int mt = 0; mt < MT; mt++) {
        fo[mt][0] = scat_off(m0 + wm + mt * 16 + r,     rs);
        fo[mt][1] = scat_off(m0 + wm + mt * 16 + r + 8, rs);
    }
#pragma unroll
    for (int nt = 0; nt < NT; nt++)
        go[nt] = scat_off(wn + nt * 8 + c2, cs);

#pragma unroll
    for (int mt = 0; mt < MT; mt++)
#pragma unroll
        for (int nt = 0; nt < NT; nt++)
#pragma unroll
            for (int h = 0; h < 2; h++)
                store_pair(C, Cplane, (size_t)(fo[mt][h] + go[nt]),
                           acc[mt][nt][h * 2], acc[mt][nt][h * 2 + 1]);
}

// ---------------------------------------------------------------------------
// Fused prep kernel: split inputs into bf16 hi/lo pairs.
// ---------------------------------------------------------------------------
__device__ __forceinline__ void put_split_g(bf16* dst, size_t plane, size_t i, float x) {
    bf16 h = __float2bfloat16(x);
    dst[i] = h;
    dst[plane + i] = __float2bfloat16(x - __bfloat162float(h));
}

__global__ void prep_all(const float* __restrict__ state,
                         const float* __restrict__ layer,
                         const float* __restrict__ oper) {
    int idx = blockIdx.x * blockDim.x + threadIdx.x;   // 1,605,632 total
    if (idx < 524288) {
        put_split_g(g_S, 524288, idx, state[idx]);
    } else if (idx < 1048576) {
        int i = idx - 524288;
        put_split_g(g_U, 524288, i, layer[i]);
    } else if (idx < 1081344) {
        int i = idx - 1048576;
        put_split_g(g_O, 32768, i, oper[i]);
    } else {
        int i = idx - 1081344;
        int Lb = i & 15; int t = i >> 4;
        int j  = t & 15;   t >>= 4;
        int ii = t & 15;   t >>= 4;
        int l  = t & 15;   t >>= 4;
        int q  = t;
        float x = layer[((((size_t)q * 16 + l) * 16 + j) * 16 + ii) * 16 + Lb];
        put_split_g(g_Ud, 524288, i, x);
    }
}

// ---------------------------------------------------------------------------
// Fused site-0 boundary (exact fp32)
// ---------------------------------------------------------------------------
__global__ void s0_all(const float* __restrict__ st, const float* __restrict__ ly,
                       const float* __restrict__ op, bf16* __restrict__ env) {
    extern __shared__ float sf[];
    float* sY  = sf;           // [k*1024 + M*64 + B]
    float* sC2 = sf + 16384;   // [L*64 + k*4 + O]
    float* sC1 = sf + 17408;   // [j*16 + L]
    const int t = threadIdx.x;
    const int A = blockIdx.x;

    {
        int j = t >> 4, L = t & 15;
        float s = 0.f;
        for (int i = 0; i < 16; i++)
            s += st[i * 64 + A] * ly[j * 256 + i * 16 + L];
        sC1[t] = s;
    }
    for (int e = t; e < 16384; e += 256) {
        int k = e >> 10, M = (e >> 6) & 15, B = e & 63;
        float s = 0.f;
        for (int sx = 0; sx < 16; sx++)
            s += ly[k * 256 + sx * 16 + M] * st[sx * 64 + B];
        sY[e] = s;
    }
    __syncthreads();
    for (int e = t; e < 1024; e += 256) {
        int L = e >> 6, k = (e >> 2) & 15, O = e & 3;
        float s = 0.f;
        for (int j = 0; j < 16; j++)
            s += sC1[j * 16 + L] * op[j * 64 + k * 4 + O];
        sC2[e] = s;
    }
    __syncthreads();
    for (int e = t; e < 65536; e += 256) {
        int B = e & 63, M = (e >> 6) & 15, O = (e >> 10) & 3, L = e >> 12;
        float v = 0.f;
#pragma unroll
        for (int k = 0; k < 16; k++)
            v += sC2[L * 64 + k * 4 + O] * sY[k * 1024 + M * 64 + B];
        size_t off = (size_t)A * 65536 + e;
        bf16 h = __float2bfloat16(v);
        env[off] = h;
        env[ESZ + off] = __float2bfloat16(v - __bfloat162float(h));
    }
}

// ---------------------------------------------------------------------------
// Site-7 boundary
// ---------------------------------------------------------------------------
__global__ void s7_x1(const float* __restrict__ st, const float* __restrict__ ly,
                      float* __restrict__ X1) {
    int idx = blockIdx.x * blockDim.x + threadIdx.x;
    if (idx >= 16384) return;
    int j = idx & 15, l = (idx >> 4) & 15, a = idx >> 8;
    float s = 0.f;
    for (int i = 0; i < 16; i++)
        s += st[a * 1024 + i * 64] * ly[l * 4096 + j * 256 + i * 16];
    X1[idx] = s;
}
__global__ void s7_x2(const float* __restrict__ X1, const float* __restrict__ op,
                      float* __restrict__ X2) {
    int idx = blockIdx.x * blockDim.x + threadIdx.x;
    if (idx >= 65536) return;
    int k = idx & 15, o = (idx >> 4) & 3, l = (idx >> 6) & 15, a = idx >> 10;
    float s = 0.f;
    for (int j = 0; j < 16; j++)
        s += X1[(a * 16 + l) * 16 + j] * op[o * 1024 + j * 64 + k * 4];
    X2[idx] = s;
}
__global__ void s7_x3(const float* __restrict__ X2, const float* __restrict__ ly,
                      float* __restrict__ X3) {
    int idx = blockIdx.x * blockDim.x + threadIdx.x;
    if (idx >= 1048576) return;
    int s5 = idx & 15, m = (idx >> 4) & 15, o = (idx >> 8) & 3,
        l = (idx >> 10) & 15, a = idx >> 14;
    float s = 0.f;
    for (int k = 0; k < 16; k++)
        s += X2[((a * 16 + l) * 4 + o) * 16 + k] * ly[m * 4096 + k * 256 + s5 * 16];
    X3[idx] = s;
}
__global__ void s7_dot(const float* __restrict__ X3, const float* __restrict__ st,
                       const bf16* __restrict__ env, float* __restrict__ partial) {
    __shared__ float red[256];
    int t = blockIdx.x * 256 + threadIdx.x;
    float x3[16];
#pragma unroll
    for (int s = 0; s < 16; s++) x3[s] = X3[t * 16 + s];
    size_t base = (size_t)t * 64;
    float acc = 0.f;
    for (int b = 0; b < 64; b++) {
        float w = 0.f;
#pragma unroll
        for (int s = 0; s < 16; s++) w += x3[s] * st[b * 1024 + s * 64];
        float e = __bfloat162float(env[base + b]) + __bfloat162float(env[ESZ + base + b]);
        acc += e * w;
    }
    red[threadIdx.x] = acc;
    __syncthreads();
    for (int step = 128; step > 0; step >>= 1) {
        if (threadIdx.x < step) red[threadIdx.x] += red[threadIdx.x + step];
        __syncthreads();
    }
    if (threadIdx.x == 0) partial[blockIdx.x] = red[0];
}
__global__ void s7_reduce(const float* __restrict__ partial, float* __restrict__ out) {
    __shared__ float red[256];
    red[threadIdx.x] = partial[threadIdx.x];
    __syncthreads();
    for (int step = 128; step > 0; step >>= 1) {
        if (threadIdx.x < step) red[threadIdx.x] += red[threadIdx.x + step];
        __syncthreads();
    }
    if (threadIdx.x == 0) out[0] = red[0];
}

// ---------------------------------------------------------------------------
extern "C" void kernel_launch(void* const* d_in, const int* in_sizes, int n_in,
                              void* d_out, int out_size) {
    const float* state = (const float*)d_in[0];  // [8, 64, 16, 64]
    const float* layer = (const float*)d_in[1];  // [1, 8, 16, 16, 16, 16]
    const float* oper  = (const float*)d_in[2];  // [8, 4, 16, 16, 4]
    float* out = (float*)d_out;

    bf16 *TA, *TB, *envA, *envB, *S, *U, *Ud, *O;
    cudaGetSymbolAddress((void**)&TA,   g_TA);
    cudaGetSymbolAddress((void**)&TB,   g_TB);
    cudaGetSymbolAddress((void**)&envA, g_envA);
    cudaGetSymbolAddress((void**)&envB, g_envB);
    cudaGetSymbolAddress((void**)&S,    g_S);
    cudaGetSymbolAddress((void**)&U,    g_U);
    cudaGetSymbolAddress((void**)&Ud,   g_Ud);
    cudaGetSymbolAddress((void**)&O,    g_O);

    // fp32 scratch carved from TB (used only after main loop frees it)
    float* fB = (float*)TB;
    float* X1 = fB, *X2 = fB + 32768, *X3 = fB + 131072;
    float* partial = fB + 1310720;

    constexpr int SMEM128  = 3 * (2 * (32 * 136) + 2 * (32 * 136)) * 2;  // 104448
    constexpr int SMEMB64  = (2 * (64 * 136) + 2 * (64 * 136)) * 2;      // 69632
    constexpr int SMEMW64K = (2 * (64 * 136) + 2 * (64 * 72)) * 2;       // 53248
    constexpr int SMEMWIDE = 3 * (2 * (32 * 136) + 2 * (32 * 72)) * 2;   // 79872
    constexpr int SMEM_S0  = 17664 * 4;                                  // 70656
    cudaFuncSetAttribute(gemm_big,    cudaFuncAttributeMaxDynamicSharedMemorySize, SMEM128);
    cudaFuncSetAttribute(gemm_big64,  cudaFuncAttributeMaxDynamicSharedMemorySize, SMEMB64);
    cudaFuncSetAttribute(gemm_w64k,   cudaFuncAttributeMaxDynamicSharedMemorySize, SMEMW64K);
    cudaFuncSetAttribute(gemm_wide64, cudaFuncAttributeMaxDynamicSharedMemorySize, SMEMWIDE);
    cudaFuncSetAttribute(s0_all,      cudaFuncAttributeMaxDynamicSharedMemorySize, SMEM_S0);

    prep_all<<<6272, 256>>>(state, layer, oper);
    s0_all<<<64, 256, SMEM_S0>>>(state, layer, oper, envA);

    bf16* envc = envA;
    bf16* envn = envB;

    for (int q = 1; q <= 6; q++) {
        const bf16* Sq  = S  + (size_t)q * 65536;
        const bf16* Uq  = U  + (size_t)q * 65536;
        const bf16* Udq = Ud + (size_t)q * 65536;
        const bf16* Oq  = O  + (size_t)q * 4096;

        // G1: T1 = env x S      M=65536 N=1024 K=64
        gemm_big64<<<dim3(1024 / 128, 65536 / 128), 256, SMEMB64>>>(
            envc, Sq, TA, 65536, 1024, ESZ, 524288, TSZ,
            mk(64, 64, 16, 4096, 4, 65536, 16, 4194304),
            mk(64, 1, 16, 262144, 1, 0, 1, 0));

        // G2: T2 = T1 x Ud      M=262144 N=256 K=256
        gemm_big<<<dim3(256 / 128, 262144 / 128), 256, SMEM128>>>(
            TA, Udq, TB, 262144, 256, 256, TSZ, 524288, TSZ,
            mk(64, 16, 64, 1024, 16, 65536, 4, 16777216),
            mk(16, 1, 16, 1048576, 1, 0, 1, 0));

        // G3: T3 = T2 x O       M=1048576 N=64 K=64
        gemm_w64k<<<dim3(1048576 / 128, 1), 256, SMEMW64K>>>(
            TB, Oq, TA, 1048576, TSZ, 32768, TSZ,
            mk(16, 4, 64, 64, 64, 4096, 16, 4194304),
            mk(4, 1, 16, 262144, 1, 0, 1, 0));

        // G4: T4 = T3 x U       M=262144 N=256 K=256
        gemm_big<<<dim3(256 / 128, 262144 / 128), 256, SMEM128>>>(
            TA, Uq, TB, 262144, 256, 256, TSZ, 524288, TSZ,
            mk(4, 16, 16, 64, 64, 1024, 64, 1048576),
            mk(16, 1, 16, 65536, 1, 0, 1, 0));

        // G5: env' = T4 x S     M=65536 N=64 K=1024
        gemm_wide64<<<dim3(65536 / 128, 1), 256, SMEMWIDE>>>(
            TB, Sq, envn, 65536, 1024, TSZ, 524288, ESZ,
            mk(16, 64, 4, 1024, 16, 4096, 64, 65536),
            mk(64, 1, 1, 0, 1, 0, 1, 0));

        bf16* t = envc; envc = envn; envn = t;
    }

    // Site 7 boundary
    const float* st7 = state + 7 * 65536;
    const float* ly7 = layer + 7 * 65536;
    const float* op7 = oper  + 7 * 4096;
    s7_x1<<<64, 256>>>(st7, ly7, X1);
    s7_x2<<<256, 256>>>(X1, op7, X2);
    s7_x3<<<4096, 256>>>(X2, ly7, X3);
    s7_dot<<<256, 256>>>(X3, st7, envc, partial);
    s7_reduce<<<1, 256>>>(partial, out);
}